// round 11
// baseline (speedup 1.0000x reference)
#include <cuda_runtime.h>
#include <cuda_bf16.h>
#include <math.h>
#include <stdint.h>

#define NN 100000
#define NE 3200000

// ---------------- scratch ----------------
__device__ float g_s[(size_t)NN * 256];
__device__ float g_h[(size_t)NN * 256];
__device__ __nv_bfloat16 g_ah[(size_t)NN * 256];   // activation hi
__device__ __nv_bfloat16 g_al[(size_t)NN * 256];   // activation lo
__device__ int8_t g_w0q1[256 * 512], g_w0q2[256 * 512];        // W0 limbs, [N][K]
__device__ __nv_bfloat16 g_w1h[256 * 128], g_w1l[256 * 128];
__device__ __nv_bfloat16 g_w2h[64 * 128],  g_w2l[64 * 128];    // N padded 40->64
__device__ int   g_deg[NN];
__device__ int   g_rowptr[NN + 1];
__device__ int   g_cursor[NN];
__device__ int   g_srcs[NE];
__device__ float g_vals[NE];

// ---------------- helpers ----------------
__device__ __forceinline__ uint32_t smem_u32(const void* p) {
    uint32_t a;
    asm("{ .reg .u64 t; cvta.to.shared.u64 t, %1; cvt.u32.u64 %0, t; }" : "=r"(a) : "l"(p));
    return a;
}

__device__ __forceinline__ void split2(float a, float b, uint32_t& hi, uint32_t& lo) {
    __nv_bfloat16 ah = __float2bfloat16(a), bh = __float2bfloat16(b);
    float ar = a - __bfloat162float(ah);
    float br = b - __bfloat162float(bh);
    __nv_bfloat16 al = __float2bfloat16(ar), bl = __float2bfloat16(br);
    hi = (uint32_t)__bfloat16_as_ushort(ah) | ((uint32_t)__bfloat16_as_ushort(bh) << 16);
    lo = (uint32_t)__bfloat16_as_ushort(al) | ((uint32_t)__bfloat16_as_ushort(bl) << 16);
}

__device__ __forceinline__ void ldm4(uint32_t* r, uint32_t addr) {
    asm volatile("ldmatrix.sync.aligned.m8n8.x4.shared.b16 {%0,%1,%2,%3}, [%4];"
                 : "=r"(r[0]), "=r"(r[1]), "=r"(r[2]), "=r"(r[3]) : "r"(addr));
}

__device__ __forceinline__ void mma16816(float* c, const uint32_t* a, uint32_t b0, uint32_t b1) {
    asm volatile(
        "mma.sync.aligned.m16n8k16.row.col.f32.bf16.bf16.f32 "
        "{%0,%1,%2,%3}, {%4,%5,%6,%7}, {%8,%9}, {%0,%1,%2,%3};"
        : "+f"(c[0]), "+f"(c[1]), "+f"(c[2]), "+f"(c[3])
        : "r"(a[0]), "r"(a[1]), "r"(a[2]), "r"(a[3]), "r"(b0), "r"(b1));
}

__device__ __forceinline__ void mma16832s8(int* c, const uint32_t* a, uint32_t b0, uint32_t b1) {
    asm volatile(
        "mma.sync.aligned.m16n8k32.row.col.s32.s8.s8.s32 "
        "{%0,%1,%2,%3}, {%4,%5,%6,%7}, {%8,%9}, {%0,%1,%2,%3};"
        : "+r"(c[0]), "+r"(c[1]), "+r"(c[2]), "+r"(c[3])
        : "r"(a[0]), "r"(a[1]), "r"(a[2]), "r"(a[3]), "r"(b0), "r"(b1));
}

__device__ __forceinline__ uint32_t pack4(int a, int b, int c, int d) {
    return (uint32_t)(a & 255) | ((uint32_t)(b & 255) << 8) |
           ((uint32_t)(c & 255) << 16) | ((uint32_t)(d & 255) << 24);
}

// two-limb int8 quantization of 4 floats (range +-8)
__device__ __forceinline__ void quant4(float4 v, uint32_t& o1, uint32_t& o2) {
    const float C1 = 15.875f;            // 127/8
    const float D1 = 8.0f / 127.0f;
    const float C2 = 4032.25f;           // C1 * 254
    int ax = __float2int_rn(v.x * C1); ax = max(-127, min(127, ax));
    int ay = __float2int_rn(v.y * C1); ay = max(-127, min(127, ay));
    int az = __float2int_rn(v.z * C1); az = max(-127, min(127, az));
    int aw = __float2int_rn(v.w * C1); aw = max(-127, min(127, aw));
    float rx = v.x - ax * D1, ry = v.y - ay * D1;
    float rz = v.z - az * D1, rw = v.w - aw * D1;
    int bx = __float2int_rn(rx * C2); bx = max(-127, min(127, bx));
    int by = __float2int_rn(ry * C2); by = max(-127, min(127, by));
    int bz = __float2int_rn(rz * C2); bz = max(-127, min(127, bz));
    int bw = __float2int_rn(rw * C2); bw = max(-127, min(127, bw));
    o1 = pack4(ax, ay, az, aw);
    o2 = pack4(bx, by, bz, bw);
}

// ---------------- CSR build ----------------
__global__ void k_zero_deg() {
    int i = blockIdx.x * blockDim.x + threadIdx.x;
    if (i < NN) g_deg[i] = 0;
}
__global__ void k_hist(const int* __restrict__ dst) {
    int e = blockIdx.x * blockDim.x + threadIdx.x;
    if (e < NE) atomicAdd(&g_deg[dst[e]], 1);
}
__global__ void k_scan() {
    __shared__ int ssum[1024];
    const int t = threadIdx.x;
    const int CH = (NN + 1023) / 1024;
    int s0 = t * CH, s1 = s0 + CH; if (s1 > NN) s1 = NN;
    int sum = 0;
    for (int i = s0; i < s1; i++) sum += g_deg[i];
    ssum[t] = sum;
    __syncthreads();
    for (int off = 1; off < 1024; off <<= 1) {
        int v = (t >= off) ? ssum[t - off] : 0;
        __syncthreads();
        ssum[t] += v;
        __syncthreads();
    }
    int run = (t == 0) ? 0 : ssum[t - 1];
    for (int i = s0; i < s1; i++) { g_rowptr[i] = run; g_cursor[i] = run; run += g_deg[i]; }
    if (t == 1023) g_rowptr[NN] = ssum[1023];
}
__global__ void k_scatter(const int* __restrict__ src, const int* __restrict__ dst,
                          const float* __restrict__ val) {
    int e = blockIdx.x * blockDim.x + threadIdx.x;
    if (e >= NE) return;
    int d = dst[e];
    int p = atomicAdd(&g_cursor[d], 1);
    g_srcs[p] = src[e];
    g_vals[p] = val[e];
}

// ---------------- weight converters ----------------
__global__ void k_cvt_w(const float* __restrict__ W, __nv_bfloat16* __restrict__ wh,
                        __nv_bfloat16* __restrict__ wl, int K, int N) {
    int idx = blockIdx.x * blockDim.x + threadIdx.x;
    if (idx >= N * K) return;
    int n = idx / K, k = idx % K;
    float v = W[(size_t)k * N + n];
    __nv_bfloat16 h = __float2bfloat16(v);
    float r = v - __bfloat162float(h);
    wh[idx] = h;
    wl[idx] = __float2bfloat16(r);
}
__global__ void k_cvt_w_pad(const float* __restrict__ W, __nv_bfloat16* __restrict__ wh,
                            __nv_bfloat16* __restrict__ wl, int K, int N, int Npad) {
    int idx = blockIdx.x * blockDim.x + threadIdx.x;
    if (idx >= Npad * K) return;
    int n = idx / K, k = idx % K;
    float v = (n < N) ? W[(size_t)k * N + n] : 0.f;
    __nv_bfloat16 h = __float2bfloat16(v);
    float r = v - __bfloat162float(h);
    wh[idx] = h;
    wl[idx] = __float2bfloat16(r);
}
// W0 [512][256] fp32 -> two int8 limbs [N=256][K=512], w ~= (p1 + p2/254) / 2032
__global__ void k_cvt_w0_s8(const float* __restrict__ W,
                            int8_t* __restrict__ p1a, int8_t* __restrict__ p2a) {
    int idx = blockIdx.x * blockDim.x + threadIdx.x;
    if (idx >= 256 * 512) return;
    int n = idx / 512, k = idx % 512;
    float v = W[(size_t)k * 256 + n];
    int p1 = __float2int_rn(v * 2032.0f); p1 = max(-127, min(127, p1));
    float r = v - p1 * (1.0f / 2032.0f);
    int p2 = __float2int_rn(r * 516128.0f); p2 = max(-127, min(127, p2));  // 2032*254
    p1a[idx] = (int8_t)p1;
    p2a[idx] = (int8_t)p2;
}

// ---------------- int8 two-limb GEMM0: C[M,256] = x[M,512] @ W0 + b0 ----------------
// A quantized in-kernel to two int8 limbs; B pre-quantized. 2 s32 accumulator chains.
// smem tiles are int8 [128][64+16pad] viewed as b16 [128][40] so ldmatrix addressing
// is identical to the bf16 kernels. chunk = 64 K-elements, 8 chunks.
__global__ void __launch_bounds__(256, 1)
k_mma_gemm_s8(const float* __restrict__ A,
              const int8_t* __restrict__ B1, const int8_t* __restrict__ B2,
              const float* __restrict__ bias, float* __restrict__ C, int M) {
    const int K = 512, N = 256;
    __shared__ __nv_bfloat16 sA1[128][40];   // b16 view of int8 [128][80]
    __shared__ __nv_bfloat16 sA2[128][40];
    __shared__ __nv_bfloat16 sB1[128][40];
    __shared__ __nv_bfloat16 sB2[128][40];

    const int tid = threadIdx.x;
    const int wid = tid >> 5, lane = tid & 31;
    const int m0 = blockIdx.y * 128;
    const int n0 = blockIdx.x * 128;
    const int wm = wid >> 2;
    const int wn = wid & 3;

    int lrow[2], lq[2];
#pragma unroll
    for (int it = 0; it < 2; it++) {
        int idx = it * 256 + tid;
        lrow[it] = idx >> 2;
        lq[it] = idx & 3;
    }

    int accH[4][4][4], accM[4][4][4];
#pragma unroll
    for (int a = 0; a < 4; a++)
#pragma unroll
        for (int b = 0; b < 4; b++)
#pragma unroll
            for (int c = 0; c < 4; c++) { accH[a][b][c] = 0; accM[a][b][c] = 0; }

    float4 fA[2][4];      // 16 K-floats per (row, seg)
    uint4 pB1[2], pB2[2];

    auto fetch = [&](int ch) {
        const int k0 = ch * 64;
#pragma unroll
        for (int it = 0; it < 2; it++) {
            int row = lrow[it], q = lq[it];
            if (m0 + row < M) {
                const float* p = &A[(size_t)(m0 + row) * K + k0 + q * 16];
                fA[it][0] = *(const float4*)(p + 0);
                fA[it][1] = *(const float4*)(p + 4);
                fA[it][2] = *(const float4*)(p + 8);
                fA[it][3] = *(const float4*)(p + 12);
            } else {
#pragma unroll
                for (int s = 0; s < 4; s++) fA[it][s] = make_float4(0.f, 0.f, 0.f, 0.f);
            }
            size_t offb = (size_t)(n0 + row) * K + k0 + q * 16;
            pB1[it] = *(const uint4*)&B1[offb];
            pB2[it] = *(const uint4*)&B2[offb];
        }
    };
    auto commit = [&]() {
#pragma unroll
        for (int it = 0; it < 2; it++) {
            int row = lrow[it], q = lq[it];
            uint4 q1v, q2v;
            quant4(fA[it][0], q1v.x, q2v.x);
            quant4(fA[it][1], q1v.y, q2v.y);
            quant4(fA[it][2], q1v.z, q2v.z);
            quant4(fA[it][3], q1v.w, q2v.w);
            *(uint4*)&sA1[row][q * 8] = q1v;
            *(uint4*)&sA2[row][q * 8] = q2v;
            *(uint4*)&sB1[row][q * 8] = pB1[it];
            *(uint4*)&sB2[row][q * 8] = pB2[it];
        }
    };

    const int nch = K / 64;   // 8
    fetch(0);
    commit();

    for (int ch = 0; ch < nch; ch++) {
        __syncthreads();
        if (ch + 1 < nch) fetch(ch + 1);

#pragma unroll
        for (int kk = 0; kk < 32; kk += 16) {      // b16 columns; one k32 mma step each
            const int r = lane & 15;
            const int koff = (lane >> 4) << 3;
            uint32_t b1f[2][4], b2f[2][4];
#pragma unroll
            for (int nt = 0; nt < 2; nt++) {
                ldm4(b1f[nt], smem_u32(&sB1[wn * 32 + nt * 16 + r][kk + koff]));
                ldm4(b2f[nt], smem_u32(&sB2[wn * 32 + nt * 16 + r][kk + koff]));
            }
            // q1*p1 -> accH, q1*p2 -> accM
#pragma unroll
            for (int mt = 0; mt < 4; mt++) {
                uint32_t af[4];
                ldm4(af, smem_u32(&sA1[wm * 64 + mt * 16 + r][kk + koff]));
#pragma unroll
                for (int j = 0; j < 4; j++) {
                    mma16832s8(accH[mt][j], af, b1f[j >> 1][j & 1], b1f[j >> 1][2 + (j & 1)]);
                    mma16832s8(accM[mt][j], af, b2f[j >> 1][j & 1], b2f[j >> 1][2 + (j & 1)]);
                }
            }
            // q2*p1 -> accM
#pragma unroll
            for (int mt = 0; mt < 4; mt++) {
                uint32_t af[4];
                ldm4(af, smem_u32(&sA2[wm * 64 + mt * 16 + r][kk + koff]));
#pragma unroll
                for (int j = 0; j < 4; j++)
                    mma16832s8(accM[mt][j], af, b1f[j >> 1][j & 1], b1f[j >> 1][2 + (j & 1)]);
            }
        }
        __syncthreads();
        if (ch + 1 < nch) commit();
    }

    // epilogue: C = Sc*(accH + accM/254) + bias
    const float Sc = 8.0f / (127.0f * 2032.0f);
    const float Sm = 1.0f / 254.0f;
    const int rbase = m0 + wm * 64 + (lane >> 2);
    const int cbase = n0 + wn * 32 + (lane & 3) * 2;
#pragma unroll
    for (int mt = 0; mt < 4; mt++) {
        int m = rbase + mt * 16;
#pragma unroll
        for (int j = 0; j < 4; j++) {
            int c = cbase + j * 8;
            float bv0 = bias[c], bv1 = bias[c + 1];
            if (m < M) {
                float2 o;
                o.x = Sc * ((float)accH[mt][j][0] + (float)accM[mt][j][0] * Sm) + bv0;
                o.y = Sc * ((float)accH[mt][j][1] + (float)accM[mt][j][1] * Sm) + bv1;
                *(float2*)&C[(size_t)m * N + c] = o;
            }
            if (m + 8 < M) {
                float2 o;
                o.x = Sc * ((float)accH[mt][j][2] + (float)accM[mt][j][2] * Sm) + bv0;
                o.y = Sc * ((float)accH[mt][j][3] + (float)accM[mt][j][3] * Sm) + bv1;
                *(float2*)&C[(size_t)(m + 8) * N + c] = o;
            }
        }
    }
}

// ---------------- tensor-core GEMM (bf16 hi/lo A): C = A @ B^T + bias ----------------
__global__ void __launch_bounds__(256, 2)
k_mma_gemm(const __nv_bfloat16* __restrict__ Ah, const __nv_bfloat16* __restrict__ Al,
           const __nv_bfloat16* __restrict__ Bh, const __nv_bfloat16* __restrict__ Bl,
           const float* __restrict__ bias, float* __restrict__ C,
           int M, int K, int N) {
    __shared__ __nv_bfloat16 sAh[128][40];
    __shared__ __nv_bfloat16 sAl[128][40];
    __shared__ __nv_bfloat16 sBh[128][40];
    __shared__ __nv_bfloat16 sBl[128][40];

    const int tid = threadIdx.x;
    const int wid = tid >> 5, lane = tid & 31;
    const int m0 = blockIdx.y * 128;
    const int n0 = blockIdx.x * 128;
    const int wm = wid >> 2;
    const int wn = wid & 3;

    int lrow[2], lq[2];
#pragma unroll
    for (int it = 0; it < 2; it++) {
        int idx = it * 256 + tid;
        lrow[it] = idx >> 2;
        lq[it] = idx & 3;
    }

    float acc[4][4][4];
#pragma unroll
    for (int a = 0; a < 4; a++)
#pragma unroll
        for (int b = 0; b < 4; b++)
#pragma unroll
            for (int c = 0; c < 4; c++) acc[a][b][c] = 0.f;

    uint4 pAh[2], pAl[2], pBh[2], pBl[2];

    auto fetch = [&](int ch) {
        const int k0 = ch * 32;
#pragma unroll
        for (int it = 0; it < 2; it++) {
            int row = lrow[it], q = lq[it];
            if (m0 + row < M) {
                size_t off = (size_t)(m0 + row) * K + k0 + q * 8;
                pAh[it] = *(const uint4*)&Ah[off];
                pAl[it] = *(const uint4*)&Al[off];
            } else {
                pAh[it] = make_uint4(0, 0, 0, 0);
                pAl[it] = make_uint4(0, 0, 0, 0);
            }
            size_t offb = (size_t)(n0 + row) * K + k0 + q * 8;
            pBh[it] = *(const uint4*)&Bh[offb];
            pBl[it] = *(const uint4*)&Bl[offb];
        }
    };
    auto commit = [&]() {
#pragma unroll
        for (int it = 0; it < 2; it++) {
            int row = lrow[it], q = lq[it];
            *(uint4*)&sAh[row][q * 8] = pAh[it];
            *(uint4*)&sAl[row][q * 8] = pAl[it];
            *(uint4*)&sBh[row][q * 8] = pBh[it];
            *(uint4*)&sBl[row][q * 8] = pBl[it];
        }
    };

    const int nch = K / 32;
    fetch(0);
    commit();

    for (int ch = 0; ch < nch; ch++) {
        __syncthreads();
        if (ch + 1 < nch) fetch(ch + 1);

#pragma unroll
        for (int kk = 0; kk < 32; kk += 16) {
            const int r = lane & 15;
            const int koff = (lane >> 4) << 3;
            uint32_t bhf[2][4], blf[2][4];
#pragma unroll
            for (int nt = 0; nt < 2; nt++) {
                ldm4(bhf[nt], smem_u32(&sBh[wn * 32 + nt * 16 + r][kk + koff]));
                ldm4(blf[nt], smem_u32(&sBl[wn * 32 + nt * 16 + r][kk + koff]));
            }
#pragma unroll
            for (int mt = 0; mt < 4; mt++) {
                uint32_t af[4];
                ldm4(af, smem_u32(&sAh[wm * 64 + mt * 16 + r][kk + koff]));
#pragma unroll
                for (int j = 0; j < 4; j++) {
                    mma16816(acc[mt][j], af, bhf[j >> 1][j & 1], bhf[j >> 1][2 + (j & 1)]);
                    mma16816(acc[mt][j], af, blf[j >> 1][j & 1], blf[j >> 1][2 + (j & 1)]);
                }
            }
#pragma unroll
            for (int mt = 0; mt < 4; mt++) {
                uint32_t af[4];
                ldm4(af, smem_u32(&sAl[wm * 64 + mt * 16 + r][kk + koff]));
#pragma unroll
                for (int j = 0; j < 4; j++)
                    mma16816(acc[mt][j], af, bhf[j >> 1][j & 1], bhf[j >> 1][2 + (j & 1)]);
            }
        }
        __syncthreads();
        if (ch + 1 < nch) commit();
    }

    const int rbase = m0 + wm * 64 + (lane >> 2);
    const int cbase = n0 + wn * 32 + (lane & 3) * 2;
#pragma unroll
    for (int mt = 0; mt < 4; mt++) {
        int m = rbase + mt * 16;
#pragma unroll
        for (int j = 0; j < 4; j++) {
            int c = cbase + j * 8;
            float bv0 = bias[c], bv1 = bias[c + 1];
            if (m < M) {
                float2 o = make_float2(acc[mt][j][0] + bv0, acc[mt][j][1] + bv1);
                *(float2*)&C[(size_t)m * N + c] = o;
            }
            if (m + 8 < M) {
                float2 o = make_float2(acc[mt][j][2] + bv0, acc[mt][j][3] + bv1);
                *(float2*)&C[(size_t)(m + 8) * N + c] = o;
            }
        }
    }
}

// ---------------- tensor-core GEMM, layer 2: K=128, Npad=64, Nout=40 ----------------
__global__ void __launch_bounds__(256, 2)
k_mma_gemm64(const __nv_bfloat16* __restrict__ Ah, const __nv_bfloat16* __restrict__ Al,
             const __nv_bfloat16* __restrict__ Bh, const __nv_bfloat16* __restrict__ Bl,
             const float* __restrict__ bias, float* __restrict__ C, int M) {
    const int K = 128, NOUT = 40;
    __shared__ __nv_bfloat16 sAh[128][40];
    __shared__ __nv_bfloat16 sAl[128][40];
    __shared__ __nv_bfloat16 sBh[64][40];
    __shared__ __nv_bfloat16 sBl[64][40];

    const int tid = threadIdx.x;
    const int wid = tid >> 5, lane = tid & 31;
    const int m0 = blockIdx.y * 128;
    const int wm = wid >> 1;
    const int wn = wid & 1;

    int lrowA[2], lqA[2];
#pragma unroll
    for (int it = 0; it < 2; it++) {
        int idx = it * 256 + tid;
        lrowA[it] = idx >> 2;
        lqA[it] = idx & 3;
    }
    const int lrowB = tid >> 2, lqB = tid & 3;

    float acc[2][4][4];
#pragma unroll
    for (int a = 0; a < 2; a++)
#pragma unroll
        for (int b = 0; b < 4; b++)
#pragma unroll
            for (int c = 0; c < 4; c++) acc[a][b][c] = 0.f;

    uint4 pAh[2], pAl[2], pBh1, pBl1;

    auto fetch = [&](int ch) {
        const int k0 = ch * 32;
#pragma unroll
        for (int it = 0; it < 2; it++) {
            int row = lrowA[it], q = lqA[it];
            if (m0 + row < M) {
                size_t off = (size_t)(m0 + row) * K + k0 + q * 8;
                pAh[it] = *(const uint4*)&Ah[off];
                pAl[it] = *(const uint4*)&Al[off];
            } else {
                pAh[it] = make_uint4(0, 0, 0, 0);
                pAl[it] = make_uint4(0, 0, 0, 0);
            }
        }
        size_t offb = (size_t)lrowB * K + k0 + lqB * 8;
        pBh1 = *(const uint4*)&Bh[offb];
        pBl1 = *(const uint4*)&Bl[offb];
    };
    auto commit = [&]() {
#pragma unroll
        for (int it = 0; it < 2; it++) {
            int row = lrowA[it], q = lqA[it];
            *(uint4*)&sAh[row][q * 8] = pAh[it];
            *(uint4*)&sAl[row][q * 8] = pAl[it];
        }
        *(uint4*)&sBh[lrowB][lqB * 8] = pBh1;
        *(uint4*)&sBl[lrowB][lqB * 8] = pBl1;
    };

    const int nch = K / 32;
    fetch(0);
    commit();

    for (int ch = 0; ch < nch; ch++) {
        __syncthreads();
        if (ch + 1 < nch) fetch(ch + 1);

#pragma unroll
        for (int kk = 0; kk < 32; kk += 16) {
            const int r = lane & 15;
            const int koff = (lane >> 4) << 3;
            uint32_t bhf[2][4], blf[2][4];
#pragma unroll
            for (int nt = 0; nt < 2; nt++) {
                ldm4(bhf[nt], smem_u32(&sBh[wn * 32 + nt * 16 + r][kk + koff]));
                ldm4(blf[nt], smem_u32(&sBl[wn * 32 + nt * 16 + r][kk + koff]));
            }
#pragma unroll
            for (int mt = 0; mt < 2; mt++) {
                uint32_t af[4];
                ldm4(af, smem_u32(&sAh[wm * 32 + mt * 16 + r][kk + koff]));
#pragma unroll
                for (int j = 0; j < 4; j++) {
                    mma16816(acc[mt][j], af, bhf[j >> 1][j & 1], bhf[j >> 1][2 + (j & 1)]);
                    mma16816(acc[mt][j], af, blf[j >> 1][j & 1], blf[j >> 1][2 + (j & 1)]);
                }
            }
#pragma unroll
            for (int mt = 0; mt < 2; mt++) {
                uint32_t af[4];
                ldm4(af, smem_u32(&sAl[wm * 32 + mt * 16 + r][kk + koff]));
#pragma unroll
                for (int j = 0; j < 4; j++)
                    mma16816(acc[mt][j], af, bhf[j >> 1][j & 1], bhf[j >> 1][2 + (j & 1)]);
            }
        }
        __syncthreads();
        if (ch + 1 < nch) commit();
    }

    const int rbase = m0 + wm * 32 + (lane >> 2);
    const int cbase = wn * 32 + (lane & 3) * 2;
#pragma unroll
    for (int mt = 0; mt < 2; mt++) {
        int m = rbase + mt * 16;
#pragma unroll
        for (int j = 0; j < 4; j++) {
            int c = cbase + j * 8;
            if (c >= NOUT) continue;
            float bv0 = bias[c], bv1 = bias[c + 1];
            if (m < M) {
                float2 o = make_float2(acc[mt][j][0] + bv0, acc[mt][j][1] + bv1);
                *(float2*)&C[(size_t)m * NOUT + c] = o;
            }
            if (m + 8 < M) {
                float2 o = make_float2(acc[mt][j][2] + bv0, acc[mt][j][3] + bv1);
                *(float2*)&C[(size_t)(m + 8) * NOUT + c] = o;
            }
        }
    }
}

// ---------------- SPMM (feature-tiled) ----------------
template <int DTOT, int LANES, int ROWS, bool RELU, int OUT>
__global__ void k_spmm(const float* __restrict__ s, float* __restrict__ h,
                       __nv_bfloat16* __restrict__ oh, __nv_bfloat16* __restrict__ ol,
                       int c0) {
    int row = blockIdx.x * ROWS + threadIdx.y;
    if (row >= NN) return;
    const int x = c0 + threadIdx.x;
    const float4* s4 = (const float4*)s;
    int e = g_rowptr[row];
    const int end = g_rowptr[row + 1];
    float4 acc = make_float4(0.f, 0.f, 0.f, 0.f);
    for (; e + 1 < end; e += 2) {
        int sc0 = g_srcs[e], sc1 = g_srcs[e + 1];
        float v0 = g_vals[e], v1 = g_vals[e + 1];
        float4 t0 = s4[(size_t)sc0 * (DTOT / 4) + x];
        float4 t1 = s4[(size_t)sc1 * (DTOT / 4) + x];
        acc.x += v0 * t0.x + v1 * t1.x;
        acc.y += v0 * t0.y + v1 * t1.y;
        acc.z += v0 * t0.z + v1 * t1.z;
        acc.w += v0 * t0.w + v1 * t1.w;
    }
    if (e < end) {
        int sc = g_srcs[e];
        float v = g_vals[e];
        float4 t = s4[(size_t)sc * (DTOT / 4) + x];
        acc.x += v * t.x; acc.y += v * t.y; acc.z += v * t.z; acc.w += v * t.w;
    }
    if (RELU) {
        acc.x = fmaxf(acc.x, 0.f); acc.y = fmaxf(acc.y, 0.f);
        acc.z = fmaxf(acc.z, 0.f); acc.w = fmaxf(acc.w, 0.f);
    }
    if (OUT == 0) {
        ((float4*)h)[(size_t)row * (DTOT / 4) + x] = acc;
    } else {
        uint32_t h0, l0, h1, l1;
        split2(acc.x, acc.y, h0, l0);
        split2(acc.z, acc.w, h1, l1);
        ((uint2*)oh)[(size_t)row * (DTOT / 4) + x] = make_uint2(h0, h1);
        ((uint2*)ol)[(size_t)row * (DTOT / 4) + x] = make_uint2(l0, l1);
    }
}

// ---------------- log_softmax ----------------
__global__ void k_lsm(const float* __restrict__ logits, float* __restrict__ out) {
    int row = blockIdx.x * blockDim.y + threadIdx.y;
    if (row >= NN) return;
    const int l = threadIdx.x;
    float a = logits[(size_t)row * 40 + l];
    float b = (l < 8) ? logits[(size_t)row * 40 + 32 + l] : -1e30f;
    float m = fmaxf(a, b);
#pragma unroll
    for (int off = 16; off > 0; off >>= 1)
        m = fmaxf(m, __shfl_xor_sync(0xFFFFFFFFu, m, off));
    float sum = expf(a - m) + ((l < 8) ? expf(b - m) : 0.f);
#pragma unroll
    for (int off = 16; off > 0; off >>= 1)
        sum += __shfl_xor_sync(0xFFFFFFFFu, sum, off);
    float ls = m + logf(sum);
    out[(size_t)row * 40 + l] = a - ls;
    if (l < 8) out[(size_t)row * 40 + 32 + l] = b - ls;
}

// ---------------- launch ----------------
extern "C" void kernel_launch(void* const* d_in, const int* in_sizes, int n_in,
                              void* d_out, int out_size) {
    const float* x    = (const float*)d_in[0];
    const int*   esrc = (const int*)d_in[1];
    const int*   edst = (const int*)d_in[2];
    const float* eval = (const float*)d_in[3];
    const float* W0   = (const float*)d_in[4];
    const float* b0   = (const float*)d_in[5];
    const float* W1   = (const float*)d_in[6];
    const float* b1   = (const float*)d_in[7];
    const float* W2   = (const float*)d_in[8];
    const float* b2   = (const float*)d_in[9];
    float* out = (float*)d_out;

    float *ps, *ph;
    __nv_bfloat16 *pah, *pal, *pw1h, *pw1l, *pw2h, *pw2l;
    int8_t *pw0q1, *pw0q2;
    cudaGetSymbolAddress((void**)&ps, g_s);
    cudaGetSymbolAddress((void**)&ph, g_h);
    cudaGetSymbolAddress((void**)&pah, g_ah);
    cudaGetSymbolAddress((void**)&pal, g_al);
    cudaGetSymbolAddress((void**)&pw0q1, g_w0q1);
    cudaGetSymbolAddress((void**)&pw0q2, g_w0q2);
    cudaGetSymbolAddress((void**)&pw1h, g_w1h);
    cudaGetSymbolAddress((void**)&pw1l, g_w1l);
    cudaGetSymbolAddress((void**)&pw2h, g_w2h);
    cudaGetSymbolAddress((void**)&pw2l, g_w2l);

    static cudaStream_t s2 = nullptr;
    static cudaEvent_t evFork = nullptr, evCsr = nullptr;
    if (s2 == nullptr) {
        cudaStreamCreateWithFlags(&s2, cudaStreamNonBlocking);
        cudaEventCreateWithFlags(&evFork, cudaEventDisableTiming);
        cudaEventCreateWithFlags(&evCsr, cudaEventDisableTiming);
    }

    // fork: W1/W2 conversion + CSR build on s2 (all off the critical path)
    cudaEventRecord(evFork, 0);
    cudaStreamWaitEvent(s2, evFork, 0);
    k_cvt_w<<<(256 * 128 + 255) / 256, 256, 0, s2>>>(W1, pw1h, pw1l, 256, 128);
    k_cvt_w_pad<<<(64 * 128 + 255) / 256, 256, 0, s2>>>(W2, pw2h, pw2l, 128, 40, 64);
    k_zero_deg<<<(NN + 255) / 256, 256, 0, s2>>>();
    k_hist<<<(NE + 255) / 256, 256, 0, s2>>>(edst);
    k_scan<<<1, 1024, 0, s2>>>();
    k_scatter<<<(NE + 255) / 256, 256, 0, s2>>>(esrc, edst, eval);
    cudaEventRecord(evCsr, s2);

    // main stream: W0 int8 limbs + layer-0 int8 GEMM (x quantized in-kernel)
    k_cvt_w0_s8<<<(256 * 512 + 255) / 256, 256>>>(W0, pw0q1, pw0q2);

    const int MB = (NN + 127) / 128;  // 782

    // Layer 0: s0 = x @ W0 + b0 (K=512, N=256), two-limb int8 tensor cores
    k_mma_gemm_s8<<<dim3(2, MB), 256>>>(x, pw0q1, pw0q2, b0, ps, NN);

    // join: SPMM needs the CSR
    cudaStreamWaitEvent(0, evCsr, 0);

    // SPMM0 + relu -> bf16 hi/lo (2 feature passes of 128 cols)
    k_spmm<256, 32, 8, true, 1><<<(NN + 7) / 8, dim3(32, 8)>>>(ps, nullptr, pah, pal, 0);
    k_spmm<256, 32, 8, true, 1><<<(NN + 7) / 8, dim3(32, 8)>>>(ps, nullptr, pah, pal, 32);

    // Layer 1: s1 = h0 @ W1 + b1 (K=256, N=128) -> ps
    k_mma_gemm<<<dim3(1, MB), 256>>>(pah, pal, pw1h, pw1l, b1, ps, NN, 256, 128);

    // SPMM1 + relu -> bf16 hi/lo (2 feature passes of 64 cols) -> pah/pal
    k_spmm<128, 16, 16, true, 1><<<(NN + 15) / 16, dim3(16, 16)>>>(ps, nullptr, pah, pal, 0);
    k_spmm<128, 16, 16, true, 1><<<(NN + 15) / 16, dim3(16, 16)>>>(ps, nullptr, pah, pal, 16);

    // Layer 2: s2 = h1 @ W2 + b2 (K=128, N=40 padded to 64) tensor cores -> ph
    k_mma_gemm64<<<dim3(1, MB), 256>>>(pah, pal, pw2h, pw2l, b2, ph, NN);

    // SPMM2: logits -> ps
    k_spmm<40, 10, 16, false, 0><<<(NN + 15) / 16, dim3(10, 16)>>>(ph, ps, nullptr, nullptr, 0);

    k_lsm<<<(NN + 7) / 8, dim3(32, 8)>>>(ps, out);
}

// round 12
// speedup vs baseline: 1.2371x; 1.2371x over previous
#include <cuda_runtime.h>
#include <cuda_bf16.h>
#include <math.h>
#include <stdint.h>

#define NN 100000
#define NE 3200000

// ---------------- scratch ----------------
__device__ float g_s[(size_t)NN * 256];
__device__ float g_h[(size_t)NN * 256];
__device__ __nv_bfloat16 g_ah[(size_t)NN * 256];   // activation hi
__device__ __nv_bfloat16 g_al[(size_t)NN * 256];   // activation lo
__device__ __nv_bfloat16 g_w0h[512 * 256], g_w0l[512 * 256];   // [N][K] n-major
__device__ __nv_bfloat16 g_w1h[256 * 128], g_w1l[256 * 128];
__device__ __nv_bfloat16 g_w2h[64 * 128],  g_w2l[64 * 128];    // N padded 40->64
__device__ int   g_deg[NN];
__device__ int   g_rowptr[NN + 1];
__device__ int   g_cursor[NN];
__device__ int   g_srcs[NE];
__device__ float g_vals[NE];

// ---------------- helpers ----------------
__device__ __forceinline__ uint32_t smem_u32(const void* p) {
    uint32_t a;
    asm("{ .reg .u64 t; cvta.to.shared.u64 t, %1; cvt.u32.u64 %0, t; }" : "=r"(a) : "l"(p));
    return a;
}

__device__ __forceinline__ void split2(float a, float b, uint32_t& hi, uint32_t& lo) {
    __nv_bfloat16 ah = __float2bfloat16(a), bh = __float2bfloat16(b);
    float ar = a - __bfloat162float(ah);
    float br = b - __bfloat162float(bh);
    __nv_bfloat16 al = __float2bfloat16(ar), bl = __float2bfloat16(br);
    hi = (uint32_t)__bfloat16_as_ushort(ah) | ((uint32_t)__bfloat16_as_ushort(bh) << 16);
    lo = (uint32_t)__bfloat16_as_ushort(al) | ((uint32_t)__bfloat16_as_ushort(bl) << 16);
}

__device__ __forceinline__ void ldm4(uint32_t* r, uint32_t addr) {
    asm volatile("ldmatrix.sync.aligned.m8n8.x4.shared.b16 {%0,%1,%2,%3}, [%4];"
                 : "=r"(r[0]), "=r"(r[1]), "=r"(r[2]), "=r"(r[3]) : "r"(addr));
}

__device__ __forceinline__ void mma16816(float* c, const uint32_t* a, uint32_t b0, uint32_t b1) {
    asm volatile(
        "mma.sync.aligned.m16n8k16.row.col.f32.bf16.bf16.f32 "
        "{%0,%1,%2,%3}, {%4,%5,%6,%7}, {%8,%9}, {%0,%1,%2,%3};"
        : "+f"(c[0]), "+f"(c[1]), "+f"(c[2]), "+f"(c[3])
        : "r"(a[0]), "r"(a[1]), "r"(a[2]), "r"(a[3]), "r"(b0), "r"(b1));
}

// ---------------- CSR build ----------------
__global__ void k_zero_deg() {
    int i = blockIdx.x * blockDim.x + threadIdx.x;
    if (i < NN) g_deg[i] = 0;
}
__global__ void k_hist(const int* __restrict__ dst) {
    int e = blockIdx.x * blockDim.x + threadIdx.x;
    if (e < NE) atomicAdd(&g_deg[dst[e]], 1);
}
__global__ void k_scan() {
    __shared__ int ssum[1024];
    const int t = threadIdx.x;
    const int CH = (NN + 1023) / 1024;
    int s0 = t * CH, s1 = s0 + CH; if (s1 > NN) s1 = NN;
    int sum = 0;
    for (int i = s0; i < s1; i++) sum += g_deg[i];
    ssum[t] = sum;
    __syncthreads();
    for (int off = 1; off < 1024; off <<= 1) {
        int v = (t >= off) ? ssum[t - off] : 0;
        __syncthreads();
        ssum[t] += v;
        __syncthreads();
    }
    int run = (t == 0) ? 0 : ssum[t - 1];
    for (int i = s0; i < s1; i++) { g_rowptr[i] = run; g_cursor[i] = run; run += g_deg[i]; }
    if (t == 1023) g_rowptr[NN] = ssum[1023];
}
__global__ void k_scatter(const int* __restrict__ src, const int* __restrict__ dst,
                          const float* __restrict__ val) {
    int e = blockIdx.x * blockDim.x + threadIdx.x;
    if (e >= NE) return;
    int d = dst[e];
    int p = atomicAdd(&g_cursor[d], 1);
    g_srcs[p] = src[e];
    g_vals[p] = val[e];
}

// ---------------- weight converters ----------------
__global__ void k_cvt_w(const float* __restrict__ W, __nv_bfloat16* __restrict__ wh,
                        __nv_bfloat16* __restrict__ wl, int K, int N) {
    int idx = blockIdx.x * blockDim.x + threadIdx.x;
    if (idx >= N * K) return;
    int n = idx / K, k = idx % K;
    float v = W[(size_t)k * N + n];
    __nv_bfloat16 h = __float2bfloat16(v);
    float r = v - __bfloat162float(h);
    wh[idx] = h;
    wl[idx] = __float2bfloat16(r);
}
__global__ void k_cvt_w_pad(const float* __restrict__ W, __nv_bfloat16* __restrict__ wh,
                            __nv_bfloat16* __restrict__ wl, int K, int N, int Npad) {
    int idx = blockIdx.x * blockDim.x + threadIdx.x;
    if (idx >= Npad * K) return;
    int n = idx / K, k = idx % K;
    float v = (n < N) ? W[(size_t)k * N + n] : 0.f;
    __nv_bfloat16 h = __float2bfloat16(v);
    float r = v - __bfloat162float(h);
    wh[idx] = h;
    wl[idx] = __float2bfloat16(r);
}

// ---------------- tensor-core GEMM (fp32 A, fused split): C = A @ B^T + bias ----------------
__global__ void __launch_bounds__(256, 2)
k_mma_gemm_f32a(const float* __restrict__ A,
                const __nv_bfloat16* __restrict__ Bh, const __nv_bfloat16* __restrict__ Bl,
                const float* __restrict__ bias, float* __restrict__ C,
                int M, int K, int N) {
    __shared__ __nv_bfloat16 sAh[128][40];
    __shared__ __nv_bfloat16 sAl[128][40];
    __shared__ __nv_bfloat16 sBh[128][40];
    __shared__ __nv_bfloat16 sBl[128][40];

    const int tid = threadIdx.x;
    const int wid = tid >> 5, lane = tid & 31;
    const int m0 = blockIdx.y * 128;
    const int n0 = blockIdx.x * 128;
    const int wm = wid >> 2;
    const int wn = wid & 3;

    int lrow[2], lq[2];
#pragma unroll
    for (int it = 0; it < 2; it++) {
        int idx = it * 256 + tid;
        lrow[it] = idx >> 2;
        lq[it] = idx & 3;
    }

    float acc[4][4][4];
#pragma unroll
    for (int a = 0; a < 4; a++)
#pragma unroll
        for (int b = 0; b < 4; b++)
#pragma unroll
            for (int c = 0; c < 4; c++) acc[a][b][c] = 0.f;

    float4 fA[2][2];
    uint4 pBh[2], pBl[2];

    auto fetch = [&](int ch) {
        const int k0 = ch * 32;
#pragma unroll
        for (int it = 0; it < 2; it++) {
            int row = lrow[it], q = lq[it];
            if (m0 + row < M) {
                const float* p = &A[(size_t)(m0 + row) * K + k0 + q * 8];
                fA[it][0] = *(const float4*)p;
                fA[it][1] = *(const float4*)(p + 4);
            } else {
                fA[it][0] = make_float4(0.f, 0.f, 0.f, 0.f);
                fA[it][1] = make_float4(0.f, 0.f, 0.f, 0.f);
            }
            size_t offb = (size_t)(n0 + row) * K + k0 + q * 8;
            pBh[it] = *(const uint4*)&Bh[offb];
            pBl[it] = *(const uint4*)&Bl[offb];
        }
    };
    auto commit = [&]() {
#pragma unroll
        for (int it = 0; it < 2; it++) {
            int row = lrow[it], q = lq[it];
            uint4 vh, vl;
            split2(fA[it][0].x, fA[it][0].y, vh.x, vl.x);
            split2(fA[it][0].z, fA[it][0].w, vh.y, vl.y);
            split2(fA[it][1].x, fA[it][1].y, vh.z, vl.z);
            split2(fA[it][1].z, fA[it][1].w, vh.w, vl.w);
            *(uint4*)&sAh[row][q * 8] = vh;
            *(uint4*)&sAl[row][q * 8] = vl;
            *(uint4*)&sBh[row][q * 8] = pBh[it];
            *(uint4*)&sBl[row][q * 8] = pBl[it];
        }
    };

    const int nch = K / 32;
    fetch(0);
    commit();

    for (int ch = 0; ch < nch; ch++) {
        __syncthreads();
        if (ch + 1 < nch) fetch(ch + 1);

#pragma unroll
        for (int kk = 0; kk < 32; kk += 16) {
            const int r = lane & 15;
            const int koff = (lane >> 4) << 3;
            uint32_t bhf[2][4], blf[2][4];
#pragma unroll
            for (int nt = 0; nt < 2; nt++) {
                ldm4(bhf[nt], smem_u32(&sBh[wn * 32 + nt * 16 + r][kk + koff]));
                ldm4(blf[nt], smem_u32(&sBl[wn * 32 + nt * 16 + r][kk + koff]));
            }
#pragma unroll
            for (int mt = 0; mt < 4; mt++) {
                uint32_t af[4];
                ldm4(af, smem_u32(&sAh[wm * 64 + mt * 16 + r][kk + koff]));
#pragma unroll
                for (int j = 0; j < 4; j++) {
                    mma16816(acc[mt][j], af, bhf[j >> 1][j & 1], bhf[j >> 1][2 + (j & 1)]);
                    mma16816(acc[mt][j], af, blf[j >> 1][j & 1], blf[j >> 1][2 + (j & 1)]);
                }
            }
#pragma unroll
            for (int mt = 0; mt < 4; mt++) {
                uint32_t af[4];
                ldm4(af, smem_u32(&sAl[wm * 64 + mt * 16 + r][kk + koff]));
#pragma unroll
                for (int j = 0; j < 4; j++)
                    mma16816(acc[mt][j], af, bhf[j >> 1][j & 1], bhf[j >> 1][2 + (j & 1)]);
            }
        }
        __syncthreads();
        if (ch + 1 < nch) commit();
    }

    const int rbase = m0 + wm * 64 + (lane >> 2);
    const int cbase = n0 + wn * 32 + (lane & 3) * 2;
#pragma unroll
    for (int mt = 0; mt < 4; mt++) {
        int m = rbase + mt * 16;
#pragma unroll
        for (int j = 0; j < 4; j++) {
            int c = cbase + j * 8;
            float bv0 = bias[c], bv1 = bias[c + 1];
            if (m < M) {
                float2 o = make_float2(acc[mt][j][0] + bv0, acc[mt][j][1] + bv1);
                *(float2*)&C[(size_t)m * N + c] = o;
            }
            if (m + 8 < M) {
                float2 o = make_float2(acc[mt][j][2] + bv0, acc[mt][j][3] + bv1);
                *(float2*)&C[(size_t)(m + 8) * N + c] = o;
            }
        }
    }
}

// ---------------- tensor-core GEMM (bf16 hi/lo A): C = A @ B^T + bias ----------------
__global__ void __launch_bounds__(256, 2)
k_mma_gemm(const __nv_bfloat16* __restrict__ Ah, const __nv_bfloat16* __restrict__ Al,
           const __nv_bfloat16* __restrict__ Bh, const __nv_bfloat16* __restrict__ Bl,
           const float* __restrict__ bias, float* __restrict__ C,
           int M, int K, int N) {
    __shared__ __nv_bfloat16 sAh[128][40];
    __shared__ __nv_bfloat16 sAl[128][40];
    __shared__ __nv_bfloat16 sBh[128][40];
    __shared__ __nv_bfloat16 sBl[128][40];

    const int tid = threadIdx.x;
    const int wid = tid >> 5, lane = tid & 31;
    const int m0 = blockIdx.y * 128;
    const int n0 = blockIdx.x * 128;
    const int wm = wid >> 2;
    const int wn = wid & 3;

    int lrow[2], lq[2];
#pragma unroll
    for (int it = 0; it < 2; it++) {
        int idx = it * 256 + tid;
        lrow[it] = idx >> 2;
        lq[it] = idx & 3;
    }

    float acc[4][4][4];
#pragma unroll
    for (int a = 0; a < 4; a++)
#pragma unroll
        for (int b = 0; b < 4; b++)
#pragma unroll
            for (int c = 0; c < 4; c++) acc[a][b][c] = 0.f;

    uint4 pAh[2], pAl[2], pBh[2], pBl[2];

    auto fetch = [&](int ch) {
        const int k0 = ch * 32;
#pragma unroll
        for (int it = 0; it < 2; it++) {
            int row = lrow[it], q = lq[it];
            if (m0 + row < M) {
                size_t off = (size_t)(m0 + row) * K + k0 + q * 8;
                pAh[it] = *(const uint4*)&Ah[off];
                pAl[it] = *(const uint4*)&Al[off];
            } else {
                pAh[it] = make_uint4(0, 0, 0, 0);
                pAl[it] = make_uint4(0, 0, 0, 0);
            }
            size_t offb = (size_t)(n0 + row) * K + k0 + q * 8;
            pBh[it] = *(const uint4*)&Bh[offb];
            pBl[it] = *(const uint4*)&Bl[offb];
        }
    };
    auto commit = [&]() {
#pragma unroll
        for (int it = 0; it < 2; it++) {
            int row = lrow[it], q = lq[it];
            *(uint4*)&sAh[row][q * 8] = pAh[it];
            *(uint4*)&sAl[row][q * 8] = pAl[it];
            *(uint4*)&sBh[row][q * 8] = pBh[it];
            *(uint4*)&sBl[row][q * 8] = pBl[it];
        }
    };

    const int nch = K / 32;
    fetch(0);
    commit();

    for (int ch = 0; ch < nch; ch++) {
        __syncthreads();
        if (ch + 1 < nch) fetch(ch + 1);

#pragma unroll
        for (int kk = 0; kk < 32; kk += 16) {
            const int r = lane & 15;
            const int koff = (lane >> 4) << 3;
            uint32_t bhf[2][4], blf[2][4];
#pragma unroll
            for (int nt = 0; nt < 2; nt++) {
                ldm4(bhf[nt], smem_u32(&sBh[wn * 32 + nt * 16 + r][kk + koff]));
                ldm4(blf[nt], smem_u32(&sBl[wn * 32 + nt * 16 + r][kk + koff]));
            }
#pragma unroll
            for (int mt = 0; mt < 4; mt++) {
                uint32_t af[4];
                ldm4(af, smem_u32(&sAh[wm * 64 + mt * 16 + r][kk + koff]));
#pragma unroll
                for (int j = 0; j < 4; j++) {
                    mma16816(acc[mt][j], af, bhf[j >> 1][j & 1], bhf[j >> 1][2 + (j & 1)]);
                    mma16816(acc[mt][j], af, blf[j >> 1][j & 1], blf[j >> 1][2 + (j & 1)]);
                }
            }
#pragma unroll
            for (int mt = 0; mt < 4; mt++) {
                uint32_t af[4];
                ldm4(af, smem_u32(&sAl[wm * 64 + mt * 16 + r][kk + koff]));
#pragma unroll
                for (int j = 0; j < 4; j++)
                    mma16816(acc[mt][j], af, bhf[j >> 1][j & 1], bhf[j >> 1][2 + (j & 1)]);
            }
        }
        __syncthreads();
        if (ch + 1 < nch) commit();
    }

    const int rbase = m0 + wm * 64 + (lane >> 2);
    const int cbase = n0 + wn * 32 + (lane & 3) * 2;
#pragma unroll
    for (int mt = 0; mt < 4; mt++) {
        int m = rbase + mt * 16;
#pragma unroll
        for (int j = 0; j < 4; j++) {
            int c = cbase + j * 8;
            float bv0 = bias[c], bv1 = bias[c + 1];
            if (m < M) {
                float2 o = make_float2(acc[mt][j][0] + bv0, acc[mt][j][1] + bv1);
                *(float2*)&C[(size_t)m * N + c] = o;
            }
            if (m + 8 < M) {
                float2 o = make_float2(acc[mt][j][2] + bv0, acc[mt][j][3] + bv1);
                *(float2*)&C[(size_t)(m + 8) * N + c] = o;
            }
        }
    }
}

// ---------------- tensor-core GEMM, layer 2: K=128, Npad=64, Nout=40 ----------------
__global__ void __launch_bounds__(256, 2)
k_mma_gemm64(const __nv_bfloat16* __restrict__ Ah, const __nv_bfloat16* __restrict__ Al,
             const __nv_bfloat16* __restrict__ Bh, const __nv_bfloat16* __restrict__ Bl,
             const float* __restrict__ bias, float* __restrict__ C, int M) {
    const int K = 128, NOUT = 40;
    __shared__ __nv_bfloat16 sAh[128][40];
    __shared__ __nv_bfloat16 sAl[128][40];
    __shared__ __nv_bfloat16 sBh[64][40];
    __shared__ __nv_bfloat16 sBl[64][40];

    const int tid = threadIdx.x;
    const int wid = tid >> 5, lane = tid & 31;
    const int m0 = blockIdx.y * 128;
    const int wm = wid >> 1;
    const int wn = wid & 1;

    int lrowA[2], lqA[2];
#pragma unroll
    for (int it = 0; it < 2; it++) {
        int idx = it * 256 + tid;
        lrowA[it] = idx >> 2;
        lqA[it] = idx & 3;
    }
    const int lrowB = tid >> 2, lqB = tid & 3;

    float acc[2][4][4];
#pragma unroll
    for (int a = 0; a < 2; a++)
#pragma unroll
        for (int b = 0; b < 4; b++)
#pragma unroll
            for (int c = 0; c < 4; c++) acc[a][b][c] = 0.f;

    uint4 pAh[2], pAl[2], pBh1, pBl1;

    auto fetch = [&](int ch) {
        const int k0 = ch * 32;
#pragma unroll
        for (int it = 0; it < 2; it++) {
            int row = lrowA[it], q = lqA[it];
            if (m0 + row < M) {
                size_t off = (size_t)(m0 + row) * K + k0 + q * 8;
                pAh[it] = *(const uint4*)&Ah[off];
                pAl[it] = *(const uint4*)&Al[off];
            } else {
                pAh[it] = make_uint4(0, 0, 0, 0);
                pAl[it] = make_uint4(0, 0, 0, 0);
            }
        }
        size_t offb = (size_t)lrowB * K + k0 + lqB * 8;
        pBh1 = *(const uint4*)&Bh[offb];
        pBl1 = *(const uint4*)&Bl[offb];
    };
    auto commit = [&]() {
#pragma unroll
        for (int it = 0; it < 2; it++) {
            int row = lrowA[it], q = lqA[it];
            *(uint4*)&sAh[row][q * 8] = pAh[it];
            *(uint4*)&sAl[row][q * 8] = pAl[it];
        }
        *(uint4*)&sBh[lrowB][lqB * 8] = pBh1;
        *(uint4*)&sBl[lrowB][lqB * 8] = pBl1;
    };

    const int nch = K / 32;
    fetch(0);
    commit();

    for (int ch = 0; ch < nch; ch++) {
        __syncthreads();
        if (ch + 1 < nch) fetch(ch + 1);

#pragma unroll
        for (int kk = 0; kk < 32; kk += 16) {
            const int r = lane & 15;
            const int koff = (lane >> 4) << 3;
            uint32_t bhf[2][4], blf[2][4];
#pragma unroll
            for (int nt = 0; nt < 2; nt++) {
                ldm4(bhf[nt], smem_u32(&sBh[wn * 32 + nt * 16 + r][kk + koff]));
                ldm4(blf[nt], smem_u32(&sBl[wn * 32 + nt * 16 + r][kk + koff]));
            }
#pragma unroll
            for (int mt = 0; mt < 2; mt++) {
                uint32_t af[4];
                ldm4(af, smem_u32(&sAh[wm * 32 + mt * 16 + r][kk + koff]));
#pragma unroll
                for (int j = 0; j < 4; j++) {
                    mma16816(acc[mt][j], af, bhf[j >> 1][j & 1], bhf[j >> 1][2 + (j & 1)]);
                    mma16816(acc[mt][j], af, blf[j >> 1][j & 1], blf[j >> 1][2 + (j & 1)]);
                }
            }
#pragma unroll
            for (int mt = 0; mt < 2; mt++) {
                uint32_t af[4];
                ldm4(af, smem_u32(&sAl[wm * 32 + mt * 16 + r][kk + koff]));
#pragma unroll
                for (int j = 0; j < 4; j++)
                    mma16816(acc[mt][j], af, bhf[j >> 1][j & 1], bhf[j >> 1][2 + (j & 1)]);
            }
        }
        __syncthreads();
        if (ch + 1 < nch) commit();
    }

    const int rbase = m0 + wm * 32 + (lane >> 2);
    const int cbase = wn * 32 + (lane & 3) * 2;
#pragma unroll
    for (int mt = 0; mt < 2; mt++) {
        int m = rbase + mt * 16;
#pragma unroll
        for (int j = 0; j < 4; j++) {
            int c = cbase + j * 8;
            if (c >= NOUT) continue;
            float bv0 = bias[c], bv1 = bias[c + 1];
            if (m < M) {
                float2 o = make_float2(acc[mt][j][0] + bv0, acc[mt][j][1] + bv1);
                *(float2*)&C[(size_t)m * NOUT + c] = o;
            }
            if (m + 8 < M) {
                float2 o = make_float2(acc[mt][j][2] + bv0, acc[mt][j][3] + bv1);
                *(float2*)&C[(size_t)(m + 8) * NOUT + c] = o;
            }
        }
    }
}

// ---------------- SPMM (feature-tiled) ----------------
template <int DTOT, int LANES, int ROWS, bool RELU, int OUT>
__global__ void k_spmm(const float* __restrict__ s, float* __restrict__ h,
                       __nv_bfloat16* __restrict__ oh, __nv_bfloat16* __restrict__ ol,
                       int c0) {
    int row = blockIdx.x * ROWS + threadIdx.y;
    if (row >= NN) return;
    const int x = c0 + threadIdx.x;
    const float4* s4 = (const float4*)s;
    int e = g_rowptr[row];
    const int end = g_rowptr[row + 1];
    float4 acc = make_float4(0.f, 0.f, 0.f, 0.f);
    for (; e + 1 < end; e += 2) {
        int sc0 = g_srcs[e], sc1 = g_srcs[e + 1];
        float v0 = g_vals[e], v1 = g_vals[e + 1];
        float4 t0 = s4[(size_t)sc0 * (DTOT / 4) + x];
        float4 t1 = s4[(size_t)sc1 * (DTOT / 4) + x];
        acc.x += v0 * t0.x + v1 * t1.x;
        acc.y += v0 * t0.y + v1 * t1.y;
        acc.z += v0 * t0.z + v1 * t1.z;
        acc.w += v0 * t0.w + v1 * t1.w;
    }
    if (e < end) {
        int sc = g_srcs[e];
        float v = g_vals[e];
        float4 t = s4[(size_t)sc * (DTOT / 4) + x];
        acc.x += v * t.x; acc.y += v * t.y; acc.z += v * t.z; acc.w += v * t.w;
    }
    if (RELU) {
        acc.x = fmaxf(acc.x, 0.f); acc.y = fmaxf(acc.y, 0.f);
        acc.z = fmaxf(acc.z, 0.f); acc.w = fmaxf(acc.w, 0.f);
    }
    if (OUT == 0) {
        ((float4*)h)[(size_t)row * (DTOT / 4) + x] = acc;
    } else {
        uint32_t h0, l0, h1, l1;
        split2(acc.x, acc.y, h0, l0);
        split2(acc.z, acc.w, h1, l1);
        ((uint2*)oh)[(size_t)row * (DTOT / 4) + x] = make_uint2(h0, h1);
        ((uint2*)ol)[(size_t)row * (DTOT / 4) + x] = make_uint2(l0, l1);
    }
}

// ---------------- fused SPMM(D=40) + log_softmax: one warp per row ----------------
__global__ void k_spmm_lsm(const float* __restrict__ s, float* __restrict__ out) {
    int row = blockIdx.x * blockDim.y + threadIdx.y;
    if (row >= NN) return;
    const int x = threadIdx.x;          // 0..31; lanes 0..9 gather
    float4 acc = make_float4(0.f, 0.f, 0.f, 0.f);
    if (x < 10) {
        const float4* s4 = (const float4*)s;
        int e = g_rowptr[row];
        const int end = g_rowptr[row + 1];
        for (; e + 1 < end; e += 2) {
            int sc0 = g_srcs[e], sc1 = g_srcs[e + 1];
            float v0 = g_vals[e], v1 = g_vals[e + 1];
            float4 t0 = s4[(size_t)sc0 * 10 + x];
            float4 t1 = s4[(size_t)sc1 * 10 + x];
            acc.x += v0 * t0.x + v1 * t1.x;
            acc.y += v0 * t0.y + v1 * t1.y;
            acc.z += v0 * t0.z + v1 * t1.z;
            acc.w += v0 * t0.w + v1 * t1.w;
        }
        if (e < end) {
            int sc = g_srcs[e];
            float v = g_vals[e];
            float4 t = s4[(size_t)sc * 10 + x];
            acc.x += v * t.x; acc.y += v * t.y; acc.z += v * t.z; acc.w += v * t.w;
        }
    }
    // warp-wide log-softmax over the 40 values held by lanes 0..9
    float m = (x < 10) ? fmaxf(fmaxf(acc.x, acc.y), fmaxf(acc.z, acc.w)) : -1e30f;
#pragma unroll
    for (int off = 16; off > 0; off >>= 1)
        m = fmaxf(m, __shfl_xor_sync(0xFFFFFFFFu, m, off));
    float sum = (x < 10)
        ? (expf(acc.x - m) + expf(acc.y - m) + expf(acc.z - m) + expf(acc.w - m))
        : 0.f;
#pragma unroll
    for (int off = 16; off > 0; off >>= 1)
        sum += __shfl_xor_sync(0xFFFFFFFFu, sum, off);
    float ls = m + logf(sum);
    if (x < 10) {
        float4 o = make_float4(acc.x - ls, acc.y - ls, acc.z - ls, acc.w - ls);
        ((float4*)out)[(size_t)row * 10 + x] = o;
    }
}

// ---------------- launch ----------------
extern "C" void kernel_launch(void* const* d_in, const int* in_sizes, int n_in,
                              void* d_out, int out_size) {
    const float* x    = (const float*)d_in[0];
    const int*   esrc = (const int*)d_in[1];
    const int*   edst = (const int*)d_in[2];
    const float* eval = (const float*)d_in[3];
    const float* W0   = (const float*)d_in[4];
    const float* b0   = (const float*)d_in[5];
    const float* W1   = (const float*)d_in[6];
    const float* b1   = (const float*)d_in[7];
    const float* W2   = (const float*)d_in[8];
    const float* b2   = (const float*)d_in[9];
    float* out = (float*)d_out;

    float *ps, *ph;
    __nv_bfloat16 *pah, *pal, *pw0h, *pw0l, *pw1h, *pw1l, *pw2h, *pw2l;
    cudaGetSymbolAddress((void**)&ps, g_s);
    cudaGetSymbolAddress((void**)&ph, g_h);
    cudaGetSymbolAddress((void**)&pah, g_ah);
    cudaGetSymbolAddress((void**)&pal, g_al);
    cudaGetSymbolAddress((void**)&pw0h, g_w0h);
    cudaGetSymbolAddress((void**)&pw0l, g_w0l);
    cudaGetSymbolAddress((void**)&pw1h, g_w1h);
    cudaGetSymbolAddress((void**)&pw1l, g_w1l);
    cudaGetSymbolAddress((void**)&pw2h, g_w2h);
    cudaGetSymbolAddress((void**)&pw2l, g_w2l);

    static cudaStream_t s2 = nullptr;
    static cudaEvent_t evFork = nullptr, evCsr = nullptr;
    if (s2 == nullptr) {
        cudaStreamCreateWithFlags(&s2, cudaStreamNonBlocking);
        cudaEventCreateWithFlags(&evFork, cudaEventDisableTiming);
        cudaEventCreateWithFlags(&evCsr, cudaEventDisableTiming);
    }

    // fork: W1/W2 conversions + CSR build on s2 (off the critical path)
    cudaEventRecord(evFork, 0);
    cudaStreamWaitEvent(s2, evFork, 0);
    k_cvt_w<<<(256 * 128 + 255) / 256, 256, 0, s2>>>(W1, pw1h, pw1l, 256, 128);
    k_cvt_w_pad<<<(64 * 128 + 255) / 256, 256, 0, s2>>>(W2, pw2h, pw2l, 128, 40, 64);
    k_zero_deg<<<(NN + 255) / 256, 256, 0, s2>>>();
    k_hist<<<(NE + 255) / 256, 256, 0, s2>>>(edst);
    k_scan<<<1, 1024, 0, s2>>>();
    k_scatter<<<(NE + 255) / 256, 256, 0, s2>>>(esrc, edst, eval);
    cudaEventRecord(evCsr, s2);

    // main stream: W0 conversion + layer-0 GEMM (A split fused in-kernel)
    k_cvt_w<<<(512 * 256 + 255) / 256, 256>>>(W0, pw0h, pw0l, 512, 256);

    const int MB = (NN + 127) / 128;  // 782

    // Layer 0: s0 = x @ W0 + b0 (K=512, N=256), fp32 A with fused hi/lo split
    k_mma_gemm_f32a<<<dim3(2, MB), 256>>>(x, pw0h, pw0l, b0, ps, NN, 512, 256);

    // join: SPMM needs the CSR
    cudaStreamWaitEvent(0, evCsr, 0);

    // SPMM0 + relu -> bf16 hi/lo (2 feature passes of 128 cols)
    k_spmm<256, 32, 8, true, 1><<<(NN + 7) / 8, dim3(32, 8)>>>(ps, nullptr, pah, pal, 0);
    k_spmm<256, 32, 8, true, 1><<<(NN + 7) / 8, dim3(32, 8)>>>(ps, nullptr, pah, pal, 32);

    // Layer 1: s1 = h0 @ W1 + b1 (K=256, N=128) -> ps
    k_mma_gemm<<<dim3(1, MB), 256>>>(pah, pal, pw1h, pw1l, b1, ps, NN, 256, 128);

    // SPMM1 + relu -> bf16 hi/lo (2 feature passes of 64 cols) -> pah/pal
    k_spmm<128, 16, 16, true, 1><<<(NN + 15) / 16, dim3(16, 16)>>>(ps, nullptr, pah, pal, 0);
    k_spmm<128, 16, 16, true, 1><<<(NN + 15) / 16, dim3(16, 16)>>>(ps, nullptr, pah, pal, 16);

    // Layer 2: s2 = h1 @ W2 + b2 (K=128, N=40 padded to 64) tensor cores -> ph
    k_mma_gemm64<<<dim3(1, MB), 256>>>(pah, pal, pw2h, pw2l, b2, ph, NN);

    // fused SPMM2 + log_softmax -> out
    k_spmm_lsm<<<(NN + 7) / 8, dim3(32, 8)>>>(ph, out);
}

// round 13
// speedup vs baseline: 1.4819x; 1.1979x over previous
#include <cuda_runtime.h>
#include <cuda_bf16.h>
#include <math.h>
#include <stdint.h>

#define NN 100000
#define NE 3200000

// ---------------- scratch ----------------
__device__ float g_s[(size_t)NN * 256];
__device__ float g_h[(size_t)NN * 256];
__device__ __nv_bfloat16 g_ah[(size_t)NN * 256];   // activation hi
__device__ __nv_bfloat16 g_al[(size_t)NN * 256];   // activation lo
__device__ __nv_bfloat16 g_w0h[512 * 256], g_w0l[512 * 256];   // [N][K] n-major
__device__ __nv_bfloat16 g_w1h[256 * 128], g_w1l[256 * 128];
__device__ __nv_bfloat16 g_w2h[64 * 128],  g_w2l[64 * 128];    // N padded 40->64
__device__ int   g_deg[NN];
__device__ int   g_rowptr[NN + 1];
__device__ int   g_cursor[NN];
__device__ int   g_srcs[NE];
__device__ float g_vals[NE];

// ---------------- helpers ----------------
__device__ __forceinline__ uint32_t smem_u32(const void* p) {
    uint32_t a;
    asm("{ .reg .u64 t; cvta.to.shared.u64 t, %1; cvt.u32.u64 %0, t; }" : "=r"(a) : "l"(p));
    return a;
}

__device__ __forceinline__ void split2(float a, float b, uint32_t& hi, uint32_t& lo) {
    __nv_bfloat16 ah = __float2bfloat16(a), bh = __float2bfloat16(b);
    float ar = a - __bfloat162float(ah);
    float br = b - __bfloat162float(bh);
    __nv_bfloat16 al = __float2bfloat16(ar), bl = __float2bfloat16(br);
    hi = (uint32_t)__bfloat16_as_ushort(ah) | ((uint32_t)__bfloat16_as_ushort(bh) << 16);
    lo = (uint32_t)__bfloat16_as_ushort(al) | ((uint32_t)__bfloat16_as_ushort(bl) << 16);
}

__device__ __forceinline__ void ldm4(uint32_t* r, uint32_t addr) {
    asm volatile("ldmatrix.sync.aligned.m8n8.x4.shared.b16 {%0,%1,%2,%3}, [%4];"
                 : "=r"(r[0]), "=r"(r[1]), "=r"(r[2]), "=r"(r[3]) : "r"(addr));
}

__device__ __forceinline__ void mma16816(float* c, const uint32_t* a, uint32_t b0, uint32_t b1) {
    asm volatile(
        "mma.sync.aligned.m16n8k16.row.col.f32.bf16.bf16.f32 "
        "{%0,%1,%2,%3}, {%4,%5,%6,%7}, {%8,%9}, {%0,%1,%2,%3};"
        : "+f"(c[0]), "+f"(c[1]), "+f"(c[2]), "+f"(c[3])
        : "r"(a[0]), "r"(a[1]), "r"(a[2]), "r"(a[3]), "r"(b0), "r"(b1));
}

// ---------------- CSR build ----------------
__global__ void k_zero_deg() {
    int i = blockIdx.x * blockDim.x + threadIdx.x;
    if (i < NN) g_deg[i] = 0;
}
__global__ void k_hist(const int* __restrict__ dst) {
    int e = blockIdx.x * blockDim.x + threadIdx.x;
    if (e < NE) atomicAdd(&g_deg[dst[e]], 1);
}
__global__ void k_scan() {
    __shared__ int ssum[1024];
    const int t = threadIdx.x;
    const int CH = (NN + 1023) / 1024;
    int s0 = t * CH, s1 = s0 + CH; if (s1 > NN) s1 = NN;
    int sum = 0;
    for (int i = s0; i < s1; i++) sum += g_deg[i];
    ssum[t] = sum;
    __syncthreads();
    for (int off = 1; off < 1024; off <<= 1) {
        int v = (t >= off) ? ssum[t - off] : 0;
        __syncthreads();
        ssum[t] += v;
        __syncthreads();
    }
    int run = (t == 0) ? 0 : ssum[t - 1];
    for (int i = s0; i < s1; i++) { g_rowptr[i] = run; g_cursor[i] = run; run += g_deg[i]; }
    if (t == 1023) g_rowptr[NN] = ssum[1023];
}
__global__ void k_scatter(const int* __restrict__ src, const int* __restrict__ dst,
                          const float* __restrict__ val) {
    int e = blockIdx.x * blockDim.x + threadIdx.x;
    if (e >= NE) return;
    int d = dst[e];
    int p = atomicAdd(&g_cursor[d], 1);
    g_srcs[p] = src[e];
    g_vals[p] = val[e];
}

// ---------------- weight converters ----------------
__global__ void k_cvt_w(const float* __restrict__ W, __nv_bfloat16* __restrict__ wh,
                        __nv_bfloat16* __restrict__ wl, int K, int N) {
    int idx = blockIdx.x * blockDim.x + threadIdx.x;
    if (idx >= N * K) return;
    int n = idx / K, k = idx % K;
    float v = W[(size_t)k * N + n];
    __nv_bfloat16 h = __float2bfloat16(v);
    float r = v - __bfloat162float(h);
    wh[idx] = h;
    wl[idx] = __float2bfloat16(r);
}
__global__ void k_cvt_w_pad(const float* __restrict__ W, __nv_bfloat16* __restrict__ wh,
                            __nv_bfloat16* __restrict__ wl, int K, int N, int Npad) {
    int idx = blockIdx.x * blockDim.x + threadIdx.x;
    if (idx >= Npad * K) return;
    int n = idx / K, k = idx % K;
    float v = (n < N) ? W[(size_t)k * N + n] : 0.f;
    __nv_bfloat16 h = __float2bfloat16(v);
    float r = v - __bfloat162float(h);
    wh[idx] = h;
    wl[idx] = __float2bfloat16(r);
}

// ---------------- tensor-core GEMM (fp32 A, fused split): C = A @ B^T + bias ----------------
__global__ void __launch_bounds__(256, 2)
k_mma_gemm_f32a(const float* __restrict__ A,
                const __nv_bfloat16* __restrict__ Bh, const __nv_bfloat16* __restrict__ Bl,
                const float* __restrict__ bias, float* __restrict__ C,
                int M, int K, int N) {
    __shared__ __nv_bfloat16 sAh[128][40];
    __shared__ __nv_bfloat16 sAl[128][40];
    __shared__ __nv_bfloat16 sBh[128][40];
    __shared__ __nv_bfloat16 sBl[128][40];

    const int tid = threadIdx.x;
    const int wid = tid >> 5, lane = tid & 31;
    const int m0 = blockIdx.y * 128;
    const int n0 = blockIdx.x * 128;
    const int wm = wid >> 2;
    const int wn = wid & 3;

    int lrow[2], lq[2];
#pragma unroll
    for (int it = 0; it < 2; it++) {
        int idx = it * 256 + tid;
        lrow[it] = idx >> 2;
        lq[it] = idx & 3;
    }

    float acc[4][4][4];
#pragma unroll
    for (int a = 0; a < 4; a++)
#pragma unroll
        for (int b = 0; b < 4; b++)
#pragma unroll
            for (int c = 0; c < 4; c++) acc[a][b][c] = 0.f;

    float4 fA[2][2];
    uint4 pBh[2], pBl[2];

    auto fetch = [&](int ch) {
        const int k0 = ch * 32;
#pragma unroll
        for (int it = 0; it < 2; it++) {
            int row = lrow[it], q = lq[it];
            if (m0 + row < M) {
                const float* p = &A[(size_t)(m0 + row) * K + k0 + q * 8];
                fA[it][0] = *(const float4*)p;
                fA[it][1] = *(const float4*)(p + 4);
            } else {
                fA[it][0] = make_float4(0.f, 0.f, 0.f, 0.f);
                fA[it][1] = make_float4(0.f, 0.f, 0.f, 0.f);
            }
            size_t offb = (size_t)(n0 + row) * K + k0 + q * 8;
            pBh[it] = *(const uint4*)&Bh[offb];
            pBl[it] = *(const uint4*)&Bl[offb];
        }
    };
    auto commit = [&]() {
#pragma unroll
        for (int it = 0; it < 2; it++) {
            int row = lrow[it], q = lq[it];
            uint4 vh, vl;
            split2(fA[it][0].x, fA[it][0].y, vh.x, vl.x);
            split2(fA[it][0].z, fA[it][0].w, vh.y, vl.y);
            split2(fA[it][1].x, fA[it][1].y, vh.z, vl.z);
            split2(fA[it][1].z, fA[it][1].w, vh.w, vl.w);
            *(uint4*)&sAh[row][q * 8] = vh;
            *(uint4*)&sAl[row][q * 8] = vl;
            *(uint4*)&sBh[row][q * 8] = pBh[it];
            *(uint4*)&sBl[row][q * 8] = pBl[it];
        }
    };

    const int nch = K / 32;
    fetch(0);
    commit();

    for (int ch = 0; ch < nch; ch++) {
        __syncthreads();
        if (ch + 1 < nch) fetch(ch + 1);

#pragma unroll
        for (int kk = 0; kk < 32; kk += 16) {
            const int r = lane & 15;
            const int koff = (lane >> 4) << 3;
            uint32_t bhf[2][4], blf[2][4];
#pragma unroll
            for (int nt = 0; nt < 2; nt++) {
                ldm4(bhf[nt], smem_u32(&sBh[wn * 32 + nt * 16 + r][kk + koff]));
                ldm4(blf[nt], smem_u32(&sBl[wn * 32 + nt * 16 + r][kk + koff]));
            }
#pragma unroll
            for (int mt = 0; mt < 4; mt++) {
                uint32_t af[4];
                ldm4(af, smem_u32(&sAh[wm * 64 + mt * 16 + r][kk + koff]));
#pragma unroll
                for (int j = 0; j < 4; j++) {
                    mma16816(acc[mt][j], af, bhf[j >> 1][j & 1], bhf[j >> 1][2 + (j & 1)]);
                    mma16816(acc[mt][j], af, blf[j >> 1][j & 1], blf[j >> 1][2 + (j & 1)]);
                }
            }
#pragma unroll
            for (int mt = 0; mt < 4; mt++) {
                uint32_t af[4];
                ldm4(af, smem_u32(&sAl[wm * 64 + mt * 16 + r][kk + koff]));
#pragma unroll
                for (int j = 0; j < 4; j++)
                    mma16816(acc[mt][j], af, bhf[j >> 1][j & 1], bhf[j >> 1][2 + (j & 1)]);
            }
        }
        __syncthreads();
        if (ch + 1 < nch) commit();
    }

    const int rbase = m0 + wm * 64 + (lane >> 2);
    const int cbase = n0 + wn * 32 + (lane & 3) * 2;
#pragma unroll
    for (int mt = 0; mt < 4; mt++) {
        int m = rbase + mt * 16;
#pragma unroll
        for (int j = 0; j < 4; j++) {
            int c = cbase + j * 8;
            float bv0 = bias[c], bv1 = bias[c + 1];
            if (m < M) {
                float2 o = make_float2(acc[mt][j][0] + bv0, acc[mt][j][1] + bv1);
                *(float2*)&C[(size_t)m * N + c] = o;
            }
            if (m + 8 < M) {
                float2 o = make_float2(acc[mt][j][2] + bv0, acc[mt][j][3] + bv1);
                *(float2*)&C[(size_t)(m + 8) * N + c] = o;
            }
        }
    }
}

// ---------------- tensor-core GEMM (bf16 hi/lo A): C = A @ B^T + bias ----------------
__global__ void __launch_bounds__(256, 2)
k_mma_gemm(const __nv_bfloat16* __restrict__ Ah, const __nv_bfloat16* __restrict__ Al,
           const __nv_bfloat16* __restrict__ Bh, const __nv_bfloat16* __restrict__ Bl,
           const float* __restrict__ bias, float* __restrict__ C,
           int M, int K, int N) {
    __shared__ __nv_bfloat16 sAh[128][40];
    __shared__ __nv_bfloat16 sAl[128][40];
    __shared__ __nv_bfloat16 sBh[128][40];
    __shared__ __nv_bfloat16 sBl[128][40];

    const int tid = threadIdx.x;
    const int wid = tid >> 5, lane = tid & 31;
    const int m0 = blockIdx.y * 128;
    const int n0 = blockIdx.x * 128;
    const int wm = wid >> 2;
    const int wn = wid & 3;

    int lrow[2], lq[2];
#pragma unroll
    for (int it = 0; it < 2; it++) {
        int idx = it * 256 + tid;
        lrow[it] = idx >> 2;
        lq[it] = idx & 3;
    }

    float acc[4][4][4];
#pragma unroll
    for (int a = 0; a < 4; a++)
#pragma unroll
        for (int b = 0; b < 4; b++)
#pragma unroll
            for (int c = 0; c < 4; c++) acc[a][b][c] = 0.f;

    uint4 pAh[2], pAl[2], pBh[2], pBl[2];

    auto fetch = [&](int ch) {
        const int k0 = ch * 32;
#pragma unroll
        for (int it = 0; it < 2; it++) {
            int row = lrow[it], q = lq[it];
            if (m0 + row < M) {
                size_t off = (size_t)(m0 + row) * K + k0 + q * 8;
                pAh[it] = *(const uint4*)&Ah[off];
                pAl[it] = *(const uint4*)&Al[off];
            } else {
                pAh[it] = make_uint4(0, 0, 0, 0);
                pAl[it] = make_uint4(0, 0, 0, 0);
            }
            size_t offb = (size_t)(n0 + row) * K + k0 + q * 8;
            pBh[it] = *(const uint4*)&Bh[offb];
            pBl[it] = *(const uint4*)&Bl[offb];
        }
    };
    auto commit = [&]() {
#pragma unroll
        for (int it = 0; it < 2; it++) {
            int row = lrow[it], q = lq[it];
            *(uint4*)&sAh[row][q * 8] = pAh[it];
            *(uint4*)&sAl[row][q * 8] = pAl[it];
            *(uint4*)&sBh[row][q * 8] = pBh[it];
            *(uint4*)&sBl[row][q * 8] = pBl[it];
        }
    };

    const int nch = K / 32;
    fetch(0);
    commit();

    for (int ch = 0; ch < nch; ch++) {
        __syncthreads();
        if (ch + 1 < nch) fetch(ch + 1);

#pragma unroll
        for (int kk = 0; kk < 32; kk += 16) {
            const int r = lane & 15;
            const int koff = (lane >> 4) << 3;
            uint32_t bhf[2][4], blf[2][4];
#pragma unroll
            for (int nt = 0; nt < 2; nt++) {
                ldm4(bhf[nt], smem_u32(&sBh[wn * 32 + nt * 16 + r][kk + koff]));
                ldm4(blf[nt], smem_u32(&sBl[wn * 32 + nt * 16 + r][kk + koff]));
            }
#pragma unroll
            for (int mt = 0; mt < 4; mt++) {
                uint32_t af[4];
                ldm4(af, smem_u32(&sAh[wm * 64 + mt * 16 + r][kk + koff]));
#pragma unroll
                for (int j = 0; j < 4; j++) {
                    mma16816(acc[mt][j], af, bhf[j >> 1][j & 1], bhf[j >> 1][2 + (j & 1)]);
                    mma16816(acc[mt][j], af, blf[j >> 1][j & 1], blf[j >> 1][2 + (j & 1)]);
                }
            }
#pragma unroll
            for (int mt = 0; mt < 4; mt++) {
                uint32_t af[4];
                ldm4(af, smem_u32(&sAl[wm * 64 + mt * 16 + r][kk + koff]));
#pragma unroll
                for (int j = 0; j < 4; j++)
                    mma16816(acc[mt][j], af, bhf[j >> 1][j & 1], bhf[j >> 1][2 + (j & 1)]);
            }
        }
        __syncthreads();
        if (ch + 1 < nch) commit();
    }

    const int rbase = m0 + wm * 64 + (lane >> 2);
    const int cbase = n0 + wn * 32 + (lane & 3) * 2;
#pragma unroll
    for (int mt = 0; mt < 4; mt++) {
        int m = rbase + mt * 16;
#pragma unroll
        for (int j = 0; j < 4; j++) {
            int c = cbase + j * 8;
            float bv0 = bias[c], bv1 = bias[c + 1];
            if (m < M) {
                float2 o = make_float2(acc[mt][j][0] + bv0, acc[mt][j][1] + bv1);
                *(float2*)&C[(size_t)m * N + c] = o;
            }
            if (m + 8 < M) {
                float2 o = make_float2(acc[mt][j][2] + bv0, acc[mt][j][3] + bv1);
                *(float2*)&C[(size_t)(m + 8) * N + c] = o;
            }
        }
    }
}

// ---------------- tensor-core GEMM, layer 2: K=128, Npad=64, Nout=40 ----------------
__global__ void __launch_bounds__(256, 2)
k_mma_gemm64(const __nv_bfloat16* __restrict__ Ah, const __nv_bfloat16* __restrict__ Al,
             const __nv_bfloat16* __restrict__ Bh, const __nv_bfloat16* __restrict__ Bl,
             const float* __restrict__ bias, float* __restrict__ C, int M) {
    const int K = 128, NOUT = 40;
    __shared__ __nv_bfloat16 sAh[128][40];
    __shared__ __nv_bfloat16 sAl[128][40];
    __shared__ __nv_bfloat16 sBh[64][40];
    __shared__ __nv_bfloat16 sBl[64][40];

    const int tid = threadIdx.x;
    const int wid = tid >> 5, lane = tid & 31;
    const int m0 = blockIdx.y * 128;
    const int wm = wid >> 1;
    const int wn = wid & 1;

    int lrowA[2], lqA[2];
#pragma unroll
    for (int it = 0; it < 2; it++) {
        int idx = it * 256 + tid;
        lrowA[it] = idx >> 2;
        lqA[it] = idx & 3;
    }
    const int lrowB = tid >> 2, lqB = tid & 3;

    float acc[2][4][4];
#pragma unroll
    for (int a = 0; a < 2; a++)
#pragma unroll
        for (int b = 0; b < 4; b++)
#pragma unroll
            for (int c = 0; c < 4; c++) acc[a][b][c] = 0.f;

    uint4 pAh[2], pAl[2], pBh1, pBl1;

    auto fetch = [&](int ch) {
        const int k0 = ch * 32;
#pragma unroll
        for (int it = 0; it < 2; it++) {
            int row = lrowA[it], q = lqA[it];
            if (m0 + row < M) {
                size_t off = (size_t)(m0 + row) * K + k0 + q * 8;
                pAh[it] = *(const uint4*)&Ah[off];
                pAl[it] = *(const uint4*)&Al[off];
            } else {
                pAh[it] = make_uint4(0, 0, 0, 0);
                pAl[it] = make_uint4(0, 0, 0, 0);
            }
        }
        size_t offb = (size_t)lrowB * K + k0 + lqB * 8;
        pBh1 = *(const uint4*)&Bh[offb];
        pBl1 = *(const uint4*)&Bl[offb];
    };
    auto commit = [&]() {
#pragma unroll
        for (int it = 0; it < 2; it++) {
            int row = lrowA[it], q = lqA[it];
            *(uint4*)&sAh[row][q * 8] = pAh[it];
            *(uint4*)&sAl[row][q * 8] = pAl[it];
        }
        *(uint4*)&sBh[lrowB][lqB * 8] = pBh1;
        *(uint4*)&sBl[lrowB][lqB * 8] = pBl1;
    };

    const int nch = K / 32;
    fetch(0);
    commit();

    for (int ch = 0; ch < nch; ch++) {
        __syncthreads();
        if (ch + 1 < nch) fetch(ch + 1);

#pragma unroll
        for (int kk = 0; kk < 32; kk += 16) {
            const int r = lane & 15;
            const int koff = (lane >> 4) << 3;
            uint32_t bhf[2][4], blf[2][4];
#pragma unroll
            for (int nt = 0; nt < 2; nt++) {
                ldm4(bhf[nt], smem_u32(&sBh[wn * 32 + nt * 16 + r][kk + koff]));
                ldm4(blf[nt], smem_u32(&sBl[wn * 32 + nt * 16 + r][kk + koff]));
            }
#pragma unroll
            for (int mt = 0; mt < 2; mt++) {
                uint32_t af[4];
                ldm4(af, smem_u32(&sAh[wm * 32 + mt * 16 + r][kk + koff]));
#pragma unroll
                for (int j = 0; j < 4; j++) {
                    mma16816(acc[mt][j], af, bhf[j >> 1][j & 1], bhf[j >> 1][2 + (j & 1)]);
                    mma16816(acc[mt][j], af, blf[j >> 1][j & 1], blf[j >> 1][2 + (j & 1)]);
                }
            }
#pragma unroll
            for (int mt = 0; mt < 2; mt++) {
                uint32_t af[4];
                ldm4(af, smem_u32(&sAl[wm * 32 + mt * 16 + r][kk + koff]));
#pragma unroll
                for (int j = 0; j < 4; j++)
                    mma16816(acc[mt][j], af, bhf[j >> 1][j & 1], bhf[j >> 1][2 + (j & 1)]);
            }
        }
        __syncthreads();
        if (ch + 1 < nch) commit();
    }

    const int rbase = m0 + wm * 32 + (lane >> 2);
    const int cbase = wn * 32 + (lane & 3) * 2;
#pragma unroll
    for (int mt = 0; mt < 2; mt++) {
        int m = rbase + mt * 16;
#pragma unroll
        for (int j = 0; j < 4; j++) {
            int c = cbase + j * 8;
            if (c >= NOUT) continue;
            float bv0 = bias[c], bv1 = bias[c + 1];
            if (m < M) {
                float2 o = make_float2(acc[mt][j][0] + bv0, acc[mt][j][1] + bv1);
                *(float2*)&C[(size_t)m * NOUT + c] = o;
            }
            if (m + 8 < M) {
                float2 o = make_float2(acc[mt][j][2] + bv0, acc[mt][j][3] + bv1);
                *(float2*)&C[(size_t)(m + 8) * NOUT + c] = o;
            }
        }
    }
}

// ---------------- SPMM (feature-tiled) ----------------
template <int DTOT, int LANES, int ROWS, bool RELU, int OUT>
__global__ void k_spmm(const float* __restrict__ s, float* __restrict__ h,
                       __nv_bfloat16* __restrict__ oh, __nv_bfloat16* __restrict__ ol,
                       int c0) {
    int row = blockIdx.x * ROWS + threadIdx.y;
    if (row >= NN) return;
    const int x = c0 + threadIdx.x;
    const float4* s4 = (const float4*)s;
    int e = g_rowptr[row];
    const int end = g_rowptr[row + 1];
    float4 acc = make_float4(0.f, 0.f, 0.f, 0.f);
    for (; e + 1 < end; e += 2) {
        int sc0 = g_srcs[e], sc1 = g_srcs[e + 1];
        float v0 = g_vals[e], v1 = g_vals[e + 1];
        float4 t0 = s4[(size_t)sc0 * (DTOT / 4) + x];
        float4 t1 = s4[(size_t)sc1 * (DTOT / 4) + x];
        acc.x += v0 * t0.x + v1 * t1.x;
        acc.y += v0 * t0.y + v1 * t1.y;
        acc.z += v0 * t0.z + v1 * t1.z;
        acc.w += v0 * t0.w + v1 * t1.w;
    }
    if (e < end) {
        int sc = g_srcs[e];
        float v = g_vals[e];
        float4 t = s4[(size_t)sc * (DTOT / 4) + x];
        acc.x += v * t.x; acc.y += v * t.y; acc.z += v * t.z; acc.w += v * t.w;
    }
    if (RELU) {
        acc.x = fmaxf(acc.x, 0.f); acc.y = fmaxf(acc.y, 0.f);
        acc.z = fmaxf(acc.z, 0.f); acc.w = fmaxf(acc.w, 0.f);
    }
    if (OUT == 0) {
        ((float4*)h)[(size_t)row * (DTOT / 4) + x] = acc;
    } else {
        uint32_t h0, l0, h1, l1;
        split2(acc.x, acc.y, h0, l0);
        split2(acc.z, acc.w, h1, l1);
        ((uint2*)oh)[(size_t)row * (DTOT / 4) + x] = make_uint2(h0, h1);
        ((uint2*)ol)[(size_t)row * (DTOT / 4) + x] = make_uint2(l0, l1);
    }
}

// ---------------- fused SPMM(D=40) + log_softmax: 1 warp/row, full-lane layout ----------------
// lane l accumulates feature l; lanes 0..7 additionally feature 32+l.
__global__ void k_spmm_lsm(const float* __restrict__ s, float* __restrict__ out) {
    int row = blockIdx.x * blockDim.y + threadIdx.y;
    if (row >= NN) return;
    const int l = threadIdx.x;          // 0..31
    float a = 0.f, b = 0.f;
    int e = g_rowptr[row];
    const int end = g_rowptr[row + 1];
    for (; e < end; e++) {
        int sc = g_srcs[e];
        float v = g_vals[e];
        const float* srow = s + (size_t)sc * 40;
        a += v * srow[l];
        if (l < 8) b += v * srow[32 + l];
    }
    float bb = (l < 8) ? b : -1e30f;
    float m = fmaxf(a, bb);
#pragma unroll
    for (int off = 16; off > 0; off >>= 1)
        m = fmaxf(m, __shfl_xor_sync(0xFFFFFFFFu, m, off));
    float sum = expf(a - m) + ((l < 8) ? expf(b - m) : 0.f);
#pragma unroll
    for (int off = 16; off > 0; off >>= 1)
        sum += __shfl_xor_sync(0xFFFFFFFFu, sum, off);
    float ls = m + logf(sum);
    out[(size_t)row * 40 + l] = a - ls;
    if (l < 8) out[(size_t)row * 40 + 32 + l] = b - ls;
}

// ---------------- launch ----------------
extern "C" void kernel_launch(void* const* d_in, const int* in_sizes, int n_in,
                              void* d_out, int out_size) {
    const float* x    = (const float*)d_in[0];
    const int*   esrc = (const int*)d_in[1];
    const int*   edst = (const int*)d_in[2];
    const float* eval = (const float*)d_in[3];
    const float* W0   = (const float*)d_in[4];
    const float* b0   = (const float*)d_in[5];
    const float* W1   = (const float*)d_in[6];
    const float* b1   = (const float*)d_in[7];
    const float* W2   = (const float*)d_in[8];
    const float* b2   = (const float*)d_in[9];
    float* out = (float*)d_out;

    float *ps, *ph;
    __nv_bfloat16 *pah, *pal, *pw0h, *pw0l, *pw1h, *pw1l, *pw2h, *pw2l;
    cudaGetSymbolAddress((void**)&ps, g_s);
    cudaGetSymbolAddress((void**)&ph, g_h);
    cudaGetSymbolAddress((void**)&pah, g_ah);
    cudaGetSymbolAddress((void**)&pal, g_al);
    cudaGetSymbolAddress((void**)&pw0h, g_w0h);
    cudaGetSymbolAddress((void**)&pw0l, g_w0l);
    cudaGetSymbolAddress((void**)&pw1h, g_w1h);
    cudaGetSymbolAddress((void**)&pw1l, g_w1l);
    cudaGetSymbolAddress((void**)&pw2h, g_w2h);
    cudaGetSymbolAddress((void**)&pw2l, g_w2l);

    static cudaStream_t s2 = nullptr;
    static cudaEvent_t evFork = nullptr, evCsr = nullptr;
    if (s2 == nullptr) {
        cudaStreamCreateWithFlags(&s2, cudaStreamNonBlocking);
        cudaEventCreateWithFlags(&evFork, cudaEventDisableTiming);
        cudaEventCreateWithFlags(&evCsr, cudaEventDisableTiming);
    }

    // fork: CSR build ONLY on s2 (round-10 schedule), concurrent with cvt_w + GEMM0
    cudaEventRecord(evFork, 0);
    cudaStreamWaitEvent(s2, evFork, 0);
    k_zero_deg<<<(NN + 255) / 256, 256, 0, s2>>>();
    k_hist<<<(NE + 255) / 256, 256, 0, s2>>>(edst);
    k_scan<<<1, 1024, 0, s2>>>();
    k_scatter<<<(NE + 255) / 256, 256, 0, s2>>>(esrc, edst, eval);
    cudaEventRecord(evCsr, s2);

    // main stream: ALL weight conversions (round-10 schedule) + layer-0 GEMM
    k_cvt_w<<<(512 * 256 + 255) / 256, 256>>>(W0, pw0h, pw0l, 512, 256);
    k_cvt_w<<<(256 * 128 + 255) / 256, 256>>>(W1, pw1h, pw1l, 256, 128);
    k_cvt_w_pad<<<(64 * 128 + 255) / 256, 256>>>(W2, pw2h, pw2l, 128, 40, 64);

    const int MB = (NN + 127) / 128;  // 782

    // Layer 0: s0 = x @ W0 + b0 (K=512, N=256), fp32 A with fused hi/lo split
    k_mma_gemm_f32a<<<dim3(2, MB), 256>>>(x, pw0h, pw0l, b0, ps, NN, 512, 256);

    // join: SPMM needs the CSR
    cudaStreamWaitEvent(0, evCsr, 0);

    // SPMM0 + relu -> bf16 hi/lo (2 feature passes of 128 cols)
    k_spmm<256, 32, 8, true, 1><<<(NN + 7) / 8, dim3(32, 8)>>>(ps, nullptr, pah, pal, 0);
    k_spmm<256, 32, 8, true, 1><<<(NN + 7) / 8, dim3(32, 8)>>>(ps, nullptr, pah, pal, 32);

    // Layer 1: s1 = h0 @ W1 + b1 (K=256, N=128) -> ps
    k_mma_gemm<<<dim3(1, MB), 256>>>(pah, pal, pw1h, pw1l, b1, ps, NN, 256, 128);

    // SPMM1 + relu -> bf16 hi/lo (2 feature passes of 64 cols) -> pah/pal
    k_spmm<128, 16, 16, true, 1><<<(NN + 15) / 16, dim3(16, 16)>>>(ps, nullptr, pah, pal, 0);
    k_spmm<128, 16, 16, true, 1><<<(NN + 15) / 16, dim3(16, 16)>>>(ps, nullptr, pah, pal, 16);

    // Layer 2: s2 = h1 @ W2 + b2 (K=128, N=40 padded to 64) tensor cores -> ph
    k_mma_gemm64<<<dim3(1, MB), 256>>>(pah, pal, pw2h, pw2l, b2, ph, NN);

    // fused SPMM2 + log_softmax (full-lane layout) -> out
    k_spmm_lsm<<<(NN + 7) / 8, dim3(32, 8)>>>(ph, out);
}

// round 14
// speedup vs baseline: 1.5777x; 1.0647x over previous
#include <cuda_runtime.h>
#include <cuda_bf16.h>
#include <cuda_fp16.h>
#include <math.h>
#include <stdint.h>

#define NN 100000
#define NE 3200000

// ---------------- scratch ----------------
__device__ float g_s[(size_t)NN * 256];            // also used as __half s0 buffer
__device__ float g_h[(size_t)NN * 256];
__device__ __nv_bfloat16 g_ah[(size_t)NN * 256];   // activation hi
__device__ __nv_bfloat16 g_al[(size_t)NN * 256];   // activation lo
__device__ __nv_bfloat16 g_w0h[512 * 256], g_w0l[512 * 256];   // [N][K] n-major
__device__ __nv_bfloat16 g_w1h[256 * 128], g_w1l[256 * 128];
__device__ __nv_bfloat16 g_w2h[64 * 128],  g_w2l[64 * 128];    // N padded 40->64
__device__ int   g_deg[NN];
__device__ int   g_rowptr[NN + 1];
__device__ int   g_cursor[NN];
__device__ int   g_srcs[NE];
__device__ float g_vals[NE];

// ---------------- helpers ----------------
__device__ __forceinline__ uint32_t smem_u32(const void* p) {
    uint32_t a;
    asm("{ .reg .u64 t; cvta.to.shared.u64 t, %1; cvt.u32.u64 %0, t; }" : "=r"(a) : "l"(p));
    return a;
}

__device__ __forceinline__ void split2(float a, float b, uint32_t& hi, uint32_t& lo) {
    __nv_bfloat16 ah = __float2bfloat16(a), bh = __float2bfloat16(b);
    float ar = a - __bfloat162float(ah);
    float br = b - __bfloat162float(bh);
    __nv_bfloat16 al = __float2bfloat16(ar), bl = __float2bfloat16(br);
    hi = (uint32_t)__bfloat16_as_ushort(ah) | ((uint32_t)__bfloat16_as_ushort(bh) << 16);
    lo = (uint32_t)__bfloat16_as_ushort(al) | ((uint32_t)__bfloat16_as_ushort(bl) << 16);
}

__device__ __forceinline__ void ldm4(uint32_t* r, uint32_t addr) {
    asm volatile("ldmatrix.sync.aligned.m8n8.x4.shared.b16 {%0,%1,%2,%3}, [%4];"
                 : "=r"(r[0]), "=r"(r[1]), "=r"(r[2]), "=r"(r[3]) : "r"(addr));
}

__device__ __forceinline__ void mma16816(float* c, const uint32_t* a, uint32_t b0, uint32_t b1) {
    asm volatile(
        "mma.sync.aligned.m16n8k16.row.col.f32.bf16.bf16.f32 "
        "{%0,%1,%2,%3}, {%4,%5,%6,%7}, {%8,%9}, {%0,%1,%2,%3};"
        : "+f"(c[0]), "+f"(c[1]), "+f"(c[2]), "+f"(c[3])
        : "r"(a[0]), "r"(a[1]), "r"(a[2]), "r"(a[3]), "r"(b0), "r"(b1));
}

// ---------------- CSR build ----------------
__global__ void k_zero_deg() {
    int i = blockIdx.x * blockDim.x + threadIdx.x;
    if (i < NN) g_deg[i] = 0;
}
__global__ void k_hist(const int* __restrict__ dst) {
    int e = blockIdx.x * blockDim.x + threadIdx.x;
    if (e < NE) atomicAdd(&g_deg[dst[e]], 1);
}
__global__ void k_scan() {
    __shared__ int ssum[1024];
    const int t = threadIdx.x;
    const int CH = (NN + 1023) / 1024;
    int s0 = t * CH, s1 = s0 + CH; if (s1 > NN) s1 = NN;
    int sum = 0;
    for (int i = s0; i < s1; i++) sum += g_deg[i];
    ssum[t] = sum;
    __syncthreads();
    for (int off = 1; off < 1024; off <<= 1) {
        int v = (t >= off) ? ssum[t - off] : 0;
        __syncthreads();
        ssum[t] += v;
        __syncthreads();
    }
    int run = (t == 0) ? 0 : ssum[t - 1];
    for (int i = s0; i < s1; i++) { g_rowptr[i] = run; g_cursor[i] = run; run += g_deg[i]; }
    if (t == 1023) g_rowptr[NN] = ssum[1023];
}
__global__ void k_scatter(const int* __restrict__ src, const int* __restrict__ dst,
                          const float* __restrict__ val) {
    int e = blockIdx.x * blockDim.x + threadIdx.x;
    if (e >= NE) return;
    int d = dst[e];
    int p = atomicAdd(&g_cursor[d], 1);
    g_srcs[p] = src[e];
    g_vals[p] = val[e];
}

// ---------------- weight converters ----------------
__global__ void k_cvt_w(const float* __restrict__ W, __nv_bfloat16* __restrict__ wh,
                        __nv_bfloat16* __restrict__ wl, int K, int N) {
    int idx = blockIdx.x * blockDim.x + threadIdx.x;
    if (idx >= N * K) return;
    int n = idx / K, k = idx % K;
    float v = W[(size_t)k * N + n];
    __nv_bfloat16 h = __float2bfloat16(v);
    float r = v - __bfloat162float(h);
    wh[idx] = h;
    wl[idx] = __float2bfloat16(r);
}
__global__ void k_cvt_w_pad(const float* __restrict__ W, __nv_bfloat16* __restrict__ wh,
                            __nv_bfloat16* __restrict__ wl, int K, int N, int Npad) {
    int idx = blockIdx.x * blockDim.x + threadIdx.x;
    if (idx >= Npad * K) return;
    int n = idx / K, k = idx % K;
    float v = (n < N) ? W[(size_t)k * N + n] : 0.f;
    __nv_bfloat16 h = __float2bfloat16(v);
    float r = v - __bfloat162float(h);
    wh[idx] = h;
    wl[idx] = __float2bfloat16(r);
}

// ---------------- tensor-core GEMM (fp32 A, fused split), fp16 output: s0 ----------------
__global__ void __launch_bounds__(256, 2)
k_mma_gemm_f32a(const float* __restrict__ A,
                const __nv_bfloat16* __restrict__ Bh, const __nv_bfloat16* __restrict__ Bl,
                const float* __restrict__ bias, __half* __restrict__ C,
                int M, int K, int N) {
    __shared__ __nv_bfloat16 sAh[128][40];
    __shared__ __nv_bfloat16 sAl[128][40];
    __shared__ __nv_bfloat16 sBh[128][40];
    __shared__ __nv_bfloat16 sBl[128][40];

    const int tid = threadIdx.x;
    const int wid = tid >> 5, lane = tid & 31;
    const int m0 = blockIdx.y * 128;
    const int n0 = blockIdx.x * 128;
    const int wm = wid >> 2;
    const int wn = wid & 3;

    int lrow[2], lq[2];
#pragma unroll
    for (int it = 0; it < 2; it++) {
        int idx = it * 256 + tid;
        lrow[it] = idx >> 2;
        lq[it] = idx & 3;
    }

    float acc[4][4][4];
#pragma unroll
    for (int a = 0; a < 4; a++)
#pragma unroll
        for (int b = 0; b < 4; b++)
#pragma unroll
            for (int c = 0; c < 4; c++) acc[a][b][c] = 0.f;

    float4 fA[2][2];
    uint4 pBh[2], pBl[2];

    auto fetch = [&](int ch) {
        const int k0 = ch * 32;
#pragma unroll
        for (int it = 0; it < 2; it++) {
            int row = lrow[it], q = lq[it];
            if (m0 + row < M) {
                const float* p = &A[(size_t)(m0 + row) * K + k0 + q * 8];
                fA[it][0] = *(const float4*)p;
                fA[it][1] = *(const float4*)(p + 4);
            } else {
                fA[it][0] = make_float4(0.f, 0.f, 0.f, 0.f);
                fA[it][1] = make_float4(0.f, 0.f, 0.f, 0.f);
            }
            size_t offb = (size_t)(n0 + row) * K + k0 + q * 8;
            pBh[it] = *(const uint4*)&Bh[offb];
            pBl[it] = *(const uint4*)&Bl[offb];
        }
    };
    auto commit = [&]() {
#pragma unroll
        for (int it = 0; it < 2; it++) {
            int row = lrow[it], q = lq[it];
            uint4 vh, vl;
            split2(fA[it][0].x, fA[it][0].y, vh.x, vl.x);
            split2(fA[it][0].z, fA[it][0].w, vh.y, vl.y);
            split2(fA[it][1].x, fA[it][1].y, vh.z, vl.z);
            split2(fA[it][1].z, fA[it][1].w, vh.w, vl.w);
            *(uint4*)&sAh[row][q * 8] = vh;
            *(uint4*)&sAl[row][q * 8] = vl;
            *(uint4*)&sBh[row][q * 8] = pBh[it];
            *(uint4*)&sBl[row][q * 8] = pBl[it];
        }
    };

    const int nch = K / 32;
    fetch(0);
    commit();

    for (int ch = 0; ch < nch; ch++) {
        __syncthreads();
        if (ch + 1 < nch) fetch(ch + 1);

#pragma unroll
        for (int kk = 0; kk < 32; kk += 16) {
            const int r = lane & 15;
            const int koff = (lane >> 4) << 3;
            uint32_t bhf[2][4], blf[2][4];
#pragma unroll
            for (int nt = 0; nt < 2; nt++) {
                ldm4(bhf[nt], smem_u32(&sBh[wn * 32 + nt * 16 + r][kk + koff]));
                ldm4(blf[nt], smem_u32(&sBl[wn * 32 + nt * 16 + r][kk + koff]));
            }
#pragma unroll
            for (int mt = 0; mt < 4; mt++) {
                uint32_t af[4];
                ldm4(af, smem_u32(&sAh[wm * 64 + mt * 16 + r][kk + koff]));
#pragma unroll
                for (int j = 0; j < 4; j++) {
                    mma16816(acc[mt][j], af, bhf[j >> 1][j & 1], bhf[j >> 1][2 + (j & 1)]);
                    mma16816(acc[mt][j], af, blf[j >> 1][j & 1], blf[j >> 1][2 + (j & 1)]);
                }
            }
#pragma unroll
            for (int mt = 0; mt < 4; mt++) {
                uint32_t af[4];
                ldm4(af, smem_u32(&sAl[wm * 64 + mt * 16 + r][kk + koff]));
#pragma unroll
                for (int j = 0; j < 4; j++)
                    mma16816(acc[mt][j], af, bhf[j >> 1][j & 1], bhf[j >> 1][2 + (j & 1)]);
            }
        }
        __syncthreads();
        if (ch + 1 < nch) commit();
    }

    // epilogue: fp16 store (s0 gathered by SPMM0 in half precision)
    const int rbase = m0 + wm * 64 + (lane >> 2);
    const int cbase = n0 + wn * 32 + (lane & 3) * 2;
#pragma unroll
    for (int mt = 0; mt < 4; mt++) {
        int m = rbase + mt * 16;
#pragma unroll
        for (int j = 0; j < 4; j++) {
            int c = cbase + j * 8;
            float bv0 = bias[c], bv1 = bias[c + 1];
            if (m < M)
                *(__half2*)&C[(size_t)m * N + c] =
                    __floats2half2_rn(acc[mt][j][0] + bv0, acc[mt][j][1] + bv1);
            if (m + 8 < M)
                *(__half2*)&C[(size_t)(m + 8) * N + c] =
                    __floats2half2_rn(acc[mt][j][2] + bv0, acc[mt][j][3] + bv1);
        }
    }
}

// ---------------- tensor-core GEMM (bf16 hi/lo A): C = A @ B^T + bias ----------------
__global__ void __launch_bounds__(256, 2)
k_mma_gemm(const __nv_bfloat16* __restrict__ Ah, const __nv_bfloat16* __restrict__ Al,
           const __nv_bfloat16* __restrict__ Bh, const __nv_bfloat16* __restrict__ Bl,
           const float* __restrict__ bias, float* __restrict__ C,
           int M, int K, int N) {
    __shared__ __nv_bfloat16 sAh[128][40];
    __shared__ __nv_bfloat16 sAl[128][40];
    __shared__ __nv_bfloat16 sBh[128][40];
    __shared__ __nv_bfloat16 sBl[128][40];

    const int tid = threadIdx.x;
    const int wid = tid >> 5, lane = tid & 31;
    const int m0 = blockIdx.y * 128;
    const int n0 = blockIdx.x * 128;
    const int wm = wid >> 2;
    const int wn = wid & 3;

    int lrow[2], lq[2];
#pragma unroll
    for (int it = 0; it < 2; it++) {
        int idx = it * 256 + tid;
        lrow[it] = idx >> 2;
        lq[it] = idx & 3;
    }

    float acc[4][4][4];
#pragma unroll
    for (int a = 0; a < 4; a++)
#pragma unroll
        for (int b = 0; b < 4; b++)
#pragma unroll
            for (int c = 0; c < 4; c++) acc[a][b][c] = 0.f;

    uint4 pAh[2], pAl[2], pBh[2], pBl[2];

    auto fetch = [&](int ch) {
        const int k0 = ch * 32;
#pragma unroll
        for (int it = 0; it < 2; it++) {
            int row = lrow[it], q = lq[it];
            if (m0 + row < M) {
                size_t off = (size_t)(m0 + row) * K + k0 + q * 8;
                pAh[it] = *(const uint4*)&Ah[off];
                pAl[it] = *(const uint4*)&Al[off];
            } else {
                pAh[it] = make_uint4(0, 0, 0, 0);
                pAl[it] = make_uint4(0, 0, 0, 0);
            }
            size_t offb = (size_t)(n0 + row) * K + k0 + q * 8;
            pBh[it] = *(const uint4*)&Bh[offb];
            pBl[it] = *(const uint4*)&Bl[offb];
        }
    };
    auto commit = [&]() {
#pragma unroll
        for (int it = 0; it < 2; it++) {
            int row = lrow[it], q = lq[it];
            *(uint4*)&sAh[row][q * 8] = pAh[it];
            *(uint4*)&sAl[row][q * 8] = pAl[it];
            *(uint4*)&sBh[row][q * 8] = pBh[it];
            *(uint4*)&sBl[row][q * 8] = pBl[it];
        }
    };

    const int nch = K / 32;
    fetch(0);
    commit();

    for (int ch = 0; ch < nch; ch++) {
        __syncthreads();
        if (ch + 1 < nch) fetch(ch + 1);

#pragma unroll
        for (int kk = 0; kk < 32; kk += 16) {
            const int r = lane & 15;
            const int koff = (lane >> 4) << 3;
            uint32_t bhf[2][4], blf[2][4];
#pragma unroll
            for (int nt = 0; nt < 2; nt++) {
                ldm4(bhf[nt], smem_u32(&sBh[wn * 32 + nt * 16 + r][kk + koff]));
                ldm4(blf[nt], smem_u32(&sBl[wn * 32 + nt * 16 + r][kk + koff]));
            }
#pragma unroll
            for (int mt = 0; mt < 4; mt++) {
                uint32_t af[4];
                ldm4(af, smem_u32(&sAh[wm * 64 + mt * 16 + r][kk + koff]));
#pragma unroll
                for (int j = 0; j < 4; j++) {
                    mma16816(acc[mt][j], af, bhf[j >> 1][j & 1], bhf[j >> 1][2 + (j & 1)]);
                    mma16816(acc[mt][j], af, blf[j >> 1][j & 1], blf[j >> 1][2 + (j & 1)]);
                }
            }
#pragma unroll
            for (int mt = 0; mt < 4; mt++) {
                uint32_t af[4];
                ldm4(af, smem_u32(&sAl[wm * 64 + mt * 16 + r][kk + koff]));
#pragma unroll
                for (int j = 0; j < 4; j++)
                    mma16816(acc[mt][j], af, bhf[j >> 1][j & 1], bhf[j >> 1][2 + (j & 1)]);
            }
        }
        __syncthreads();
        if (ch + 1 < nch) commit();
    }

    const int rbase = m0 + wm * 64 + (lane >> 2);
    const int cbase = n0 + wn * 32 + (lane & 3) * 2;
#pragma unroll
    for (int mt = 0; mt < 4; mt++) {
        int m = rbase + mt * 16;
#pragma unroll
        for (int j = 0; j < 4; j++) {
            int c = cbase + j * 8;
            float bv0 = bias[c], bv1 = bias[c + 1];
            if (m < M) {
                float2 o = make_float2(acc[mt][j][0] + bv0, acc[mt][j][1] + bv1);
                *(float2*)&C[(size_t)m * N + c] = o;
            }
            if (m + 8 < M) {
                float2 o = make_float2(acc[mt][j][2] + bv0, acc[mt][j][3] + bv1);
                *(float2*)&C[(size_t)(m + 8) * N + c] = o;
            }
        }
    }
}

// ---------------- tensor-core GEMM, layer 2: K=128, Npad=64, Nout=40 ----------------
__global__ void __launch_bounds__(256, 2)
k_mma_gemm64(const __nv_bfloat16* __restrict__ Ah, const __nv_bfloat16* __restrict__ Al,
             const __nv_bfloat16* __restrict__ Bh, const __nv_bfloat16* __restrict__ Bl,
             const float* __restrict__ bias, float* __restrict__ C, int M) {
    const int K = 128, NOUT = 40;
    __shared__ __nv_bfloat16 sAh[128][40];
    __shared__ __nv_bfloat16 sAl[128][40];
    __shared__ __nv_bfloat16 sBh[64][40];
    __shared__ __nv_bfloat16 sBl[64][40];

    const int tid = threadIdx.x;
    const int wid = tid >> 5, lane = tid & 31;
    const int m0 = blockIdx.y * 128;
    const int wm = wid >> 1;
    const int wn = wid & 1;

    int lrowA[2], lqA[2];
#pragma unroll
    for (int it = 0; it < 2; it++) {
        int idx = it * 256 + tid;
        lrowA[it] = idx >> 2;
        lqA[it] = idx & 3;
    }
    const int lrowB = tid >> 2, lqB = tid & 3;

    float acc[2][4][4];
#pragma unroll
    for (int a = 0; a < 2; a++)
#pragma unroll
        for (int b = 0; b < 4; b++)
#pragma unroll
            for (int c = 0; c < 4; c++) acc[a][b][c] = 0.f;

    uint4 pAh[2], pAl[2], pBh1, pBl1;

    auto fetch = [&](int ch) {
        const int k0 = ch * 32;
#pragma unroll
        for (int it = 0; it < 2; it++) {
            int row = lrowA[it], q = lqA[it];
            if (m0 + row < M) {
                size_t off = (size_t)(m0 + row) * K + k0 + q * 8;
                pAh[it] = *(const uint4*)&Ah[off];
                pAl[it] = *(const uint4*)&Al[off];
            } else {
                pAh[it] = make_uint4(0, 0, 0, 0);
                pAl[it] = make_uint4(0, 0, 0, 0);
            }
        }
        size_t offb = (size_t)lrowB * K + k0 + lqB * 8;
        pBh1 = *(const uint4*)&Bh[offb];
        pBl1 = *(const uint4*)&Bl[offb];
    };
    auto commit = [&]() {
#pragma unroll
        for (int it = 0; it < 2; it++) {
            int row = lrowA[it], q = lqA[it];
            *(uint4*)&sAh[row][q * 8] = pAh[it];
            *(uint4*)&sAl[row][q * 8] = pAl[it];
        }
        *(uint4*)&sBh[lrowB][lqB * 8] = pBh1;
        *(uint4*)&sBl[lrowB][lqB * 8] = pBl1;
    };

    const int nch = K / 32;
    fetch(0);
    commit();

    for (int ch = 0; ch < nch; ch++) {
        __syncthreads();
        if (ch + 1 < nch) fetch(ch + 1);

#pragma unroll
        for (int kk = 0; kk < 32; kk += 16) {
            const int r = lane & 15;
            const int koff = (lane >> 4) << 3;
            uint32_t bhf[2][4], blf[2][4];
#pragma unroll
            for (int nt = 0; nt < 2; nt++) {
                ldm4(bhf[nt], smem_u32(&sBh[wn * 32 + nt * 16 + r][kk + koff]));
                ldm4(blf[nt], smem_u32(&sBl[wn * 32 + nt * 16 + r][kk + koff]));
            }
#pragma unroll
            for (int mt = 0; mt < 2; mt++) {
                uint32_t af[4];
                ldm4(af, smem_u32(&sAh[wm * 32 + mt * 16 + r][kk + koff]));
#pragma unroll
                for (int j = 0; j < 4; j++) {
                    mma16816(acc[mt][j], af, bhf[j >> 1][j & 1], bhf[j >> 1][2 + (j & 1)]);
                    mma16816(acc[mt][j], af, blf[j >> 1][j & 1], blf[j >> 1][2 + (j & 1)]);
                }
            }
#pragma unroll
            for (int mt = 0; mt < 2; mt++) {
                uint32_t af[4];
                ldm4(af, smem_u32(&sAl[wm * 32 + mt * 16 + r][kk + koff]));
#pragma unroll
                for (int j = 0; j < 4; j++)
                    mma16816(acc[mt][j], af, bhf[j >> 1][j & 1], bhf[j >> 1][2 + (j & 1)]);
            }
        }
        __syncthreads();
        if (ch + 1 < nch) commit();
    }

    const int rbase = m0 + wm * 32 + (lane >> 2);
    const int cbase = wn * 32 + (lane & 3) * 2;
#pragma unroll
    for (int mt = 0; mt < 2; mt++) {
        int m = rbase + mt * 16;
#pragma unroll
        for (int j = 0; j < 4; j++) {
            int c = cbase + j * 8;
            if (c >= NOUT) continue;
            float bv0 = bias[c], bv1 = bias[c + 1];
            if (m < M) {
                float2 o = make_float2(acc[mt][j][0] + bv0, acc[mt][j][1] + bv1);
                *(float2*)&C[(size_t)m * NOUT + c] = o;
            }
            if (m + 8 < M) {
                float2 o = make_float2(acc[mt][j][2] + bv0, acc[mt][j][3] + bv1);
                *(float2*)&C[(size_t)(m + 8) * NOUT + c] = o;
            }
        }
    }
}

// ---------------- SPMM0: fp16 input, single pass, 8 features/lane -> bf16 hi/lo ----------------
__global__ void k_spmm0_h(const __half* __restrict__ s,
                          __nv_bfloat16* __restrict__ oh, __nv_bfloat16* __restrict__ ol) {
    int row = blockIdx.x * blockDim.y + threadIdx.y;
    if (row >= NN) return;
    const int x = threadIdx.x;                       // 0..31; features [8x, 8x+8)
    const uint4* s4 = (const uint4*)s;               // 32 uint4 per 256-half row
    float acc[8];
#pragma unroll
    for (int i = 0; i < 8; i++) acc[i] = 0.f;
    int e = g_rowptr[row];
    const int end = g_rowptr[row + 1];
    for (; e + 1 < end; e += 2) {
        int sc0 = g_srcs[e], sc1 = g_srcs[e + 1];
        float v0 = g_vals[e], v1 = g_vals[e + 1];
        uint4 t0 = s4[(size_t)sc0 * 32 + x];
        uint4 t1 = s4[(size_t)sc1 * 32 + x];
        const __half2* h0 = (const __half2*)&t0;
        const __half2* h1 = (const __half2*)&t1;
#pragma unroll
        for (int i = 0; i < 4; i++) {
            float2 f0 = __half22float2(h0[i]);
            float2 f1 = __half22float2(h1[i]);
            acc[2 * i]     += v0 * f0.x + v1 * f1.x;
            acc[2 * i + 1] += v0 * f0.y + v1 * f1.y;
        }
    }
    if (e < end) {
        int sc = g_srcs[e];
        float v = g_vals[e];
        uint4 t = s4[(size_t)sc * 32 + x];
        const __half2* h = (const __half2*)&t;
#pragma unroll
        for (int i = 0; i < 4; i++) {
            float2 f = __half22float2(h[i]);
            acc[2 * i]     += v * f.x;
            acc[2 * i + 1] += v * f.y;
        }
    }
    uint4 hi, lo;
    {
        float a0 = fmaxf(acc[0], 0.f), a1 = fmaxf(acc[1], 0.f);
        float a2 = fmaxf(acc[2], 0.f), a3 = fmaxf(acc[3], 0.f);
        float a4 = fmaxf(acc[4], 0.f), a5 = fmaxf(acc[5], 0.f);
        float a6 = fmaxf(acc[6], 0.f), a7 = fmaxf(acc[7], 0.f);
        split2(a0, a1, hi.x, lo.x);
        split2(a2, a3, hi.y, lo.y);
        split2(a4, a5, hi.z, lo.z);
        split2(a6, a7, hi.w, lo.w);
    }
    ((uint4*)oh)[(size_t)row * 32 + x] = hi;
    ((uint4*)ol)[(size_t)row * 32 + x] = lo;
}

// ---------------- SPMM (feature-tiled, fp32 input) ----------------
template <int DTOT, int LANES, int ROWS, bool RELU, int OUT>
__global__ void k_spmm(const float* __restrict__ s, float* __restrict__ h,
                       __nv_bfloat16* __restrict__ oh, __nv_bfloat16* __restrict__ ol,
                       int c0) {
    int row = blockIdx.x * ROWS + threadIdx.y;
    if (row >= NN) return;
    const int x = c0 + threadIdx.x;
    const float4* s4 = (const float4*)s;
    int e = g_rowptr[row];
    const int end = g_rowptr[row + 1];
    float4 acc = make_float4(0.f, 0.f, 0.f, 0.f);
    for (; e + 1 < end; e += 2) {
        int sc0 = g_srcs[e], sc1 = g_srcs[e + 1];
        float v0 = g_vals[e], v1 = g_vals[e + 1];
        float4 t0 = s4[(size_t)sc0 * (DTOT / 4) + x];
        float4 t1 = s4[(size_t)sc1 * (DTOT / 4) + x];
        acc.x += v0 * t0.x + v1 * t1.x;
        acc.y += v0 * t0.y + v1 * t1.y;
        acc.z += v0 * t0.z + v1 * t1.z;
        acc.w += v0 * t0.w + v1 * t1.w;
    }
    if (e < end) {
        int sc = g_srcs[e];
        float v = g_vals[e];
        float4 t = s4[(size_t)sc * (DTOT / 4) + x];
        acc.x += v * t.x; acc.y += v * t.y; acc.z += v * t.z; acc.w += v * t.w;
    }
    if (RELU) {
        acc.x = fmaxf(acc.x, 0.f); acc.y = fmaxf(acc.y, 0.f);
        acc.z = fmaxf(acc.z, 0.f); acc.w = fmaxf(acc.w, 0.f);
    }
    if (OUT == 0) {
        ((float4*)h)[(size_t)row * (DTOT / 4) + x] = acc;
    } else {
        uint32_t h0, l0, h1, l1;
        split2(acc.x, acc.y, h0, l0);
        split2(acc.z, acc.w, h1, l1);
        ((uint2*)oh)[(size_t)row * (DTOT / 4) + x] = make_uint2(h0, h1);
        ((uint2*)ol)[(size_t)row * (DTOT / 4) + x] = make_uint2(l0, l1);
    }
}

// ---------------- fused SPMM(D=40) + log_softmax: 1 warp/row, full-lane layout ----------------
__global__ void k_spmm_lsm(const float* __restrict__ s, float* __restrict__ out) {
    int row = blockIdx.x * blockDim.y + threadIdx.y;
    if (row >= NN) return;
    const int l = threadIdx.x;
    float a = 0.f, b = 0.f;
    int e = g_rowptr[row];
    const int end = g_rowptr[row + 1];
    for (; e < end; e++) {
        int sc = g_srcs[e];
        float v = g_vals[e];
        const float* srow = s + (size_t)sc * 40;
        a += v * srow[l];
        if (l < 8) b += v * srow[32 + l];
    }
    float bb = (l < 8) ? b : -1e30f;
    float m = fmaxf(a, bb);
#pragma unroll
    for (int off = 16; off > 0; off >>= 1)
        m = fmaxf(m, __shfl_xor_sync(0xFFFFFFFFu, m, off));
    float sum = expf(a - m) + ((l < 8) ? expf(b - m) : 0.f);
#pragma unroll
    for (int off = 16; off > 0; off >>= 1)
        sum += __shfl_xor_sync(0xFFFFFFFFu, sum, off);
    float ls = m + logf(sum);
    out[(size_t)row * 40 + l] = a - ls;
    if (l < 8) out[(size_t)row * 40 + 32 + l] = b - ls;
}

// ---------------- launch ----------------
extern "C" void kernel_launch(void* const* d_in, const int* in_sizes, int n_in,
                              void* d_out, int out_size) {
    const float* x    = (const float*)d_in[0];
    const int*   esrc = (const int*)d_in[1];
    const int*   edst = (const int*)d_in[2];
    const float* eval = (const float*)d_in[3];
    const float* W0   = (const float*)d_in[4];
    const float* b0   = (const float*)d_in[5];
    const float* W1   = (const float*)d_in[6];
    const float* b1   = (const float*)d_in[7];
    const float* W2   = (const float*)d_in[8];
    const float* b2   = (const float*)d_in[9];
    float* out = (float*)d_out;

    float *ps, *ph;
    __nv_bfloat16 *pah, *pal, *pw0h, *pw0l, *pw1h, *pw1l, *pw2h, *pw2l;
    cudaGetSymbolAddress((void**)&ps, g_s);
    cudaGetSymbolAddress((void**)&ph, g_h);
    cudaGetSymbolAddress((void**)&pah, g_ah);
    cudaGetSymbolAddress((void**)&pal, g_al);
    cudaGetSymbolAddress((void**)&pw0h, g_w0h);
    cudaGetSymbolAddress((void**)&pw0l, g_w0l);
    cudaGetSymbolAddress((void**)&pw1h, g_w1h);
    cudaGetSymbolAddress((void**)&pw1l, g_w1l);
    cudaGetSymbolAddress((void**)&pw2h, g_w2h);
    cudaGetSymbolAddress((void**)&pw2l, g_w2l);
    __half* ps_h = (__half*)ps;   // s0 stored as fp16 in the g_s buffer

    static cudaStream_t s2 = nullptr;
    static cudaEvent_t evFork = nullptr, evCsr = nullptr;
    if (s2 == nullptr) {
        cudaStreamCreateWithFlags(&s2, cudaStreamNonBlocking);
        cudaEventCreateWithFlags(&evFork, cudaEventDisableTiming);
        cudaEventCreateWithFlags(&evCsr, cudaEventDisableTiming);
    }

    // fork: CSR build ONLY on s2, concurrent with cvt_w + GEMM0
    cudaEventRecord(evFork, 0);
    cudaStreamWaitEvent(s2, evFork, 0);
    k_zero_deg<<<(NN + 255) / 256, 256, 0, s2>>>();
    k_hist<<<(NE + 255) / 256, 256, 0, s2>>>(edst);
    k_scan<<<1, 1024, 0, s2>>>();
    k_scatter<<<(NE + 255) / 256, 256, 0, s2>>>(esrc, edst, eval);
    cudaEventRecord(evCsr, s2);

    // main stream: ALL weight conversions + layer-0 GEMM
    k_cvt_w<<<(512 * 256 + 255) / 256, 256>>>(W0, pw0h, pw0l, 512, 256);
    k_cvt_w<<<(256 * 128 + 255) / 256, 256>>>(W1, pw1h, pw1l, 256, 128);
    k_cvt_w_pad<<<(64 * 128 + 255) / 256, 256>>>(W2, pw2h, pw2l, 128, 40, 64);

    const int MB = (NN + 127) / 128;  // 782

    // Layer 0: s0 = x @ W0 + b0 (K=512, N=256), fp32 A fused split, fp16 output
    k_mma_gemm_f32a<<<dim3(2, MB), 256>>>(x, pw0h, pw0l, b0, ps_h, NN, 512, 256);

    // join: SPMM needs the CSR
    cudaStreamWaitEvent(0, evCsr, 0);

    // SPMM0 + relu -> bf16 hi/lo (single pass, fp16 gather: 512 B/edge)
    k_spmm0_h<<<(NN + 7) / 8, dim3(32, 8)>>>(ps_h, pah, pal);

    // Layer 1: s1 = h0 @ W1 + b1 (K=256, N=128) -> ph (fp32)
    k_mma_gemm<<<dim3(1, MB), 256>>>(pah, pal, pw1h, pw1l, b1, ph, NN, 256, 128);

    // SPMM1 + relu -> bf16 hi/lo (2 feature passes of 64 cols) -> pah/pal
    k_spmm<128, 16, 16, true, 1><<<(NN + 15) / 16, dim3(16, 16)>>>(ph, nullptr, pah, pal, 0);
    k_spmm<128, 16, 16, true, 1><<<(NN + 15) / 16, dim3(16, 16)>>>(ph, nullptr, pah, pal, 16);

    // Layer 2: s2 = h1 @ W2 + b2 (K=128, N=40 padded to 64) tensor cores -> ph
    k_mma_gemm64<<<dim3(1, MB), 256>>>(pah, pal, pw2h, pw2l, b2, ph, NN);

    // fused SPMM2 + log_softmax -> out
    k_spmm_lsm<<<(NN + 7) / 8, dim3(32, 8)>>>(ph, out);
}

// round 15
// speedup vs baseline: 1.6300x; 1.0331x over previous
#include <cuda_runtime.h>
#include <cuda_bf16.h>
#include <cuda_fp16.h>
#include <math.h>
#include <stdint.h>

#define NN 100000
#define NE 3200000

// ---------------- scratch ----------------
__device__ float g_s[(size_t)NN * 256];            // used as __half buffers too
__device__ float g_h[(size_t)NN * 256];
__device__ __nv_bfloat16 g_ah[(size_t)NN * 256];   // activation hi
__device__ __nv_bfloat16 g_al[(size_t)NN * 256];   // activation lo
__device__ __nv_bfloat16 g_w0h[512 * 256], g_w0l[512 * 256];   // [N][K] n-major
__device__ __nv_bfloat16 g_w1h[256 * 128], g_w1l[256 * 128];
__device__ __nv_bfloat16 g_w2h[64 * 128],  g_w2l[64 * 128];    // N padded 40->64
__device__ int   g_deg[NN];
__device__ int   g_rowptr[NN + 1];
__device__ int   g_cursor[NN];
__device__ int   g_srcs[NE];
__device__ float g_vals[NE];

// ---------------- helpers ----------------
__device__ __forceinline__ uint32_t smem_u32(const void* p) {
    uint32_t a;
    asm("{ .reg .u64 t; cvta.to.shared.u64 t, %1; cvt.u32.u64 %0, t; }" : "=r"(a) : "l"(p));
    return a;
}

__device__ __forceinline__ void split2(float a, float b, uint32_t& hi, uint32_t& lo) {
    __nv_bfloat16 ah = __float2bfloat16(a), bh = __float2bfloat16(b);
    float ar = a - __bfloat162float(ah);
    float br = b - __bfloat162float(bh);
    __nv_bfloat16 al = __float2bfloat16(ar), bl = __float2bfloat16(br);
    hi = (uint32_t)__bfloat16_as_ushort(ah) | ((uint32_t)__bfloat16_as_ushort(bh) << 16);
    lo = (uint32_t)__bfloat16_as_ushort(al) | ((uint32_t)__bfloat16_as_ushort(bl) << 16);
}

__device__ __forceinline__ void ldm4(uint32_t* r, uint32_t addr) {
    asm volatile("ldmatrix.sync.aligned.m8n8.x4.shared.b16 {%0,%1,%2,%3}, [%4];"
                 : "=r"(r[0]), "=r"(r[1]), "=r"(r[2]), "=r"(r[3]) : "r"(addr));
}

__device__ __forceinline__ void mma16816(float* c, const uint32_t* a, uint32_t b0, uint32_t b1) {
    asm volatile(
        "mma.sync.aligned.m16n8k16.row.col.f32.bf16.bf16.f32 "
        "{%0,%1,%2,%3}, {%4,%5,%6,%7}, {%8,%9}, {%0,%1,%2,%3};"
        : "+f"(c[0]), "+f"(c[1]), "+f"(c[2]), "+f"(c[3])
        : "r"(a[0]), "r"(a[1]), "r"(a[2]), "r"(a[3]), "r"(b0), "r"(b1));
}

// ---------------- CSR build ----------------
__global__ void k_zero_deg() {
    int i = blockIdx.x * blockDim.x + threadIdx.x;
    if (i < NN) g_deg[i] = 0;
}
__global__ void k_hist(const int* __restrict__ dst) {
    int e = blockIdx.x * blockDim.x + threadIdx.x;
    if (e < NE) atomicAdd(&g_deg[dst[e]], 1);
}
__global__ void k_scan() {
    __shared__ int ssum[1024];
    const int t = threadIdx.x;
    const int CH = (NN + 1023) / 1024;
    int s0 = t * CH, s1 = s0 + CH; if (s1 > NN) s1 = NN;
    int sum = 0;
    for (int i = s0; i < s1; i++) sum += g_deg[i];
    ssum[t] = sum;
    __syncthreads();
    for (int off = 1; off < 1024; off <<= 1) {
        int v = (t >= off) ? ssum[t - off] : 0;
        __syncthreads();
        ssum[t] += v;
        __syncthreads();
    }
    int run = (t == 0) ? 0 : ssum[t - 1];
    for (int i = s0; i < s1; i++) { g_rowptr[i] = run; g_cursor[i] = run; run += g_deg[i]; }
    if (t == 1023) g_rowptr[NN] = ssum[1023];
}
__global__ void k_scatter(const int* __restrict__ src, const int* __restrict__ dst,
                          const float* __restrict__ val) {
    int e = blockIdx.x * blockDim.x + threadIdx.x;
    if (e >= NE) return;
    int d = dst[e];
    int p = atomicAdd(&g_cursor[d], 1);
    g_srcs[p] = src[e];
    g_vals[p] = val[e];
}

// ---------------- weight converters ----------------
__global__ void k_cvt_w(const float* __restrict__ W, __nv_bfloat16* __restrict__ wh,
                        __nv_bfloat16* __restrict__ wl, int K, int N) {
    int idx = blockIdx.x * blockDim.x + threadIdx.x;
    if (idx >= N * K) return;
    int n = idx / K, k = idx % K;
    float v = W[(size_t)k * N + n];
    __nv_bfloat16 h = __float2bfloat16(v);
    float r = v - __bfloat162float(h);
    wh[idx] = h;
    wl[idx] = __float2bfloat16(r);
}
__global__ void k_cvt_w_pad(const float* __restrict__ W, __nv_bfloat16* __restrict__ wh,
                            __nv_bfloat16* __restrict__ wl, int K, int N, int Npad) {
    int idx = blockIdx.x * blockDim.x + threadIdx.x;
    if (idx >= Npad * K) return;
    int n = idx / K, k = idx % K;
    float v = (n < N) ? W[(size_t)k * N + n] : 0.f;
    __nv_bfloat16 h = __float2bfloat16(v);
    float r = v - __bfloat162float(h);
    wh[idx] = h;
    wl[idx] = __float2bfloat16(r);
}

// ---------------- tensor-core GEMM (fp32 A, fused split), fp16 output ----------------
__global__ void __launch_bounds__(256, 2)
k_mma_gemm_f32a(const float* __restrict__ A,
                const __nv_bfloat16* __restrict__ Bh, const __nv_bfloat16* __restrict__ Bl,
                const float* __restrict__ bias, __half* __restrict__ C,
                int M, int K, int N) {
    __shared__ __nv_bfloat16 sAh[128][40];
    __shared__ __nv_bfloat16 sAl[128][40];
    __shared__ __nv_bfloat16 sBh[128][40];
    __shared__ __nv_bfloat16 sBl[128][40];

    const int tid = threadIdx.x;
    const int wid = tid >> 5, lane = tid & 31;
    const int m0 = blockIdx.y * 128;
    const int n0 = blockIdx.x * 128;
    const int wm = wid >> 2;
    const int wn = wid & 3;

    int lrow[2], lq[2];
#pragma unroll
    for (int it = 0; it < 2; it++) {
        int idx = it * 256 + tid;
        lrow[it] = idx >> 2;
        lq[it] = idx & 3;
    }

    float acc[4][4][4];
#pragma unroll
    for (int a = 0; a < 4; a++)
#pragma unroll
        for (int b = 0; b < 4; b++)
#pragma unroll
            for (int c = 0; c < 4; c++) acc[a][b][c] = 0.f;

    float4 fA[2][2];
    uint4 pBh[2], pBl[2];

    auto fetch = [&](int ch) {
        const int k0 = ch * 32;
#pragma unroll
        for (int it = 0; it < 2; it++) {
            int row = lrow[it], q = lq[it];
            if (m0 + row < M) {
                const float* p = &A[(size_t)(m0 + row) * K + k0 + q * 8];
                fA[it][0] = *(const float4*)p;
                fA[it][1] = *(const float4*)(p + 4);
            } else {
                fA[it][0] = make_float4(0.f, 0.f, 0.f, 0.f);
                fA[it][1] = make_float4(0.f, 0.f, 0.f, 0.f);
            }
            size_t offb = (size_t)(n0 + row) * K + k0 + q * 8;
            pBh[it] = *(const uint4*)&Bh[offb];
            pBl[it] = *(const uint4*)&Bl[offb];
        }
    };
    auto commit = [&]() {
#pragma unroll
        for (int it = 0; it < 2; it++) {
            int row = lrow[it], q = lq[it];
            uint4 vh, vl;
            split2(fA[it][0].x, fA[it][0].y, vh.x, vl.x);
            split2(fA[it][0].z, fA[it][0].w, vh.y, vl.y);
            split2(fA[it][1].x, fA[it][1].y, vh.z, vl.z);
            split2(fA[it][1].z, fA[it][1].w, vh.w, vl.w);
            *(uint4*)&sAh[row][q * 8] = vh;
            *(uint4*)&sAl[row][q * 8] = vl;
            *(uint4*)&sBh[row][q * 8] = pBh[it];
            *(uint4*)&sBl[row][q * 8] = pBl[it];
        }
    };

    const int nch = K / 32;
    fetch(0);
    commit();

    for (int ch = 0; ch < nch; ch++) {
        __syncthreads();
        if (ch + 1 < nch) fetch(ch + 1);

#pragma unroll
        for (int kk = 0; kk < 32; kk += 16) {
            const int r = lane & 15;
            const int koff = (lane >> 4) << 3;
            uint32_t bhf[2][4], blf[2][4];
#pragma unroll
            for (int nt = 0; nt < 2; nt++) {
                ldm4(bhf[nt], smem_u32(&sBh[wn * 32 + nt * 16 + r][kk + koff]));
                ldm4(blf[nt], smem_u32(&sBl[wn * 32 + nt * 16 + r][kk + koff]));
            }
#pragma unroll
            for (int mt = 0; mt < 4; mt++) {
                uint32_t af[4];
                ldm4(af, smem_u32(&sAh[wm * 64 + mt * 16 + r][kk + koff]));
#pragma unroll
                for (int j = 0; j < 4; j++) {
                    mma16816(acc[mt][j], af, bhf[j >> 1][j & 1], bhf[j >> 1][2 + (j & 1)]);
                    mma16816(acc[mt][j], af, blf[j >> 1][j & 1], blf[j >> 1][2 + (j & 1)]);
                }
            }
#pragma unroll
            for (int mt = 0; mt < 4; mt++) {
                uint32_t af[4];
                ldm4(af, smem_u32(&sAl[wm * 64 + mt * 16 + r][kk + koff]));
#pragma unroll
                for (int j = 0; j < 4; j++)
                    mma16816(acc[mt][j], af, bhf[j >> 1][j & 1], bhf[j >> 1][2 + (j & 1)]);
            }
        }
        __syncthreads();
        if (ch + 1 < nch) commit();
    }

    const int rbase = m0 + wm * 64 + (lane >> 2);
    const int cbase = n0 + wn * 32 + (lane & 3) * 2;
#pragma unroll
    for (int mt = 0; mt < 4; mt++) {
        int m = rbase + mt * 16;
#pragma unroll
        for (int j = 0; j < 4; j++) {
            int c = cbase + j * 8;
            float bv0 = bias[c], bv1 = bias[c + 1];
            if (m < M)
                *(__half2*)&C[(size_t)m * N + c] =
                    __floats2half2_rn(acc[mt][j][0] + bv0, acc[mt][j][1] + bv1);
            if (m + 8 < M)
                *(__half2*)&C[(size_t)(m + 8) * N + c] =
                    __floats2half2_rn(acc[mt][j][2] + bv0, acc[mt][j][3] + bv1);
        }
    }
}

// ---------------- tensor-core GEMM (bf16 hi/lo A), fp16 output ----------------
__global__ void __launch_bounds__(256, 2)
k_mma_gemm(const __nv_bfloat16* __restrict__ Ah, const __nv_bfloat16* __restrict__ Al,
           const __nv_bfloat16* __restrict__ Bh, const __nv_bfloat16* __restrict__ Bl,
           const float* __restrict__ bias, __half* __restrict__ C,
           int M, int K, int N) {
    __shared__ __nv_bfloat16 sAh[128][40];
    __shared__ __nv_bfloat16 sAl[128][40];
    __shared__ __nv_bfloat16 sBh[128][40];
    __shared__ __nv_bfloat16 sBl[128][40];

    const int tid = threadIdx.x;
    const int wid = tid >> 5, lane = tid & 31;
    const int m0 = blockIdx.y * 128;
    const int n0 = blockIdx.x * 128;
    const int wm = wid >> 2;
    const int wn = wid & 3;

    int lrow[2], lq[2];
#pragma unroll
    for (int it = 0; it < 2; it++) {
        int idx = it * 256 + tid;
        lrow[it] = idx >> 2;
        lq[it] = idx & 3;
    }

    float acc[4][4][4];
#pragma unroll
    for (int a = 0; a < 4; a++)
#pragma unroll
        for (int b = 0; b < 4; b++)
#pragma unroll
            for (int c = 0; c < 4; c++) acc[a][b][c] = 0.f;

    uint4 pAh[2], pAl[2], pBh[2], pBl[2];

    auto fetch = [&](int ch) {
        const int k0 = ch * 32;
#pragma unroll
        for (int it = 0; it < 2; it++) {
            int row = lrow[it], q = lq[it];
            if (m0 + row < M) {
                size_t off = (size_t)(m0 + row) * K + k0 + q * 8;
                pAh[it] = *(const uint4*)&Ah[off];
                pAl[it] = *(const uint4*)&Al[off];
            } else {
                pAh[it] = make_uint4(0, 0, 0, 0);
                pAl[it] = make_uint4(0, 0, 0, 0);
            }
            size_t offb = (size_t)(n0 + row) * K + k0 + q * 8;
            pBh[it] = *(const uint4*)&Bh[offb];
            pBl[it] = *(const uint4*)&Bl[offb];
        }
    };
    auto commit = [&]() {
#pragma unroll
        for (int it = 0; it < 2; it++) {
            int row = lrow[it], q = lq[it];
            *(uint4*)&sAh[row][q * 8] = pAh[it];
            *(uint4*)&sAl[row][q * 8] = pAl[it];
            *(uint4*)&sBh[row][q * 8] = pBh[it];
            *(uint4*)&sBl[row][q * 8] = pBl[it];
        }
    };

    const int nch = K / 32;
    fetch(0);
    commit();

    for (int ch = 0; ch < nch; ch++) {
        __syncthreads();
        if (ch + 1 < nch) fetch(ch + 1);

#pragma unroll
        for (int kk = 0; kk < 32; kk += 16) {
            const int r = lane & 15;
            const int koff = (lane >> 4) << 3;
            uint32_t bhf[2][4], blf[2][4];
#pragma unroll
            for (int nt = 0; nt < 2; nt++) {
                ldm4(bhf[nt], smem_u32(&sBh[wn * 32 + nt * 16 + r][kk + koff]));
                ldm4(blf[nt], smem_u32(&sBl[wn * 32 + nt * 16 + r][kk + koff]));
            }
#pragma unroll
            for (int mt = 0; mt < 4; mt++) {
                uint32_t af[4];
                ldm4(af, smem_u32(&sAh[wm * 64 + mt * 16 + r][kk + koff]));
#pragma unroll
                for (int j = 0; j < 4; j++) {
                    mma16816(acc[mt][j], af, bhf[j >> 1][j & 1], bhf[j >> 1][2 + (j & 1)]);
                    mma16816(acc[mt][j], af, blf[j >> 1][j & 1], blf[j >> 1][2 + (j & 1)]);
                }
            }
#pragma unroll
            for (int mt = 0; mt < 4; mt++) {
                uint32_t af[4];
                ldm4(af, smem_u32(&sAl[wm * 64 + mt * 16 + r][kk + koff]));
#pragma unroll
                for (int j = 0; j < 4; j++)
                    mma16816(acc[mt][j], af, bhf[j >> 1][j & 1], bhf[j >> 1][2 + (j & 1)]);
            }
        }
        __syncthreads();
        if (ch + 1 < nch) commit();
    }

    const int rbase = m0 + wm * 64 + (lane >> 2);
    const int cbase = n0 + wn * 32 + (lane & 3) * 2;
#pragma unroll
    for (int mt = 0; mt < 4; mt++) {
        int m = rbase + mt * 16;
#pragma unroll
        for (int j = 0; j < 4; j++) {
            int c = cbase + j * 8;
            float bv0 = bias[c], bv1 = bias[c + 1];
            if (m < M)
                *(__half2*)&C[(size_t)m * N + c] =
                    __floats2half2_rn(acc[mt][j][0] + bv0, acc[mt][j][1] + bv1);
            if (m + 8 < M)
                *(__half2*)&C[(size_t)(m + 8) * N + c] =
                    __floats2half2_rn(acc[mt][j][2] + bv0, acc[mt][j][3] + bv1);
        }
    }
}

// ---------------- tensor-core GEMM, layer 2: K=128, Npad=64, Nout=40, fp16 out ----------------
__global__ void __launch_bounds__(256, 2)
k_mma_gemm64(const __nv_bfloat16* __restrict__ Ah, const __nv_bfloat16* __restrict__ Al,
             const __nv_bfloat16* __restrict__ Bh, const __nv_bfloat16* __restrict__ Bl,
             const float* __restrict__ bias, __half* __restrict__ C, int M) {
    const int K = 128, NOUT = 40;
    __shared__ __nv_bfloat16 sAh[128][40];
    __shared__ __nv_bfloat16 sAl[128][40];
    __shared__ __nv_bfloat16 sBh[64][40];
    __shared__ __nv_bfloat16 sBl[64][40];

    const int tid = threadIdx.x;
    const int wid = tid >> 5, lane = tid & 31;
    const int m0 = blockIdx.y * 128;
    const int wm = wid >> 1;
    const int wn = wid & 1;

    int lrowA[2], lqA[2];
#pragma unroll
    for (int it = 0; it < 2; it++) {
        int idx = it * 256 + tid;
        lrowA[it] = idx >> 2;
        lqA[it] = idx & 3;
    }
    const int lrowB = tid >> 2, lqB = tid & 3;

    float acc[2][4][4];
#pragma unroll
    for (int a = 0; a < 2; a++)
#pragma unroll
        for (int b = 0; b < 4; b++)
#pragma unroll
            for (int c = 0; c < 4; c++) acc[a][b][c] = 0.f;

    uint4 pAh[2], pAl[2], pBh1, pBl1;

    auto fetch = [&](int ch) {
        const int k0 = ch * 32;
#pragma unroll
        for (int it = 0; it < 2; it++) {
            int row = lrowA[it], q = lqA[it];
            if (m0 + row < M) {
                size_t off = (size_t)(m0 + row) * K + k0 + q * 8;
                pAh[it] = *(const uint4*)&Ah[off];
                pAl[it] = *(const uint4*)&Al[off];
            } else {
                pAh[it] = make_uint4(0, 0, 0, 0);
                pAl[it] = make_uint4(0, 0, 0, 0);
            }
        }
        size_t offb = (size_t)lrowB * K + k0 + lqB * 8;
        pBh1 = *(const uint4*)&Bh[offb];
        pBl1 = *(const uint4*)&Bl[offb];
    };
    auto commit = [&]() {
#pragma unroll
        for (int it = 0; it < 2; it++) {
            int row = lrowA[it], q = lqA[it];
            *(uint4*)&sAh[row][q * 8] = pAh[it];
            *(uint4*)&sAl[row][q * 8] = pAl[it];
        }
        *(uint4*)&sBh[lrowB][lqB * 8] = pBh1;
        *(uint4*)&sBl[lrowB][lqB * 8] = pBl1;
    };

    const int nch = K / 32;
    fetch(0);
    commit();

    for (int ch = 0; ch < nch; ch++) {
        __syncthreads();
        if (ch + 1 < nch) fetch(ch + 1);

#pragma unroll
        for (int kk = 0; kk < 32; kk += 16) {
            const int r = lane & 15;
            const int koff = (lane >> 4) << 3;
            uint32_t bhf[2][4], blf[2][4];
#pragma unroll
            for (int nt = 0; nt < 2; nt++) {
                ldm4(bhf[nt], smem_u32(&sBh[wn * 32 + nt * 16 + r][kk + koff]));
                ldm4(blf[nt], smem_u32(&sBl[wn * 32 + nt * 16 + r][kk + koff]));
            }
#pragma unroll
            for (int mt = 0; mt < 2; mt++) {
                uint32_t af[4];
                ldm4(af, smem_u32(&sAh[wm * 32 + mt * 16 + r][kk + koff]));
#pragma unroll
                for (int j = 0; j < 4; j++) {
                    mma16816(acc[mt][j], af, bhf[j >> 1][j & 1], bhf[j >> 1][2 + (j & 1)]);
                    mma16816(acc[mt][j], af, blf[j >> 1][j & 1], blf[j >> 1][2 + (j & 1)]);
                }
            }
#pragma unroll
            for (int mt = 0; mt < 2; mt++) {
                uint32_t af[4];
                ldm4(af, smem_u32(&sAl[wm * 32 + mt * 16 + r][kk + koff]));
#pragma unroll
                for (int j = 0; j < 4; j++)
                    mma16816(acc[mt][j], af, bhf[j >> 1][j & 1], bhf[j >> 1][2 + (j & 1)]);
            }
        }
        __syncthreads();
        if (ch + 1 < nch) commit();
    }

    const int rbase = m0 + wm * 32 + (lane >> 2);
    const int cbase = wn * 32 + (lane & 3) * 2;
#pragma unroll
    for (int mt = 0; mt < 2; mt++) {
        int m = rbase + mt * 16;
#pragma unroll
        for (int j = 0; j < 4; j++) {
            int c = cbase + j * 8;
            if (c >= NOUT) continue;
            float bv0 = bias[c], bv1 = bias[c + 1];
            if (m < M)
                *(__half2*)&C[(size_t)m * NOUT + c] =
                    __floats2half2_rn(acc[mt][j][0] + bv0, acc[mt][j][1] + bv1);
            if (m + 8 < M)
                *(__half2*)&C[(size_t)(m + 8) * NOUT + c] =
                    __floats2half2_rn(acc[mt][j][2] + bv0, acc[mt][j][3] + bv1);
        }
    }
}

// ---------------- SPMM fp16 gather, single pass: D halves, DL = D/8 lanes ----------------
// each lane gathers one uint4 (8 halves); output bf16 hi/lo.
template <int D, int DL, int ROWS>
__global__ void k_spmm_h(const __half* __restrict__ s,
                         __nv_bfloat16* __restrict__ oh, __nv_bfloat16* __restrict__ ol) {
    int row = blockIdx.x * ROWS + threadIdx.y;
    if (row >= NN) return;
    const int x = threadIdx.x;                       // 0..DL-1
    const uint4* s4 = (const uint4*)s;               // DL uint4 per row
    float acc[8];
#pragma unroll
    for (int i = 0; i < 8; i++) acc[i] = 0.f;
    int e = g_rowptr[row];
    const int end = g_rowptr[row + 1];
    for (; e + 1 < end; e += 2) {
        int sc0 = g_srcs[e], sc1 = g_srcs[e + 1];
        float v0 = g_vals[e], v1 = g_vals[e + 1];
        uint4 t0 = s4[(size_t)sc0 * DL + x];
        uint4 t1 = s4[(size_t)sc1 * DL + x];
        const __half2* h0 = (const __half2*)&t0;
        const __half2* h1 = (const __half2*)&t1;
#pragma unroll
        for (int i = 0; i < 4; i++) {
            float2 f0 = __half22float2(h0[i]);
            float2 f1 = __half22float2(h1[i]);
            acc[2 * i]     += v0 * f0.x + v1 * f1.x;
            acc[2 * i + 1] += v0 * f0.y + v1 * f1.y;
        }
    }
    if (e < end) {
        int sc = g_srcs[e];
        float v = g_vals[e];
        uint4 t = s4[(size_t)sc * DL + x];
        const __half2* h = (const __half2*)&t;
#pragma unroll
        for (int i = 0; i < 4; i++) {
            float2 f = __half22float2(h[i]);
            acc[2 * i]     += v * f.x;
            acc[2 * i + 1] += v * f.y;
        }
    }
    uint4 hi, lo;
    {
        float a0 = fmaxf(acc[0], 0.f), a1 = fmaxf(acc[1], 0.f);
        float a2 = fmaxf(acc[2], 0.f), a3 = fmaxf(acc[3], 0.f);
        float a4 = fmaxf(acc[4], 0.f), a5 = fmaxf(acc[5], 0.f);
        float a6 = fmaxf(acc[6], 0.f), a7 = fmaxf(acc[7], 0.f);
        split2(a0, a1, hi.x, lo.x);
        split2(a2, a3, hi.y, lo.y);
        split2(a4, a5, hi.z, lo.z);
        split2(a6, a7, hi.w, lo.w);
    }
    ((uint4*)oh)[(size_t)row * DL + x] = hi;
    ((uint4*)ol)[(size_t)row * DL + x] = lo;
}

// ---------------- fused SPMM(D=40, fp16 in) + log_softmax: 1 warp/row ----------------
__global__ void k_spmm_lsm(const __half* __restrict__ s, float* __restrict__ out) {
    int row = blockIdx.x * blockDim.y + threadIdx.y;
    if (row >= NN) return;
    const int l = threadIdx.x;
    float a = 0.f, b = 0.f;
    int e = g_rowptr[row];
    const int end = g_rowptr[row + 1];
    for (; e < end; e++) {
        int sc = g_srcs[e];
        float v = g_vals[e];
        const __half* srow = s + (size_t)sc * 40;
        a += v * __half2float(srow[l]);
        if (l < 8) b += v * __half2float(srow[32 + l]);
    }
    float bb = (l < 8) ? b : -1e30f;
    float m = fmaxf(a, bb);
#pragma unroll
    for (int off = 16; off > 0; off >>= 1)
        m = fmaxf(m, __shfl_xor_sync(0xFFFFFFFFu, m, off));
    float sum = expf(a - m) + ((l < 8) ? expf(b - m) : 0.f);
#pragma unroll
    for (int off = 16; off > 0; off >>= 1)
        sum += __shfl_xor_sync(0xFFFFFFFFu, sum, off);
    float ls = m + logf(sum);
    out[(size_t)row * 40 + l] = a - ls;
    if (l < 8) out[(size_t)row * 40 + 32 + l] = b - ls;
}

// ---------------- launch ----------------
extern "C" void kernel_launch(void* const* d_in, const int* in_sizes, int n_in,
                              void* d_out, int out_size) {
    const float* x    = (const float*)d_in[0];
    const int*   esrc = (const int*)d_in[1];
    const int*   edst = (const int*)d_in[2];
    const float* eval = (const float*)d_in[3];
    const float* W0   = (const float*)d_in[4];
    const float* b0   = (const float*)d_in[5];
    const float* W1   = (const float*)d_in[6];
    const float* b1   = (const float*)d_in[7];
    const float* W2   = (const float*)d_in[8];
    const float* b2   = (const float*)d_in[9];
    float* out = (float*)d_out;

    float *ps, *ph;
    __nv_bfloat16 *pah, *pal, *pw0h, *pw0l, *pw1h, *pw1l, *pw2h, *pw2l;
    cudaGetSymbolAddress((void**)&ps, g_s);
    cudaGetSymbolAddress((void**)&ph, g_h);
    cudaGetSymbolAddress((void**)&pah, g_ah);
    cudaGetSymbolAddress((void**)&pal, g_al);
    cudaGetSymbolAddress((void**)&pw0h, g_w0h);
    cudaGetSymbolAddress((void**)&pw0l, g_w0l);
    cudaGetSymbolAddress((void**)&pw1h, g_w1h);
    cudaGetSymbolAddress((void**)&pw1l, g_w1l);
    cudaGetSymbolAddress((void**)&pw2h, g_w2h);
    cudaGetSymbolAddress((void**)&pw2l, g_w2l);
    __half* ps_h = (__half*)ps;   // fp16 s0 / s2
    __half* ph_h = (__half*)ph;   // fp16 s1

    static cudaStream_t s2 = nullptr;
    static cudaEvent_t evFork = nullptr, evCsr = nullptr;
    if (s2 == nullptr) {
        cudaStreamCreateWithFlags(&s2, cudaStreamNonBlocking);
        cudaEventCreateWithFlags(&evFork, cudaEventDisableTiming);
        cudaEventCreateWithFlags(&evCsr, cudaEventDisableTiming);
    }

    // fork: CSR build ONLY on s2, concurrent with cvt_w + GEMM0
    cudaEventRecord(evFork, 0);
    cudaStreamWaitEvent(s2, evFork, 0);
    k_zero_deg<<<(NN + 255) / 256, 256, 0, s2>>>();
    k_hist<<<(NE + 255) / 256, 256, 0, s2>>>(edst);
    k_scan<<<1, 1024, 0, s2>>>();
    k_scatter<<<(NE + 255) / 256, 256, 0, s2>>>(esrc, edst, eval);
    cudaEventRecord(evCsr, s2);

    // main stream: ALL weight conversions + layer-0 GEMM
    k_cvt_w<<<(512 * 256 + 255) / 256, 256>>>(W0, pw0h, pw0l, 512, 256);
    k_cvt_w<<<(256 * 128 + 255) / 256, 256>>>(W1, pw1h, pw1l, 256, 128);
    k_cvt_w_pad<<<(64 * 128 + 255) / 256, 256>>>(W2, pw2h, pw2l, 128, 40, 64);

    const int MB = (NN + 127) / 128;  // 782

    // Layer 0: s0 = x @ W0 + b0 (K=512, N=256), fp16 output -> ps_h
    k_mma_gemm_f32a<<<dim3(2, MB), 256>>>(x, pw0h, pw0l, b0, ps_h, NN, 512, 256);

    // join: SPMM needs the CSR
    cudaStreamWaitEvent(0, evCsr, 0);

    // SPMM0 + relu -> bf16 hi/lo (single pass, fp16 gather 512 B/edge)
    k_spmm_h<256, 32, 8><<<(NN + 7) / 8, dim3(32, 8)>>>(ps_h, pah, pal);

    // Layer 1: s1 = h0 @ W1 + b1 (K=256, N=128), fp16 output -> ph_h
    k_mma_gemm<<<dim3(1, MB), 256>>>(pah, pal, pw1h, pw1l, b1, ph_h, NN, 256, 128);

    // SPMM1 + relu -> bf16 hi/lo (single pass, fp16 gather 256 B/edge)
    k_spmm_h<128, 16, 16><<<(NN + 15) / 16, dim3(16, 16)>>>(ph_h, pah, pal);

    // Layer 2: s2 = h1 @ W2 + b2 (K=128, N=40 padded to 64), fp16 output -> ps_h
    k_mma_gemm64<<<dim3(1, MB), 256>>>(pah, pal, pw2h, pw2l, b2, ps_h, NN);

    // fused SPMM2 + log_softmax (fp16 gather) -> out
    k_spmm_lsm<<<(NN + 7) / 8, dim3(32, 8)>>>(ps_h, out);
}

// round 16
// speedup vs baseline: 2.2610x; 1.3871x over previous
#include <cuda_runtime.h>
#include <cuda_fp16.h>
#include <math.h>
#include <stdint.h>

#define NN 100000
#define NE 3200000

// ---------------- scratch ----------------
__device__ float g_s[(size_t)NN * 256];            // __half s0 / s2 buffer
__device__ float g_h[(size_t)NN * 256];            // __half s1 buffer
__device__ __half g_a[(size_t)NN * 256];           // fp16 activations (h0 / h1)
__device__ __half g_w0[256 * 512];                 // [N][K] n-major fp16
__device__ __half g_w1[128 * 256];
__device__ __half g_w2[64 * 128];                  // N padded 40->64
__device__ int   g_deg[NN];
__device__ int   g_rowptr[NN + 1];
__device__ int   g_cursor[NN];
__device__ int   g_srcs[NE];
__device__ float g_vals[NE];

// ---------------- helpers ----------------
__device__ __forceinline__ uint32_t smem_u32(const void* p) {
    uint32_t a;
    asm("{ .reg .u64 t; cvta.to.shared.u64 t, %1; cvt.u32.u64 %0, t; }" : "=r"(a) : "l"(p));
    return a;
}

__device__ __forceinline__ uint32_t h2u(float a, float b) {
    __half2 h = __floats2half2_rn(a, b);
    return *(uint32_t*)&h;
}

__device__ __forceinline__ void ldm4(uint32_t* r, uint32_t addr) {
    asm volatile("ldmatrix.sync.aligned.m8n8.x4.shared.b16 {%0,%1,%2,%3}, [%4];"
                 : "=r"(r[0]), "=r"(r[1]), "=r"(r[2]), "=r"(r[3]) : "r"(addr));
}

__device__ __forceinline__ void mma_f16(float* c, const uint32_t* a, uint32_t b0, uint32_t b1) {
    asm volatile(
        "mma.sync.aligned.m16n8k16.row.col.f32.f16.f16.f32 "
        "{%0,%1,%2,%3}, {%4,%5,%6,%7}, {%8,%9}, {%0,%1,%2,%3};"
        : "+f"(c[0]), "+f"(c[1]), "+f"(c[2]), "+f"(c[3])
        : "r"(a[0]), "r"(a[1]), "r"(a[2]), "r"(a[3]), "r"(b0), "r"(b1));
}

// ---------------- CSR build ----------------
__global__ void k_zero_deg() {
    int i = blockIdx.x * blockDim.x + threadIdx.x;
    if (i < NN) g_deg[i] = 0;
}
__global__ void k_hist(const int* __restrict__ dst) {
    int e = blockIdx.x * blockDim.x + threadIdx.x;
    if (e < NE) atomicAdd(&g_deg[dst[e]], 1);
}
__global__ void k_scan() {
    __shared__ int ssum[1024];
    const int t = threadIdx.x;
    const int CH = (NN + 1023) / 1024;
    int s0 = t * CH, s1 = s0 + CH; if (s1 > NN) s1 = NN;
    int sum = 0;
    for (int i = s0; i < s1; i++) sum += g_deg[i];
    ssum[t] = sum;
    __syncthreads();
    for (int off = 1; off < 1024; off <<= 1) {
        int v = (t >= off) ? ssum[t - off] : 0;
        __syncthreads();
        ssum[t] += v;
        __syncthreads();
    }
    int run = (t == 0) ? 0 : ssum[t - 1];
    for (int i = s0; i < s1; i++) { g_rowptr[i] = run; g_cursor[i] = run; run += g_deg[i]; }
    if (t == 1023) g_rowptr[NN] = ssum[1023];
}
__global__ void k_scatter(const int* __restrict__ src, const int* __restrict__ dst,
                          const float* __restrict__ val) {
    int e = blockIdx.x * blockDim.x + threadIdx.x;
    if (e >= NE) return;
    int d = dst[e];
    int p = atomicAdd(&g_cursor[d], 1);
    g_srcs[p] = src[e];
    g_vals[p] = val[e];
}

// ---------------- weight converter: W [K][N] fp32 -> [Npad][K] fp16 n-major ----------------
__global__ void k_cvt_w_h(const float* __restrict__ W, __half* __restrict__ wh,
                          int K, int N, int Npad) {
    int idx = blockIdx.x * blockDim.x + threadIdx.x;
    if (idx >= Npad * K) return;
    int n = idx / K, k = idx % K;
    float v = (n < N) ? W[(size_t)k * N + n] : 0.f;
    wh[idx] = __float2half(v);
}

// ---------------- fp16 GEMM (fp32 A converted in-kernel): C = A @ B^T + bias ----------------
// BM=128, BN=128, BK=32. 256 threads = 8 warps (2m x 4n), warp tile 64x32.
__global__ void __launch_bounds__(256, 2)
k_gemm_f32a(const float* __restrict__ A, const __half* __restrict__ B,
            const float* __restrict__ bias, __half* __restrict__ C,
            int M, int K, int N) {
    __shared__ __half sA[128][40];
    __shared__ __half sB[128][40];

    const int tid = threadIdx.x;
    const int wid = tid >> 5, lane = tid & 31;
    const int m0 = blockIdx.y * 128;
    const int n0 = blockIdx.x * 128;
    const int wm = wid >> 2;
    const int wn = wid & 3;

    int lrow[2], lq[2];
#pragma unroll
    for (int it = 0; it < 2; it++) {
        int idx = it * 256 + tid;
        lrow[it] = idx >> 2;
        lq[it] = idx & 3;
    }

    float acc[4][4][4];
#pragma unroll
    for (int a = 0; a < 4; a++)
#pragma unroll
        for (int b = 0; b < 4; b++)
#pragma unroll
            for (int c = 0; c < 4; c++) acc[a][b][c] = 0.f;

    float4 fA[2][2];
    uint4 pB[2];

    auto fetch = [&](int ch) {
        const int k0 = ch * 32;
#pragma unroll
        for (int it = 0; it < 2; it++) {
            int row = lrow[it], q = lq[it];
            if (m0 + row < M) {
                const float* p = &A[(size_t)(m0 + row) * K + k0 + q * 8];
                fA[it][0] = *(const float4*)p;
                fA[it][1] = *(const float4*)(p + 4);
            } else {
                fA[it][0] = make_float4(0.f, 0.f, 0.f, 0.f);
                fA[it][1] = make_float4(0.f, 0.f, 0.f, 0.f);
            }
            size_t offb = (size_t)(n0 + row) * K + k0 + q * 8;
            pB[it] = *(const uint4*)&B[offb];
        }
    };
    auto commit = [&]() {
#pragma unroll
        for (int it = 0; it < 2; it++) {
            int row = lrow[it], q = lq[it];
            uint4 v;
            v.x = h2u(fA[it][0].x, fA[it][0].y);
            v.y = h2u(fA[it][0].z, fA[it][0].w);
            v.z = h2u(fA[it][1].x, fA[it][1].y);
            v.w = h2u(fA[it][1].z, fA[it][1].w);
            *(uint4*)&sA[row][q * 8] = v;
            *(uint4*)&sB[row][q * 8] = pB[it];
        }
    };

    const int nch = K / 32;
    fetch(0);
    commit();

    for (int ch = 0; ch < nch; ch++) {
        __syncthreads();
        if (ch + 1 < nch) fetch(ch + 1);

#pragma unroll
        for (int kk = 0; kk < 32; kk += 16) {
            const int r = lane & 15;
            const int koff = (lane >> 4) << 3;
            uint32_t bf[2][4];
#pragma unroll
            for (int nt = 0; nt < 2; nt++)
                ldm4(bf[nt], smem_u32(&sB[wn * 32 + nt * 16 + r][kk + koff]));
#pragma unroll
            for (int mt = 0; mt < 4; mt++) {
                uint32_t af[4];
                ldm4(af, smem_u32(&sA[wm * 64 + mt * 16 + r][kk + koff]));
#pragma unroll
                for (int j = 0; j < 4; j++)
                    mma_f16(acc[mt][j], af, bf[j >> 1][j & 1], bf[j >> 1][2 + (j & 1)]);
            }
        }
        __syncthreads();
        if (ch + 1 < nch) commit();
    }

    const int rbase = m0 + wm * 64 + (lane >> 2);
    const int cbase = n0 + wn * 32 + (lane & 3) * 2;
#pragma unroll
    for (int mt = 0; mt < 4; mt++) {
        int m = rbase + mt * 16;
#pragma unroll
        for (int j = 0; j < 4; j++) {
            int c = cbase + j * 8;
            float bv0 = bias[c], bv1 = bias[c + 1];
            if (m < M)
                *(__half2*)&C[(size_t)m * N + c] =
                    __floats2half2_rn(acc[mt][j][0] + bv0, acc[mt][j][1] + bv1);
            if (m + 8 < M)
                *(__half2*)&C[(size_t)(m + 8) * N + c] =
                    __floats2half2_rn(acc[mt][j][2] + bv0, acc[mt][j][3] + bv1);
        }
    }
}

// ---------------- fp16 GEMM (fp16 A): C = A @ B^T + bias ----------------
__global__ void __launch_bounds__(256, 2)
k_gemm_h(const __half* __restrict__ A, const __half* __restrict__ B,
         const float* __restrict__ bias, __half* __restrict__ C,
         int M, int K, int N) {
    __shared__ __half sA[128][40];
    __shared__ __half sB[128][40];

    const int tid = threadIdx.x;
    const int wid = tid >> 5, lane = tid & 31;
    const int m0 = blockIdx.y * 128;
    const int n0 = blockIdx.x * 128;
    const int wm = wid >> 2;
    const int wn = wid & 3;

    int lrow[2], lq[2];
#pragma unroll
    for (int it = 0; it < 2; it++) {
        int idx = it * 256 + tid;
        lrow[it] = idx >> 2;
        lq[it] = idx & 3;
    }

    float acc[4][4][4];
#pragma unroll
    for (int a = 0; a < 4; a++)
#pragma unroll
        for (int b = 0; b < 4; b++)
#pragma unroll
            for (int c = 0; c < 4; c++) acc[a][b][c] = 0.f;

    uint4 pA[2], pB[2];

    auto fetch = [&](int ch) {
        const int k0 = ch * 32;
#pragma unroll
        for (int it = 0; it < 2; it++) {
            int row = lrow[it], q = lq[it];
            if (m0 + row < M) {
                size_t off = (size_t)(m0 + row) * K + k0 + q * 8;
                pA[it] = *(const uint4*)&A[off];
            } else {
                pA[it] = make_uint4(0, 0, 0, 0);
            }
            size_t offb = (size_t)(n0 + row) * K + k0 + q * 8;
            pB[it] = *(const uint4*)&B[offb];
        }
    };
    auto commit = [&]() {
#pragma unroll
        for (int it = 0; it < 2; it++) {
            int row = lrow[it], q = lq[it];
            *(uint4*)&sA[row][q * 8] = pA[it];
            *(uint4*)&sB[row][q * 8] = pB[it];
        }
    };

    const int nch = K / 32;
    fetch(0);
    commit();

    for (int ch = 0; ch < nch; ch++) {
        __syncthreads();
        if (ch + 1 < nch) fetch(ch + 1);

#pragma unroll
        for (int kk = 0; kk < 32; kk += 16) {
            const int r = lane & 15;
            const int koff = (lane >> 4) << 3;
            uint32_t bf[2][4];
#pragma unroll
            for (int nt = 0; nt < 2; nt++)
                ldm4(bf[nt], smem_u32(&sB[wn * 32 + nt * 16 + r][kk + koff]));
#pragma unroll
            for (int mt = 0; mt < 4; mt++) {
                uint32_t af[4];
                ldm4(af, smem_u32(&sA[wm * 64 + mt * 16 + r][kk + koff]));
#pragma unroll
                for (int j = 0; j < 4; j++)
                    mma_f16(acc[mt][j], af, bf[j >> 1][j & 1], bf[j >> 1][2 + (j & 1)]);
            }
        }
        __syncthreads();
        if (ch + 1 < nch) commit();
    }

    const int rbase = m0 + wm * 64 + (lane >> 2);
    const int cbase = n0 + wn * 32 + (lane & 3) * 2;
#pragma unroll
    for (int mt = 0; mt < 4; mt++) {
        int m = rbase + mt * 16;
#pragma unroll
        for (int j = 0; j < 4; j++) {
            int c = cbase + j * 8;
            float bv0 = bias[c], bv1 = bias[c + 1];
            if (m < M)
                *(__half2*)&C[(size_t)m * N + c] =
                    __floats2half2_rn(acc[mt][j][0] + bv0, acc[mt][j][1] + bv1);
            if (m + 8 < M)
                *(__half2*)&C[(size_t)(m + 8) * N + c] =
                    __floats2half2_rn(acc[mt][j][2] + bv0, acc[mt][j][3] + bv1);
        }
    }
}

// ---------------- fp16 GEMM, layer 2: K=128, Npad=64, Nout=40 ----------------
__global__ void __launch_bounds__(256, 2)
k_gemm64_h(const __half* __restrict__ A, const __half* __restrict__ B,
           const float* __restrict__ bias, __half* __restrict__ C, int M) {
    const int K = 128, NOUT = 40;
    __shared__ __half sA[128][40];
    __shared__ __half sB[64][40];

    const int tid = threadIdx.x;
    const int wid = tid >> 5, lane = tid & 31;
    const int m0 = blockIdx.y * 128;
    const int wm = wid >> 1;
    const int wn = wid & 1;

    int lrowA[2], lqA[2];
#pragma unroll
    for (int it = 0; it < 2; it++) {
        int idx = it * 256 + tid;
        lrowA[it] = idx >> 2;
        lqA[it] = idx & 3;
    }
    const int lrowB = tid >> 2, lqB = tid & 3;

    float acc[2][4][4];
#pragma unroll
    for (int a = 0; a < 2; a++)
#pragma unroll
        for (int b = 0; b < 4; b++)
#pragma unroll
            for (int c = 0; c < 4; c++) acc[a][b][c] = 0.f;

    uint4 pA[2], pB1;

    auto fetch = [&](int ch) {
        const int k0 = ch * 32;
#pragma unroll
        for (int it = 0; it < 2; it++) {
            int row = lrowA[it], q = lqA[it];
            if (m0 + row < M) {
                size_t off = (size_t)(m0 + row) * K + k0 + q * 8;
                pA[it] = *(const uint4*)&A[off];
            } else {
                pA[it] = make_uint4(0, 0, 0, 0);
            }
        }
        size_t offb = (size_t)lrowB * K + k0 + lqB * 8;
        pB1 = *(const uint4*)&B[offb];
    };
    auto commit = [&]() {
#pragma unroll
        for (int it = 0; it < 2; it++) {
            int row = lrowA[it], q = lqA[it];
            *(uint4*)&sA[row][q * 8] = pA[it];
        }
        *(uint4*)&sB[lrowB][lqB * 8] = pB1;
    };

    const int nch = K / 32;
    fetch(0);
    commit();

    for (int ch = 0; ch < nch; ch++) {
        __syncthreads();
        if (ch + 1 < nch) fetch(ch + 1);

#pragma unroll
        for (int kk = 0; kk < 32; kk += 16) {
            const int r = lane & 15;
            const int koff = (lane >> 4) << 3;
            uint32_t bf[2][4];
#pragma unroll
            for (int nt = 0; nt < 2; nt++)
                ldm4(bf[nt], smem_u32(&sB[wn * 32 + nt * 16 + r][kk + koff]));
#pragma unroll
            for (int mt = 0; mt < 2; mt++) {
                uint32_t af[4];
                ldm4(af, smem_u32(&sA[wm * 32 + mt * 16 + r][kk + koff]));
#pragma unroll
                for (int j = 0; j < 4; j++)
                    mma_f16(acc[mt][j], af, bf[j >> 1][j & 1], bf[j >> 1][2 + (j & 1)]);
            }
        }
        __syncthreads();
        if (ch + 1 < nch) commit();
    }

    const int rbase = m0 + wm * 32 + (lane >> 2);
    const int cbase = wn * 32 + (lane & 3) * 2;
#pragma unroll
    for (int mt = 0; mt < 2; mt++) {
        int m = rbase + mt * 16;
#pragma unroll
        for (int j = 0; j < 4; j++) {
            int c = cbase + j * 8;
            if (c >= NOUT) continue;
            float bv0 = bias[c], bv1 = bias[c + 1];
            if (m < M)
                *(__half2*)&C[(size_t)m * NOUT + c] =
                    __floats2half2_rn(acc[mt][j][0] + bv0, acc[mt][j][1] + bv1);
            if (m + 8 < M)
                *(__half2*)&C[(size_t)(m + 8) * NOUT + c] =
                    __floats2half2_rn(acc[mt][j][2] + bv0, acc[mt][j][3] + bv1);
        }
    }
}

// ---------------- SPMM fp16 gather -> fp16 out, single pass ----------------
// D halves per row, DL = D/8 lanes; each lane gathers one uint4 (8 halves).
template <int DL, int ROWS>
__global__ void k_spmm_h(const __half* __restrict__ s, __half* __restrict__ o) {
    int row = blockIdx.x * ROWS + threadIdx.y;
    if (row >= NN) return;
    const int x = threadIdx.x;
    const uint4* s4 = (const uint4*)s;
    float acc[8];
#pragma unroll
    for (int i = 0; i < 8; i++) acc[i] = 0.f;
    int e = g_rowptr[row];
    const int end = g_rowptr[row + 1];
    for (; e + 1 < end; e += 2) {
        int sc0 = g_srcs[e], sc1 = g_srcs[e + 1];
        float v0 = g_vals[e], v1 = g_vals[e + 1];
        uint4 t0 = s4[(size_t)sc0 * DL + x];
        uint4 t1 = s4[(size_t)sc1 * DL + x];
        const __half2* h0 = (const __half2*)&t0;
        const __half2* h1 = (const __half2*)&t1;
#pragma unroll
        for (int i = 0; i < 4; i++) {
            float2 f0 = __half22float2(h0[i]);
            float2 f1 = __half22float2(h1[i]);
            acc[2 * i]     += v0 * f0.x + v1 * f1.x;
            acc[2 * i + 1] += v0 * f0.y + v1 * f1.y;
        }
    }
    if (e < end) {
        int sc = g_srcs[e];
        float v = g_vals[e];
        uint4 t = s4[(size_t)sc * DL + x];
        const __half2* h = (const __half2*)&t;
#pragma unroll
        for (int i = 0; i < 4; i++) {
            float2 f = __half22float2(h[i]);
            acc[2 * i]     += v * f.x;
            acc[2 * i + 1] += v * f.y;
        }
    }
    uint4 ov;
    ov.x = h2u(fmaxf(acc[0], 0.f), fmaxf(acc[1], 0.f));
    ov.y = h2u(fmaxf(acc[2], 0.f), fmaxf(acc[3], 0.f));
    ov.z = h2u(fmaxf(acc[4], 0.f), fmaxf(acc[5], 0.f));
    ov.w = h2u(fmaxf(acc[6], 0.f), fmaxf(acc[7], 0.f));
    ((uint4*)o)[(size_t)row * DL + x] = ov;
}

// ---------------- fused SPMM(D=40, fp16 in) + log_softmax: 1 warp/row ----------------
__global__ void k_spmm_lsm(const __half* __restrict__ s, float* __restrict__ out) {
    int row = blockIdx.x * blockDim.y + threadIdx.y;
    if (row >= NN) return;
    const int l = threadIdx.x;
    float a = 0.f, b = 0.f;
    int e = g_rowptr[row];
    const int end = g_rowptr[row + 1];
    for (; e < end; e++) {
        int sc = g_srcs[e];
        float v = g_vals[e];
        const __half* srow = s + (size_t)sc * 40;
        a += v * __half2float(srow[l]);
        if (l < 8) b += v * __half2float(srow[32 + l]);
    }
    float bb = (l < 8) ? b : -1e30f;
    float m = fmaxf(a, bb);
#pragma unroll
    for (int off = 16; off > 0; off >>= 1)
        m = fmaxf(m, __shfl_xor_sync(0xFFFFFFFFu, m, off));
    float sum = expf(a - m) + ((l < 8) ? expf(b - m) : 0.f);
#pragma unroll
    for (int off = 16; off > 0; off >>= 1)
        sum += __shfl_xor_sync(0xFFFFFFFFu, sum, off);
    float ls = m + logf(sum);
    out[(size_t)row * 40 + l] = a - ls;
    if (l < 8) out[(size_t)row * 40 + 32 + l] = b - ls;
}

// ---------------- launch ----------------
extern "C" void kernel_launch(void* const* d_in, const int* in_sizes, int n_in,
                              void* d_out, int out_size) {
    const float* x    = (const float*)d_in[0];
    const int*   esrc = (const int*)d_in[1];
    const int*   edst = (const int*)d_in[2];
    const float* eval = (const float*)d_in[3];
    const float* W0   = (const float*)d_in[4];
    const float* b0   = (const float*)d_in[5];
    const float* W1   = (const float*)d_in[6];
    const float* b1   = (const float*)d_in[7];
    const float* W2   = (const float*)d_in[8];
    const float* b2   = (const float*)d_in[9];
    float* out = (float*)d_out;

    float *ps, *ph;
    __half *pa, *pw0, *pw1, *pw2;
    cudaGetSymbolAddress((void**)&ps, g_s);
    cudaGetSymbolAddress((void**)&ph, g_h);
    cudaGetSymbolAddress((void**)&pa, g_a);
    cudaGetSymbolAddress((void**)&pw0, g_w0);
    cudaGetSymbolAddress((void**)&pw1, g_w1);
    cudaGetSymbolAddress((void**)&pw2, g_w2);
    __half* ps_h = (__half*)ps;   // fp16 s0 / s2
    __half* ph_h = (__half*)ph;   // fp16 s1

    static cudaStream_t s2 = nullptr;
    static cudaEvent_t evFork = nullptr, evCsr = nullptr;
    if (s2 == nullptr) {
        cudaStreamCreateWithFlags(&s2, cudaStreamNonBlocking);
        cudaEventCreateWithFlags(&evFork, cudaEventDisableTiming);
        cudaEventCreateWithFlags(&evCsr, cudaEventDisableTiming);
    }

    // fork: CSR build ONLY on s2, concurrent with cvt_w + GEMM0
    cudaEventRecord(evFork, 0);
    cudaStreamWaitEvent(s2, evFork, 0);
    k_zero_deg<<<(NN + 255) / 256, 256, 0, s2>>>();
    k_hist<<<(NE + 255) / 256, 256, 0, s2>>>(edst);
    k_scan<<<1, 1024, 0, s2>>>();
    k_scatter<<<(NE + 255) / 256, 256, 0, s2>>>(esrc, edst, eval);
    cudaEventRecord(evCsr, s2);

    // main stream: weight conversions + layer-0 GEMM
    k_cvt_w_h<<<(256 * 512 + 255) / 256, 256>>>(W0, pw0, 512, 256, 256);
    k_cvt_w_h<<<(128 * 256 + 255) / 256, 256>>>(W1, pw1, 256, 128, 128);
    k_cvt_w_h<<<(64 * 128 + 255) / 256, 256>>>(W2, pw2, 128, 40, 64);

    const int MB = (NN + 127) / 128;  // 782

    // Layer 0: s0 = x @ W0 + b0 (K=512, N=256), fp16 single-pass -> ps_h
    k_gemm_f32a<<<dim3(2, MB), 256>>>(x, pw0, b0, ps_h, NN, 512, 256);

    // join: SPMM needs the CSR
    cudaStreamWaitEvent(0, evCsr, 0);

    // SPMM0 + relu -> fp16 h0 (single pass, 512 B/edge gather)
    k_spmm_h<32, 8><<<(NN + 7) / 8, dim3(32, 8)>>>(ps_h, pa);

    // Layer 1: s1 = h0 @ W1 + b1 (K=256, N=128), fp16 -> ph_h
    k_gemm_h<<<dim3(1, MB), 256>>>(pa, pw1, b1, ph_h, NN, 256, 128);

    // SPMM1 + relu -> fp16 h1 (single pass, 256 B/edge gather)
    k_spmm_h<16, 16><<<(NN + 15) / 16, dim3(16, 16)>>>(ph_h, pa);

    // Layer 2: s2 = h1 @ W2 + b2 (K=128, N=40 padded to 64), fp16 -> ps_h
    k_gemm64_h<<<dim3(1, MB), 256>>>(pa, pw2, b2, ps_h, NN);

    // fused SPMM2 + log_softmax (fp16 gather) -> out
    k_spmm_lsm<<<(NN + 7) / 8, dim3(32, 8)>>>(ps_h, out);
}

// round 17
// speedup vs baseline: 2.3538x; 1.0410x over previous
#include <cuda_runtime.h>
#include <cuda_fp16.h>
#include <math.h>
#include <stdint.h>

#define NN 100000
#define NE 3200000

// ---------------- scratch ----------------
__device__ float g_s[(size_t)NN * 256];            // __half s0 / s2 buffer
__device__ float g_h[(size_t)NN * 256];            // __half s1 buffer
__device__ __half g_a[(size_t)NN * 256];           // fp16 activations (h0 / h1)
__device__ __half g_w0[256 * 512];                 // [N][K] n-major fp16
__device__ __half g_w1[128 * 256];
__device__ __half g_w2[64 * 128];                  // N padded 40->64
__device__ int   g_deg[NN];
__device__ int   g_rowptr[NN + 1];
__device__ int   g_cursor[NN];
__device__ int   g_srcs[NE];
__device__ float g_vals[NE];

// ---------------- helpers ----------------
__device__ __forceinline__ uint32_t smem_u32(const void* p) {
    uint32_t a;
    asm("{ .reg .u64 t; cvta.to.shared.u64 t, %1; cvt.u32.u64 %0, t; }" : "=r"(a) : "l"(p));
    return a;
}

__device__ __forceinline__ uint32_t h2u(float a, float b) {
    __half2 h = __floats2half2_rn(a, b);
    return *(uint32_t*)&h;
}

__device__ __forceinline__ void ldm4(uint32_t* r, uint32_t addr) {
    asm volatile("ldmatrix.sync.aligned.m8n8.x4.shared.b16 {%0,%1,%2,%3}, [%4];"
                 : "=r"(r[0]), "=r"(r[1]), "=r"(r[2]), "=r"(r[3]) : "r"(addr));
}

__device__ __forceinline__ void mma_f16(float* c, const uint32_t* a, uint32_t b0, uint32_t b1) {
    asm volatile(
        "mma.sync.aligned.m16n8k16.row.col.f32.f16.f16.f32 "
        "{%0,%1,%2,%3}, {%4,%5,%6,%7}, {%8,%9}, {%0,%1,%2,%3};"
        : "+f"(c[0]), "+f"(c[1]), "+f"(c[2]), "+f"(c[3])
        : "r"(a[0]), "r"(a[1]), "r"(a[2]), "r"(a[3]), "r"(b0), "r"(b1));
}

// ---------------- CSR build ----------------
__global__ void k_zero_deg() {
    int i = blockIdx.x * blockDim.x + threadIdx.x;
    if (i < NN) g_deg[i] = 0;
}
__global__ void k_hist(const int* __restrict__ dst) {
    int e = blockIdx.x * blockDim.x + threadIdx.x;
    if (e < NE) atomicAdd(&g_deg[dst[e]], 1);
}
__global__ void k_scan() {
    __shared__ int ssum[1024];
    const int t = threadIdx.x;
    const int CH = (NN + 1023) / 1024;
    int s0 = t * CH, s1 = s0 + CH; if (s1 > NN) s1 = NN;
    int sum = 0;
    for (int i = s0; i < s1; i++) sum += g_deg[i];
    ssum[t] = sum;
    __syncthreads();
    for (int off = 1; off < 1024; off <<= 1) {
        int v = (t >= off) ? ssum[t - off] : 0;
        __syncthreads();
        ssum[t] += v;
        __syncthreads();
    }
    int run = (t == 0) ? 0 : ssum[t - 1];
    for (int i = s0; i < s1; i++) { g_rowptr[i] = run; g_cursor[i] = run; run += g_deg[i]; }
    if (t == 1023) g_rowptr[NN] = ssum[1023];
}
__global__ void k_scatter(const int* __restrict__ src, const int* __restrict__ dst,
                          const float* __restrict__ val) {
    int e = blockIdx.x * blockDim.x + threadIdx.x;
    if (e >= NE) return;
    int d = dst[e];
    int p = atomicAdd(&g_cursor[d], 1);
    g_srcs[p] = src[e];
    g_vals[p] = val[e];
}

// ---------------- weight converter: W [K][N] fp32 -> [Npad][K] fp16 n-major ----------------
__global__ void k_cvt_w_h(const float* __restrict__ W, __half* __restrict__ wh,
                          int K, int N, int Npad) {
    int idx = blockIdx.x * blockDim.x + threadIdx.x;
    if (idx >= Npad * K) return;
    int n = idx / K, k = idx % K;
    float v = (n < N) ? W[(size_t)k * N + n] : 0.f;
    wh[idx] = __float2half(v);
}

// ---------------- fp16 GEMM (fp32 A converted in-kernel): C = A @ B^T + bias ----------------
__global__ void __launch_bounds__(256, 2)
k_gemm_f32a(const float* __restrict__ A, const __half* __restrict__ B,
            const float* __restrict__ bias, __half* __restrict__ C,
            int M, int K, int N) {
    __shared__ __half sA[128][40];
    __shared__ __half sB[128][40];

    const int tid = threadIdx.x;
    const int wid = tid >> 5, lane = tid & 31;
    const int m0 = blockIdx.y * 128;
    const int n0 = blockIdx.x * 128;
    const int wm = wid >> 2;
    const int wn = wid & 3;

    int lrow[2], lq[2];
#pragma unroll
    for (int it = 0; it < 2; it++) {
        int idx = it * 256 + tid;
        lrow[it] = idx >> 2;
        lq[it] = idx & 3;
    }

    float acc[4][4][4];
#pragma unroll
    for (int a = 0; a < 4; a++)
#pragma unroll
        for (int b = 0; b < 4; b++)
#pragma unroll
            for (int c = 0; c < 4; c++) acc[a][b][c] = 0.f;

    float4 fA[2][2];
    uint4 pB[2];

    auto fetch = [&](int ch) {
        const int k0 = ch * 32;
#pragma unroll
        for (int it = 0; it < 2; it++) {
            int row = lrow[it], q = lq[it];
            if (m0 + row < M) {
                const float* p = &A[(size_t)(m0 + row) * K + k0 + q * 8];
                fA[it][0] = *(const float4*)p;
                fA[it][1] = *(const float4*)(p + 4);
            } else {
                fA[it][0] = make_float4(0.f, 0.f, 0.f, 0.f);
                fA[it][1] = make_float4(0.f, 0.f, 0.f, 0.f);
            }
            size_t offb = (size_t)(n0 + row) * K + k0 + q * 8;
            pB[it] = *(const uint4*)&B[offb];
        }
    };
    auto commit = [&]() {
#pragma unroll
        for (int it = 0; it < 2; it++) {
            int row = lrow[it], q = lq[it];
            uint4 v;
            v.x = h2u(fA[it][0].x, fA[it][0].y);
            v.y = h2u(fA[it][0].z, fA[it][0].w);
            v.z = h2u(fA[it][1].x, fA[it][1].y);
            v.w = h2u(fA[it][1].z, fA[it][1].w);
            *(uint4*)&sA[row][q * 8] = v;
            *(uint4*)&sB[row][q * 8] = pB[it];
        }
    };

    const int nch = K / 32;
    fetch(0);
    commit();

    for (int ch = 0; ch < nch; ch++) {
        __syncthreads();
        if (ch + 1 < nch) fetch(ch + 1);

#pragma unroll
        for (int kk = 0; kk < 32; kk += 16) {
            const int r = lane & 15;
            const int koff = (lane >> 4) << 3;
            uint32_t bf[2][4];
#pragma unroll
            for (int nt = 0; nt < 2; nt++)
                ldm4(bf[nt], smem_u32(&sB[wn * 32 + nt * 16 + r][kk + koff]));
#pragma unroll
            for (int mt = 0; mt < 4; mt++) {
                uint32_t af[4];
                ldm4(af, smem_u32(&sA[wm * 64 + mt * 16 + r][kk + koff]));
#pragma unroll
                for (int j = 0; j < 4; j++)
                    mma_f16(acc[mt][j], af, bf[j >> 1][j & 1], bf[j >> 1][2 + (j & 1)]);
            }
        }
        __syncthreads();
        if (ch + 1 < nch) commit();
    }

    const int rbase = m0 + wm * 64 + (lane >> 2);
    const int cbase = n0 + wn * 32 + (lane & 3) * 2;
#pragma unroll
    for (int mt = 0; mt < 4; mt++) {
        int m = rbase + mt * 16;
#pragma unroll
        for (int j = 0; j < 4; j++) {
            int c = cbase + j * 8;
            float bv0 = bias[c], bv1 = bias[c + 1];
            if (m < M)
                *(__half2*)&C[(size_t)m * N + c] =
                    __floats2half2_rn(acc[mt][j][0] + bv0, acc[mt][j][1] + bv1);
            if (m + 8 < M)
                *(__half2*)&C[(size_t)(m + 8) * N + c] =
                    __floats2half2_rn(acc[mt][j][2] + bv0, acc[mt][j][3] + bv1);
        }
    }
}

// ---------------- fp16 GEMM (fp16 A): C = A @ B^T + bias ----------------
__global__ void __launch_bounds__(256, 2)
k_gemm_h(const __half* __restrict__ A, const __half* __restrict__ B,
         const float* __restrict__ bias, __half* __restrict__ C,
         int M, int K, int N) {
    __shared__ __half sA[128][40];
    __shared__ __half sB[128][40];

    const int tid = threadIdx.x;
    const int wid = tid >> 5, lane = tid & 31;
    const int m0 = blockIdx.y * 128;
    const int n0 = blockIdx.x * 128;
    const int wm = wid >> 2;
    const int wn = wid & 3;

    int lrow[2], lq[2];
#pragma unroll
    for (int it = 0; it < 2; it++) {
        int idx = it * 256 + tid;
        lrow[it] = idx >> 2;
        lq[it] = idx & 3;
    }

    float acc[4][4][4];
#pragma unroll
    for (int a = 0; a < 4; a++)
#pragma unroll
        for (int b = 0; b < 4; b++)
#pragma unroll
            for (int c = 0; c < 4; c++) acc[a][b][c] = 0.f;

    uint4 pA[2], pB[2];

    auto fetch = [&](int ch) {
        const int k0 = ch * 32;
#pragma unroll
        for (int it = 0; it < 2; it++) {
            int row = lrow[it], q = lq[it];
            if (m0 + row < M) {
                size_t off = (size_t)(m0 + row) * K + k0 + q * 8;
                pA[it] = *(const uint4*)&A[off];
            } else {
                pA[it] = make_uint4(0, 0, 0, 0);
            }
            size_t offb = (size_t)(n0 + row) * K + k0 + q * 8;
            pB[it] = *(const uint4*)&B[offb];
        }
    };
    auto commit = [&]() {
#pragma unroll
        for (int it = 0; it < 2; it++) {
            int row = lrow[it], q = lq[it];
            *(uint4*)&sA[row][q * 8] = pA[it];
            *(uint4*)&sB[row][q * 8] = pB[it];
        }
    };

    const int nch = K / 32;
    fetch(0);
    commit();

    for (int ch = 0; ch < nch; ch++) {
        __syncthreads();
        if (ch + 1 < nch) fetch(ch + 1);

#pragma unroll
        for (int kk = 0; kk < 32; kk += 16) {
            const int r = lane & 15;
            const int koff = (lane >> 4) << 3;
            uint32_t bf[2][4];
#pragma unroll
            for (int nt = 0; nt < 2; nt++)
                ldm4(bf[nt], smem_u32(&sB[wn * 32 + nt * 16 + r][kk + koff]));
#pragma unroll
            for (int mt = 0; mt < 4; mt++) {
                uint32_t af[4];
                ldm4(af, smem_u32(&sA[wm * 64 + mt * 16 + r][kk + koff]));
#pragma unroll
                for (int j = 0; j < 4; j++)
                    mma_f16(acc[mt][j], af, bf[j >> 1][j & 1], bf[j >> 1][2 + (j & 1)]);
            }
        }
        __syncthreads();
        if (ch + 1 < nch) commit();
    }

    const int rbase = m0 + wm * 64 + (lane >> 2);
    const int cbase = n0 + wn * 32 + (lane & 3) * 2;
#pragma unroll
    for (int mt = 0; mt < 4; mt++) {
        int m = rbase + mt * 16;
#pragma unroll
        for (int j = 0; j < 4; j++) {
            int c = cbase + j * 8;
            float bv0 = bias[c], bv1 = bias[c + 1];
            if (m < M)
                *(__half2*)&C[(size_t)m * N + c] =
                    __floats2half2_rn(acc[mt][j][0] + bv0, acc[mt][j][1] + bv1);
            if (m + 8 < M)
                *(__half2*)&C[(size_t)(m + 8) * N + c] =
                    __floats2half2_rn(acc[mt][j][2] + bv0, acc[mt][j][3] + bv1);
        }
    }
}

// ---------------- fp16 GEMM, layer 2: K=128, Npad=64, Nout=40 ----------------
__global__ void __launch_bounds__(256, 2)
k_gemm64_h(const __half* __restrict__ A, const __half* __restrict__ B,
           const float* __restrict__ bias, __half* __restrict__ C, int M) {
    const int K = 128, NOUT = 40;
    __shared__ __half sA[128][40];
    __shared__ __half sB[64][40];

    const int tid = threadIdx.x;
    const int wid = tid >> 5, lane = tid & 31;
    const int m0 = blockIdx.y * 128;
    const int wm = wid >> 1;
    const int wn = wid & 1;

    int lrowA[2], lqA[2];
#pragma unroll
    for (int it = 0; it < 2; it++) {
        int idx = it * 256 + tid;
        lrowA[it] = idx >> 2;
        lqA[it] = idx & 3;
    }
    const int lrowB = tid >> 2, lqB = tid & 3;

    float acc[2][4][4];
#pragma unroll
    for (int a = 0; a < 2; a++)
#pragma unroll
        for (int b = 0; b < 4; b++)
#pragma unroll
            for (int c = 0; c < 4; c++) acc[a][b][c] = 0.f;

    uint4 pA[2], pB1;

    auto fetch = [&](int ch) {
        const int k0 = ch * 32;
#pragma unroll
        for (int it = 0; it < 2; it++) {
            int row = lrowA[it], q = lqA[it];
            if (m0 + row < M) {
                size_t off = (size_t)(m0 + row) * K + k0 + q * 8;
                pA[it] = *(const uint4*)&A[off];
            } else {
                pA[it] = make_uint4(0, 0, 0, 0);
            }
        }
        size_t offb = (size_t)lrowB * K + k0 + lqB * 8;
        pB1 = *(const uint4*)&B[offb];
    };
    auto commit = [&]() {
#pragma unroll
        for (int it = 0; it < 2; it++) {
            int row = lrowA[it], q = lqA[it];
            *(uint4*)&sA[row][q * 8] = pA[it];
        }
        *(uint4*)&sB[lrowB][lqB * 8] = pB1;
    };

    const int nch = K / 32;
    fetch(0);
    commit();

    for (int ch = 0; ch < nch; ch++) {
        __syncthreads();
        if (ch + 1 < nch) fetch(ch + 1);

#pragma unroll
        for (int kk = 0; kk < 32; kk += 16) {
            const int r = lane & 15;
            const int koff = (lane >> 4) << 3;
            uint32_t bf[2][4];
#pragma unroll
            for (int nt = 0; nt < 2; nt++)
                ldm4(bf[nt], smem_u32(&sB[wn * 32 + nt * 16 + r][kk + koff]));
#pragma unroll
            for (int mt = 0; mt < 2; mt++) {
                uint32_t af[4];
                ldm4(af, smem_u32(&sA[wm * 32 + mt * 16 + r][kk + koff]));
#pragma unroll
                for (int j = 0; j < 4; j++)
                    mma_f16(acc[mt][j], af, bf[j >> 1][j & 1], bf[j >> 1][2 + (j & 1)]);
            }
        }
        __syncthreads();
        if (ch + 1 < nch) commit();
    }

    const int rbase = m0 + wm * 32 + (lane >> 2);
    const int cbase = wn * 32 + (lane & 3) * 2;
#pragma unroll
    for (int mt = 0; mt < 2; mt++) {
        int m = rbase + mt * 16;
#pragma unroll
        for (int j = 0; j < 4; j++) {
            int c = cbase + j * 8;
            if (c >= NOUT) continue;
            float bv0 = bias[c], bv1 = bias[c + 1];
            if (m < M)
                *(__half2*)&C[(size_t)m * NOUT + c] =
                    __floats2half2_rn(acc[mt][j][0] + bv0, acc[mt][j][1] + bv1);
            if (m + 8 < M)
                *(__half2*)&C[(size_t)(m + 8) * NOUT + c] =
                    __floats2half2_rn(acc[mt][j][2] + bv0, acc[mt][j][3] + bv1);
        }
    }
}

// ---------------- SPMM fp16 gather -> fp16 out, 4-edge unrolled ----------------
// D halves per row, DL = D/8 lanes; each lane gathers one uint4 (8 halves).
template <int DL, int ROWS>
__global__ void k_spmm_h(const __half* __restrict__ s, __half* __restrict__ o) {
    int row = blockIdx.x * ROWS + threadIdx.y;
    if (row >= NN) return;
    const int x = threadIdx.x;
    const uint4* s4 = (const uint4*)s;
    float acc[8];
#pragma unroll
    for (int i = 0; i < 8; i++) acc[i] = 0.f;
    int e = g_rowptr[row];
    const int end = g_rowptr[row + 1];
    // 4-edge unrolled main loop: 4 independent gathers in flight
    for (; e + 3 < end; e += 4) {
        int sc0 = g_srcs[e], sc1 = g_srcs[e + 1], sc2 = g_srcs[e + 2], sc3 = g_srcs[e + 3];
        float v0 = g_vals[e], v1 = g_vals[e + 1], v2 = g_vals[e + 2], v3 = g_vals[e + 3];
        uint4 t0 = s4[(size_t)sc0 * DL + x];
        uint4 t1 = s4[(size_t)sc1 * DL + x];
        uint4 t2 = s4[(size_t)sc2 * DL + x];
        uint4 t3 = s4[(size_t)sc3 * DL + x];
        const __half2* h0 = (const __half2*)&t0;
        const __half2* h1 = (const __half2*)&t1;
        const __half2* h2 = (const __half2*)&t2;
        const __half2* h3 = (const __half2*)&t3;
#pragma unroll
        for (int i = 0; i < 4; i++) {
            float2 f0 = __half22float2(h0[i]);
            float2 f1 = __half22float2(h1[i]);
            float2 f2 = __half22float2(h2[i]);
            float2 f3 = __half22float2(h3[i]);
            acc[2 * i]     += v0 * f0.x + v1 * f1.x + v2 * f2.x + v3 * f3.x;
            acc[2 * i + 1] += v0 * f0.y + v1 * f1.y + v2 * f2.y + v3 * f3.y;
        }
    }
    for (; e < end; e++) {
        int sc = g_srcs[e];
        float v = g_vals[e];
        uint4 t = s4[(size_t)sc * DL + x];
        const __half2* h = (const __half2*)&t;
#pragma unroll
        for (int i = 0; i < 4; i++) {
            float2 f = __half22float2(h[i]);
            acc[2 * i]     += v * f.x;
            acc[2 * i + 1] += v * f.y;
        }
    }
    uint4 ov;
    ov.x = h2u(fmaxf(acc[0], 0.f), fmaxf(acc[1], 0.f));
    ov.y = h2u(fmaxf(acc[2], 0.f), fmaxf(acc[3], 0.f));
    ov.z = h2u(fmaxf(acc[4], 0.f), fmaxf(acc[5], 0.f));
    ov.w = h2u(fmaxf(acc[6], 0.f), fmaxf(acc[7], 0.f));
    ((uint4*)o)[(size_t)row * DL + x] = ov;
}

// ---------------- fused SPMM(D=40, fp16 in) + log_softmax: 1 warp/row, 2-edge unrolled ----------------
__global__ void k_spmm_lsm(const __half* __restrict__ s, float* __restrict__ out) {
    int row = blockIdx.x * blockDim.y + threadIdx.y;
    if (row >= NN) return;
    const int l = threadIdx.x;
    float a = 0.f, b = 0.f;
    int e = g_rowptr[row];
    const int end = g_rowptr[row + 1];
    for (; e + 1 < end; e += 2) {
        int sc0 = g_srcs[e], sc1 = g_srcs[e + 1];
        float v0 = g_vals[e], v1 = g_vals[e + 1];
        const __half* s0r = s + (size_t)sc0 * 40;
        const __half* s1r = s + (size_t)sc1 * 40;
        float p0 = __half2float(s0r[l]);
        float p1 = __half2float(s1r[l]);
        a += v0 * p0 + v1 * p1;
        if (l < 8) {
            float q0 = __half2float(s0r[32 + l]);
            float q1 = __half2float(s1r[32 + l]);
            b += v0 * q0 + v1 * q1;
        }
    }
    if (e < end) {
        int sc = g_srcs[e];
        float v = g_vals[e];
        const __half* srow = s + (size_t)sc * 40;
        a += v * __half2float(srow[l]);
        if (l < 8) b += v * __half2float(srow[32 + l]);
    }
    float bb = (l < 8) ? b : -1e30f;
    float m = fmaxf(a, bb);
#pragma unroll
    for (int off = 16; off > 0; off >>= 1)
        m = fmaxf(m, __shfl_xor_sync(0xFFFFFFFFu, m, off));
    float sum = expf(a - m) + ((l < 8) ? expf(b - m) : 0.f);
#pragma unroll
    for (int off = 16; off > 0; off >>= 1)
        sum += __shfl_xor_sync(0xFFFFFFFFu, sum, off);
    float ls = m + logf(sum);
    out[(size_t)row * 40 + l] = a - ls;
    if (l < 8) out[(size_t)row * 40 + 32 + l] = b - ls;
}

// ---------------- launch ----------------
extern "C" void kernel_launch(void* const* d_in, const int* in_sizes, int n_in,
                              void* d_out, int out_size) {
    const float* x    = (const float*)d_in[0];
    const int*   esrc = (const int*)d_in[1];
    const int*   edst = (const int*)d_in[2];
    const float* eval = (const float*)d_in[3];
    const float* W0   = (const float*)d_in[4];
    const float* b0   = (const float*)d_in[5];
    const float* W1   = (const float*)d_in[6];
    const float* b1   = (const float*)d_in[7];
    const float* W2   = (const float*)d_in[8];
    const float* b2   = (const float*)d_in[9];
    float* out = (float*)d_out;

    float *ps, *ph;
    __half *pa, *pw0, *pw1, *pw2;
    cudaGetSymbolAddress((void**)&ps, g_s);
    cudaGetSymbolAddress((void**)&ph, g_h);
    cudaGetSymbolAddress((void**)&pa, g_a);
    cudaGetSymbolAddress((void**)&pw0, g_w0);
    cudaGetSymbolAddress((void**)&pw1, g_w1);
    cudaGetSymbolAddress((void**)&pw2, g_w2);
    __half* ps_h = (__half*)ps;
    __half* ph_h = (__half*)ph;

    static cudaStream_t s2 = nullptr;
    static cudaEvent_t evFork = nullptr, evCsr = nullptr;
    if (s2 == nullptr) {
        cudaStreamCreateWithFlags(&s2, cudaStreamNonBlocking);
        cudaEventCreateWithFlags(&evFork, cudaEventDisableTiming);
        cudaEventCreateWithFlags(&evCsr, cudaEventDisableTiming);
    }

    // fork: CSR build ONLY on s2, concurrent with cvt_w + GEMM0
    cudaEventRecord(evFork, 0);
    cudaStreamWaitEvent(s2, evFork, 0);
    k_zero_deg<<<(NN + 255) / 256, 256, 0, s2>>>();
    k_hist<<<(NE + 255) / 256, 256, 0, s2>>>(edst);
    k_scan<<<1, 1024, 0, s2>>>();
    k_scatter<<<(NE + 255) / 256, 256, 0, s2>>>(esrc, edst, eval);
    cudaEventRecord(evCsr, s2);

    // main stream: weight conversions + layer-0 GEMM
    k_cvt_w_h<<<(256 * 512 + 255) / 256, 256>>>(W0, pw0, 512, 256, 256);
    k_cvt_w_h<<<(128 * 256 + 255) / 256, 256>>>(W1, pw1, 256, 128, 128);
    k_cvt_w_h<<<(64 * 128 + 255) / 256, 256>>>(W2, pw2, 128, 40, 64);

    const int MB = (NN + 127) / 128;  // 782

    // Layer 0: s0 = x @ W0 + b0 (K=512, N=256), fp16 single-pass -> ps_h
    k_gemm_f32a<<<dim3(2, MB), 256>>>(x, pw0, b0, ps_h, NN, 512, 256);

    // join: SPMM needs the CSR
    cudaStreamWaitEvent(0, evCsr, 0);

    // SPMM0 + relu -> fp16 h0 (single pass, 4-edge unrolled)
    k_spmm_h<32, 8><<<(NN + 7) / 8, dim3(32, 8)>>>(ps_h, pa);

    // Layer 1: s1 = h0 @ W1 + b1 (K=256, N=128), fp16 -> ph_h
    k_gemm_h<<<dim3(1, MB), 256>>>(pa, pw1, b1, ph_h, NN, 256, 128);

    // SPMM1 + relu -> fp16 h1 (single pass, 4-edge unrolled)
    k_spmm_h<16, 16><<<(NN + 15) / 16, dim3(16, 16)>>>(ph_h, pa);

    // Layer 2: s2 = h1 @ W2 + b2 (K=128, N=40 padded to 64), fp16 -> ps_h
    k_gemm64_h<<<dim3(1, MB), 256>>>(pa, pw2, b2, ps_h, NN);

    // fused SPMM2 + log_softmax (fp16 gather, 2-edge unrolled) -> out
    k_spmm_lsm<<<(NN + 7) / 8, dim3(32, 8)>>>(ps_h, out);
}